// round 1
// baseline (speedup 1.0000x reference)
#include <cuda_runtime.h>
#include <math.h>

#define BSZ   2
#define CF    128
#define NTOT  13824      // 24^3
#define MTOT  512        // 8^3
#define NHEAD 4
#define DHEAD 64
#define INNER 256
#define SCALE 0.125f     // 64^-0.5
#define FEAT_OUT_ELEMS 3538944   // 2*128*13824

// ------------------ scratch (device globals; no allocs) ------------------
__device__ __align__(16) float g_t1   [BSZ*CF*NTOT];            // dwconv1 out
__device__ __align__(16) float g_q    [BSZ*NHEAD*NTOT*DHEAD];   // feat_q  [bh][n][d]
__device__ __align__(16) float g_fv   [BSZ*NHEAD*NTOT*DHEAD];   // feat_v  [bh][n][d]
__device__ __align__(16) float g_mq   [BSZ*NHEAD*MTOT*DHEAD];   // map_q   [bh][m][d]
__device__ __align__(16) float g_mv   [BSZ*NHEAD*MTOT*DHEAD];   // map_v   [bh][m][d]
__device__ __align__(16) float g_attn [(size_t)BSZ*NHEAD*MTOT*NTOT]; // logits [bh][m][n]
__device__ __align__(16) float g_attnout[BSZ*INNER*NTOT];       // feat attn out [b][c][n]
__device__ __align__(16) float g_dw2  [BSZ*INNER*NTOT];         // dwconv2 out
__device__ __align__(16) float g_monum[BSZ*NHEAD*MTOT*DHEAD];   // map_out numerator
__device__ __align__(16) float g_colsum[BSZ*NHEAD*MTOT];

// ------------------ depthwise 3x3x3, SAME, zero pad ------------------
__device__ __forceinline__ void dw_body(const float* __restrict__ in,
                                        const float* __restrict__ w,
                                        float* __restrict__ out, int C)
{
    int n = blockIdx.x * 256 + threadIdx.x;
    int c = blockIdx.y, b = blockIdx.z;
    int z = n / 576, y = (n / 24) % 24, x = n % 24;
    const float* wc = w + c * 27;
    const float* ip = in + ((size_t)(b * C + c)) * NTOT;
    float s = 0.f;
    #pragma unroll
    for (int dz = -1; dz <= 1; dz++) {
        int zz = z + dz; if (zz < 0 || zz >= 24) continue;
        #pragma unroll
        for (int dy = -1; dy <= 1; dy++) {
            int yy = y + dy; if (yy < 0 || yy >= 24) continue;
            #pragma unroll
            for (int dx = -1; dx <= 1; dx++) {
                int xx = x + dx; if (xx < 0 || xx >= 24) continue;
                s += wc[(dz+1)*9 + (dy+1)*3 + (dx+1)] * ip[(zz*24 + yy)*24 + xx];
            }
        }
    }
    out[((size_t)(b * C + c)) * NTOT + n] = s;
}

__global__ void k_dwconv1(const float* __restrict__ feat, const float* __restrict__ w)
{   dw_body(feat, w, g_t1, CF); }

__global__ void k_dwconv2(const float* __restrict__ w)
{   dw_body(g_attnout, w, g_dw2, INNER); }

// ------------------ pointwise qv GEMM: [512,128] @ [128,N] + head scatter ----
__global__ __launch_bounds__(256) void k_pw_qv(const float* __restrict__ A)
{
    __shared__ float As[32][65], Bs[32][65];
    int t = threadIdx.x;
    int bn = blockIdx.x * 64, bo = blockIdx.y * 64, b = blockIdx.z;
    int ty = t / 16, tx = t % 16;
    float acc[4][4] = {};
    const float* Xb = g_t1 + (size_t)b * CF * NTOT;
    for (int kc = 0; kc < 128; kc += 32) {
        #pragma unroll
        for (int i = 0; i < 8; i++) {
            int idx = t + i * 256;
            int o = idx >> 5, cc = idx & 31;
            As[cc][o] = A[(bo + o) * 128 + kc + cc];
        }
        #pragma unroll
        for (int i = 0; i < 8; i++) {
            int idx = t + i * 256;
            int cc = idx >> 6, n = idx & 63;
            Bs[cc][n] = Xb[(size_t)(kc + cc) * NTOT + bn + n];
        }
        __syncthreads();
        #pragma unroll
        for (int k = 0; k < 32; k++) {
            float a[4], bb[4];
            #pragma unroll
            for (int j = 0; j < 4; j++) a[j]  = As[k][ty * 4 + j];
            #pragma unroll
            for (int j = 0; j < 4; j++) bb[j] = Bs[k][tx * 4 + j];
            #pragma unroll
            for (int jm = 0; jm < 4; jm++)
                #pragma unroll
                for (int jn = 0; jn < 4; jn++) acc[jm][jn] += a[jm] * bb[jn];
        }
        __syncthreads();
    }
    #pragma unroll
    for (int jm = 0; jm < 4; jm++) {
        int o = bo + ty * 4 + jm;
        #pragma unroll
        for (int jn = 0; jn < 4; jn++) {
            int n = bn + tx * 4 + jn;
            float v = acc[jm][jn];
            if (o < 256) {
                g_q[((size_t)(b * 4 + (o & 3)) * NTOT + n) * 64 + (o >> 2)] = v;
            } else {
                int c = o - 256;
                g_fv[((size_t)(b * 4 + (c & 3)) * NTOT + n) * 64 + (c >> 2)] = v;
            }
        }
    }
}

// ------------------ map qv: [512,64] @ smap[b][64][512] ------------------
__global__ void k_map_qv(const float* __restrict__ w, const float* __restrict__ smap)
{
    int m = blockIdx.x * 256 + threadIdx.x;   // 0..511
    int o = blockIdx.y, b = blockIdx.z;
    float s = 0.f;
    #pragma unroll 8
    for (int c = 0; c < 64; c++)
        s += w[o * 64 + c] * smap[((size_t)(b * 64 + c)) * 512 + m];
    if (o < 256)
        g_mq[((size_t)(b * 4 + (o & 3)) * 512 + m) * 64 + (o >> 2)] = s;
    else {
        int c = o - 256;
        g_mv[((size_t)(b * 4 + (c & 3)) * 512 + m) * 64 + (c >> 2)] = s;
    }
}

// ------------------ attention pass 1: logits + row softmax + feat_out ----
__global__ __launch_bounds__(256) void k_attn1()
{
    __shared__ float mqs[64 * 64], mvs[64 * 64];
    int bh = blockIdx.y;
    int b = bh >> 2, h = bh & 3;
    int t = threadIdx.x;
    int n = blockIdx.x * 256 + t;

    float q[64], out[64];
    const float4* qrow = (const float4*)(g_q + ((size_t)bh * NTOT + n) * 64);
    #pragma unroll
    for (int i = 0; i < 16; i++) {
        float4 v = qrow[i];
        q[4*i] = v.x; q[4*i+1] = v.y; q[4*i+2] = v.z; q[4*i+3] = v.w;
    }
    #pragma unroll
    for (int d = 0; d < 64; d++) out[d] = 0.f;
    float rowsum = 0.f;

    float* arow = g_attn + (size_t)bh * MTOT * NTOT + n;

    for (int mc = 0; mc < MTOT; mc += 64) {
        __syncthreads();
        const float4* sq = (const float4*)(g_mq + ((size_t)bh * MTOT + mc) * 64);
        const float4* sv = (const float4*)(g_mv + ((size_t)bh * MTOT + mc) * 64);
        float4* dq = (float4*)mqs; float4* dv = (float4*)mvs;
        #pragma unroll
        for (int i = 0; i < 4; i++) {
            dq[t + i * 256] = sq[t + i * 256];
            dv[t + i * 256] = sv[t + i * 256];
        }
        __syncthreads();
        for (int mm = 0; mm < 64; mm++) {
            const float4* kq = (const float4*)(mqs + mm * 64);
            float a0 = 0.f, a1 = 0.f, a2 = 0.f, a3 = 0.f;
            #pragma unroll
            for (int i = 0; i < 16; i++) {
                float4 kk = kq[i];
                a0 += q[4*i]   * kk.x;
                a1 += q[4*i+1] * kk.y;
                a2 += q[4*i+2] * kk.z;
                a3 += q[4*i+3] * kk.w;
            }
            float acc = ((a0 + a1) + (a2 + a3)) * SCALE;
            arow[(size_t)(mc + mm) * NTOT] = acc;          // coalesced over n
            float e = __expf(acc);
            rowsum += e;
            const float4* vv4 = (const float4*)(mvs + mm * 64);
            #pragma unroll
            for (int i = 0; i < 16; i++) {
                float4 vv = vv4[i];
                out[4*i]   += e * vv.x;
                out[4*i+1] += e * vv.y;
                out[4*i+2] += e * vv.z;
                out[4*i+3] += e * vv.w;
            }
        }
    }
    float inv = 1.f / rowsum;
    float* ao = g_attnout + (size_t)b * INNER * NTOT + n;
    #pragma unroll
    for (int d = 0; d < 64; d++)
        ao[(size_t)(4 * d + h) * NTOT] = out[d] * inv;     // coalesced over n
}

// ------------------ zero accumulators ------------------
__global__ void k_zero()
{
    int i = blockIdx.x * 256 + threadIdx.x;
    if (i < BSZ * NHEAD * MTOT * DHEAD) g_monum[i] = 0.f;
    if (i < BSZ * NHEAD * MTOT)         g_colsum[i] = 0.f;
}

// ------------------ attention pass 2: colsum + map_out numerator ----------
// map_out_num[m][d] += sum_n exp(S[m][n]) * feat_v[n][d]
__global__ __launch_bounds__(256) void k_attn2()
{
    __shared__ float Es[32][65], Vs[32][65];
    int bh = blockIdx.y;
    int mtile = (blockIdx.x & 7) * 64;
    int nbase = (blockIdx.x >> 3) * 1536;
    int t = threadIdx.x;
    int ty = t / 16, tx = t % 16;
    float acc[4][4] = {};
    float csum[8] = {};
    const float* Ab = g_attn + (size_t)bh * MTOT * NTOT;
    const float* Vb = g_fv   + (size_t)bh * NTOT * 64;

    for (int kb = 0; kb < 1536; kb += 32) {
        #pragma unroll
        for (int i = 0; i < 8; i++) {
            int idx = t + i * 256;
            int mr = idx >> 5, nc = idx & 31;
            float e = __expf(Ab[(size_t)(mtile + mr) * NTOT + nbase + kb + nc]);
            Es[nc][mr] = e;
            csum[i] += e;           // mr is fixed per i across the k loop
        }
        #pragma unroll
        for (int i = 0; i < 8; i++) {
            int idx = t + i * 256;
            int nr = idx >> 6, d = idx & 63;
            Vs[nr][d] = Vb[(size_t)(nbase + kb + nr) * 64 + d];
        }
        __syncthreads();
        #pragma unroll
        for (int k = 0; k < 32; k++) {
            float a[4], v[4];
            #pragma unroll
            for (int j = 0; j < 4; j++) a[j] = Es[k][ty * 4 + j];
            #pragma unroll
            for (int j = 0; j < 4; j++) v[j] = Vs[k][tx * 4 + j];
            #pragma unroll
            for (int jm = 0; jm < 4; jm++)
                #pragma unroll
                for (int jd = 0; jd < 4; jd++) acc[jm][jd] += a[jm] * v[jd];
        }
        __syncthreads();
    }
    #pragma unroll
    for (int i = 0; i < 8; i++)
        atomicAdd(&g_colsum[(size_t)bh * MTOT + mtile + (t >> 5) + i * 8], csum[i]);
    #pragma unroll
    for (int jm = 0; jm < 4; jm++) {
        int m = mtile + ty * 4 + jm;
        #pragma unroll
        for (int jd = 0; jd < 4; jd++)
            atomicAdd(&g_monum[((size_t)bh * MTOT + m) * 64 + tx * 4 + jd], acc[jm][jd]);
    }
}

// ------------------ finalize map_out: divide + merge heads + [64,256] proj --
__global__ void k_mapout(const float* __restrict__ w, float* __restrict__ outp)
{
    int gid = blockIdx.x * 256 + threadIdx.x;   // < 65536
    int m = gid & 511;
    int o = (gid >> 9) & 63;
    int b = gid >> 15;
    float inv[4];
    #pragma unroll
    for (int hh = 0; hh < 4; hh++)
        inv[hh] = 1.f / g_colsum[(size_t)(b * 4 + hh) * 512 + m];
    float s = 0.f;
    #pragma unroll 4
    for (int c = 0; c < 256; c++) {
        int d = c >> 2, hh = c & 3;
        s += w[o * 256 + c] * g_monum[((size_t)(b * 4 + hh) * 512 + m) * 64 + d] * inv[hh];
    }
    outp[(size_t)FEAT_OUT_ELEMS + ((size_t)(b * 64 + o)) * 512 + m] = s;
}

// ------------------ pointwise out GEMM: [128,256] @ [256,N] -> d_out ------
__global__ __launch_bounds__(256) void k_pw_out(const float* __restrict__ A,
                                                float* __restrict__ outp)
{
    __shared__ float As[32][65], Bs[32][65];
    int t = threadIdx.x;
    int bn = blockIdx.x * 64, bo = blockIdx.y * 64, b = blockIdx.z;
    int ty = t / 16, tx = t % 16;
    float acc[4][4] = {};
    const float* Xb = g_dw2 + (size_t)b * INNER * NTOT;
    for (int kc = 0; kc < 256; kc += 32) {
        #pragma unroll
        for (int i = 0; i < 8; i++) {
            int idx = t + i * 256;
            int o = idx >> 5, cc = idx & 31;
            As[cc][o] = A[(bo + o) * 256 + kc + cc];
        }
        #pragma unroll
        for (int i = 0; i < 8; i++) {
            int idx = t + i * 256;
            int cc = idx >> 6, n = idx & 63;
            Bs[cc][n] = Xb[(size_t)(kc + cc) * NTOT + bn + n];
        }
        __syncthreads();
        #pragma unroll
        for (int k = 0; k < 32; k++) {
            float a[4], bb[4];
            #pragma unroll
            for (int j = 0; j < 4; j++) a[j]  = As[k][ty * 4 + j];
            #pragma unroll
            for (int j = 0; j < 4; j++) bb[j] = Bs[k][tx * 4 + j];
            #pragma unroll
            for (int jm = 0; jm < 4; jm++)
                #pragma unroll
                for (int jn = 0; jn < 4; jn++) acc[jm][jn] += a[jm] * bb[jn];
        }
        __syncthreads();
    }
    #pragma unroll
    for (int jm = 0; jm < 4; jm++) {
        int o = bo + ty * 4 + jm;
        #pragma unroll
        for (int jn = 0; jn < 4; jn++) {
            int n = bn + tx * 4 + jn;
            outp[((size_t)(b * 128 + o)) * NTOT + n] = acc[jm][jn];
        }
    }
}

// ------------------ launch ------------------
extern "C" void kernel_launch(void* const* d_in, const int* in_sizes, int n_in,
                              void* d_out, int out_size)
{
    const float* feat    = (const float*)d_in[0];
    const float* smap    = (const float*)d_in[1];
    const float* fqv_dw  = (const float*)d_in[2];
    const float* fqv_pw  = (const float*)d_in[3];
    const float* fout_dw = (const float*)d_in[4];
    const float* fout_pw = (const float*)d_in[5];
    const float* mqv_w   = (const float*)d_in[6];
    const float* mout_w  = (const float*)d_in[7];
    float* outp = (float*)d_out;

    k_dwconv1<<<dim3(54, 128, 2), 256>>>(feat, fqv_dw);
    k_pw_qv  <<<dim3(216, 8, 2), 256>>>(fqv_pw);
    k_map_qv <<<dim3(2, 512, 2), 256>>>(mqv_w, smap);
    k_zero   <<<1024, 256>>>();
    k_attn1  <<<dim3(54, 8), 256>>>();
    k_attn2  <<<dim3(72, 8), 256>>>();
    k_mapout <<<256, 256>>>(mout_w, outp);
    k_dwconv2<<<dim3(54, 256, 2), 256>>>(fout_dw);
    k_pw_out <<<dim3(216, 2, 2), 256>>>(fout_pw, outp);
}

// round 3
// speedup vs baseline: 1.8614x; 1.8614x over previous
#include <cuda_runtime.h>
#include <math.h>
#include <stdint.h>

#define BSZ   2
#define CF    128
#define NTOT  13824      // 24^3
#define MTOT  512        // 8^3
#define NHEAD 4
#define DHEAD 64
#define INNER 256
#define SCALE 0.125f     // 64^-0.5
#define FEAT_OUT_ELEMS 3538944   // 2*128*13824
#define KSPLIT 9
#define KLEN   1536      // 13824/9

// ------------------ scratch (device globals; no allocs) ------------------
__device__ __align__(16) float g_t1   [BSZ*CF*NTOT];            // dwconv1 out
__device__ __align__(16) float g_q    [BSZ*NHEAD*NTOT*DHEAD];   // feat_q  [bh][n][d]
__device__ __align__(16) float g_fv   [BSZ*NHEAD*NTOT*DHEAD];   // feat_v  [bh][n][d]
__device__ __align__(16) float g_mq   [BSZ*NHEAD*MTOT*DHEAD];   // map_q   [bh][m][d]
__device__ __align__(16) float g_mv   [BSZ*NHEAD*MTOT*DHEAD];   // map_v   [bh][m][d]
__device__ __align__(16) float g_attn [(size_t)BSZ*NHEAD*MTOT*NTOT]; // E=exp(logits) [bh][m][n] (tf32 bits)
__device__ __align__(16) float g_attnout[BSZ*INNER*NTOT];       // feat attn out [b][c][n]
__device__ __align__(16) float g_dw2  [BSZ*INNER*NTOT];         // dwconv2 out
__device__ __align__(16) float g_monum[BSZ*NHEAD*MTOT*DHEAD];   // map_out numerator
__device__ __align__(16) float g_colsum[BSZ*NHEAD*MTOT];

// ------------------ tf32 mma helpers ------------------
__device__ __forceinline__ uint32_t f2t(float x){
    uint32_t r; asm("cvt.rna.tf32.f32 %0,%1;":"=r"(r):"f"(x)); return r;
}
__device__ __forceinline__ float f2tf(float x){ return __uint_as_float(f2t(x)); }

__device__ __forceinline__ void mma8(float* c, const uint32_t* a, const uint32_t* b){
    asm volatile("mma.sync.aligned.m16n8k8.row.col.f32.tf32.tf32.f32 "
        "{%0,%1,%2,%3},{%4,%5,%6,%7},{%8,%9},{%0,%1,%2,%3};"
        : "+f"(c[0]),"+f"(c[1]),"+f"(c[2]),"+f"(c[3])
        : "r"(a[0]),"r"(a[1]),"r"(a[2]),"r"(a[3]),"r"(b[0]),"r"(b[1]));
}

// ------------------ depthwise 3x3x3, SAME, zero pad ------------------
__device__ __forceinline__ void dw_body(const float* __restrict__ in,
                                        const float* __restrict__ w,
                                        float* __restrict__ out, int C)
{
    int n = blockIdx.x * 256 + threadIdx.x;
    int c = blockIdx.y, b = blockIdx.z;
    int z = n / 576, y = (n / 24) % 24, x = n % 24;
    const float* wc = w + c * 27;
    const float* ip = in + ((size_t)(b * C + c)) * NTOT;
    float s = 0.f;
    #pragma unroll
    for (int dz = -1; dz <= 1; dz++) {
        int zz = z + dz; if (zz < 0 || zz >= 24) continue;
        #pragma unroll
        for (int dy = -1; dy <= 1; dy++) {
            int yy = y + dy; if (yy < 0 || yy >= 24) continue;
            #pragma unroll
            for (int dx = -1; dx <= 1; dx++) {
                int xx = x + dx; if (xx < 0 || xx >= 24) continue;
                s += wc[(dz+1)*9 + (dy+1)*3 + (dx+1)] * ip[(zz*24 + yy)*24 + xx];
            }
        }
    }
    out[((size_t)(b * C + c)) * NTOT + n] = s;
}

__global__ void k_dwconv1(const float* __restrict__ feat, const float* __restrict__ w)
{   dw_body(feat, w, g_t1, CF); }

__global__ void k_dwconv2(const float* __restrict__ w)
{   dw_body(g_attnout, w, g_dw2, INNER); }

// ------------------ pointwise qv GEMM (tf32 mma): [512,128]@[128,N] + head scatter
// block: 64(M out-ch) x 128(N voxels); 8 warps 2x4; warp tile 32x32
__global__ __launch_bounds__(256) void k_pw_qv(const float* __restrict__ A)
{
    __shared__ float As[64*36];   // [m][k] pitch 36
    __shared__ float Bs[32*136];  // [k][n] pitch 136
    int t = threadIdx.x, w = t >> 5, l = t & 31, g = l >> 2, q4 = l & 3;
    int bn = blockIdx.x * 128, bo = blockIdx.y * 64, b = blockIdx.z;
    int wm = (w >> 2) * 32, wn = (w & 3) * 32;
    float C[2][4][4] = {};
    const float* Xb = g_t1 + (size_t)b * CF * NTOT;
    for (int kc = 0; kc < 128; kc += 32) {
        __syncthreads();
        #pragma unroll
        for (int i = 0; i < 8; i++) {
            int idx = t + i * 256; int m = idx >> 5, k = idx & 31;
            As[m*36 + k] = f2tf(A[(bo + m)*128 + kc + k]);
        }
        #pragma unroll
        for (int i = 0; i < 16; i++) {
            int idx = t + i * 256; int k = idx >> 7, n = idx & 127;
            Bs[k*136 + n] = f2tf(Xb[(size_t)(kc + k)*NTOT + bn + n]);
        }
        __syncthreads();
        #pragma unroll
        for (int kk = 0; kk < 4; kk++) {
            uint32_t a[2][4], bb[4][2];
            #pragma unroll
            for (int mi = 0; mi < 2; mi++) {
                const float* ap = &As[(wm + mi*16 + g)*36 + kk*8 + q4];
                a[mi][0] = __float_as_uint(ap[0]);
                a[mi][1] = __float_as_uint(ap[8*36]);
                a[mi][2] = __float_as_uint(ap[4]);
                a[mi][3] = __float_as_uint(ap[8*36+4]);
            }
            #pragma unroll
            for (int ni = 0; ni < 4; ni++) {
                const float* bp = &Bs[(kk*8 + q4)*136 + wn + ni*8 + g];
                bb[ni][0] = __float_as_uint(bp[0]);
                bb[ni][1] = __float_as_uint(bp[4*136]);
            }
            #pragma unroll
            for (int mi = 0; mi < 2; mi++)
                #pragma unroll
                for (int ni = 0; ni < 4; ni++) mma8(C[mi][ni], a[mi], bb[ni]);
        }
    }
    #pragma unroll
    for (int mi = 0; mi < 2; mi++)
        #pragma unroll
        for (int ni = 0; ni < 4; ni++)
            #pragma unroll
            for (int cc = 0; cc < 4; cc++) {
                int o = bo + wm + mi*16 + g + (cc >> 1)*8;
                int n = bn + wn + ni*8 + 2*q4 + (cc & 1);
                float v = C[mi][ni][cc];
                if (o < 256)
                    g_q[((size_t)(b*4 + (o & 3))*NTOT + n)*64 + (o >> 2)] = v;
                else {
                    int c2 = o - 256;
                    g_fv[((size_t)(b*4 + (c2 & 3))*NTOT + n)*64 + (c2 >> 2)] = v;
                }
            }
}

// ------------------ map qv: [512,64] @ smap[b][64][512] ------------------
__global__ void k_map_qv(const float* __restrict__ w, const float* __restrict__ smap)
{
    int m = blockIdx.x * 256 + threadIdx.x;
    int o = blockIdx.y, b = blockIdx.z;
    float s = 0.f;
    #pragma unroll 8
    for (int c = 0; c < 64; c++)
        s += w[o * 64 + c] * smap[((size_t)(b * 64 + c)) * 512 + m];
    if (o < 256)
        g_mq[((size_t)(b * 4 + (o & 3)) * 512 + m) * 64 + (o >> 2)] = s;
    else {
        int c = o - 256;
        g_mv[((size_t)(b * 4 + (c & 3)) * 512 + m) * 64 + (c >> 2)] = s;
    }
}

// ------------------ attention pass 1 (tf32 mma flash block, static smem) ---
// n-tile = 64 rows; loop over 8 chunks of 64 map tokens.
// 8 warps: wn=(w>>2)*32 over n-rows (2 groups), wc=(w&3)*16 over cols (4 groups)
// smem: mqs[64][68] (reused: Q-stage -> map_q chunk -> E tile -> O tile),
//       mvs[64][72], srs[64].  Total 35.3 KB static.
__global__ __launch_bounds__(256) void k_attn1()
{
    __shared__ float mqs[64*68];
    __shared__ float mvs[64*72];
    __shared__ float srs[64];
    int t = threadIdx.x, w = t >> 5, l = t & 31, g = l >> 2, q4 = l & 3;
    int bh = blockIdx.y, b = bh >> 2, h = bh & 3;
    int nb = blockIdx.x * 64;
    int wn = (w >> 2) * 32, wc = (w & 3) * 16;

    if (t < 64) srs[t] = 0.f;
    // stage Q tile [64][64] into mqs
    #pragma unroll
    for (int i = 0; i < 16; i++) {
        int idx = t + i * 256; int n = idx >> 6, d = idx & 63;
        mqs[n*68 + d] = g_q[((size_t)bh*NTOT + nb + n)*64 + d];
    }
    __syncthreads();
    // Q fragments (tf32) held in registers for the whole kernel
    uint32_t QF[8][2][4];
    #pragma unroll
    for (int kk = 0; kk < 8; kk++)
        #pragma unroll
        for (int mi = 0; mi < 2; mi++) {
            const float* ap = &mqs[(wn + mi*16 + g)*68 + kk*8 + q4];
            QF[kk][mi][0] = f2t(ap[0]);
            QF[kk][mi][1] = f2t(ap[8*68]);
            QF[kk][mi][2] = f2t(ap[4]);
            QF[kk][mi][3] = f2t(ap[8*68+4]);
        }
    float OF[2][2][4] = {};
    float rs[2][2] = {};
    float* arow_base = g_attn + (size_t)bh * MTOT * NTOT + nb;

    for (int mc = 0; mc < 8; mc++) {
        __syncthreads();   // prior reads of mqs/mvs done (also QF loads on iter 0)
        #pragma unroll
        for (int i = 0; i < 16; i++) {
            int idx = t + i * 256; int m = idx >> 6, d = idx & 63;
            mqs[m*68 + d] = f2tf(g_mq[((size_t)bh*MTOT + mc*64 + m)*64 + d]);
            mvs[m*72 + d] = f2tf(g_mv[((size_t)bh*MTOT + mc*64 + m)*64 + d]);
        }
        __syncthreads();
        // S = Q @ MQ^T
        float C[2][2][4] = {};
        #pragma unroll
        for (int kk = 0; kk < 8; kk++) {
            uint32_t bb[2][2];
            #pragma unroll
            for (int ni = 0; ni < 2; ni++) {
                const float* bp = &mqs[(wc + ni*8 + g)*68 + kk*8 + q4];
                bb[ni][0] = __float_as_uint(bp[0]);
                bb[ni][1] = __float_as_uint(bp[4]);
            }
            #pragma unroll
            for (int mi = 0; mi < 2; mi++)
                #pragma unroll
                for (int ni = 0; ni < 2; ni++) mma8(C[mi][ni], QF[kk][mi], bb[ni]);
        }
        __syncthreads();   // all warps done reading mqs(MQ) before E overwrites it
        // exp, rowsum, stage E (tf32 bits) into mqs as [n][m]
        #pragma unroll
        for (int mi = 0; mi < 2; mi++)
            #pragma unroll
            for (int ni = 0; ni < 2; ni++)
                #pragma unroll
                for (int cc = 0; cc < 4; cc++) {
                    float e = __expf(C[mi][ni][cc] * SCALE);
                    rs[mi][cc >> 1] += e;
                    mqs[(wn + mi*16 + (cc>>1)*8 + g)*68 + wc + ni*8 + 2*q4 + (cc&1)] = f2tf(e);
                }
        __syncthreads();
        // write E chunk to g_attn [m][n] (coalesced over n)
        float* ar = arow_base + (size_t)(mc * 64) * NTOT;
        #pragma unroll
        for (int i = 0; i < 16; i++) {
            int idx = t + i * 256; int n = idx & 63, m = idx >> 6;
            ar[(size_t)m * NTOT + n] = mqs[n*68 + m];
        }
        // O += E @ MV
        #pragma unroll
        for (int kk = 0; kk < 8; kk++) {
            uint32_t a[2][4], bb[2][2];
            #pragma unroll
            for (int mi = 0; mi < 2; mi++) {
                const float* ap = &mqs[(wn + mi*16 + g)*68 + kk*8 + q4];
                a[mi][0] = __float_as_uint(ap[0]);
                a[mi][1] = __float_as_uint(ap[8*68]);
                a[mi][2] = __float_as_uint(ap[4]);
                a[mi][3] = __float_as_uint(ap[8*68+4]);
            }
            #pragma unroll
            for (int ni = 0; ni < 2; ni++) {
                const float* bp = &mvs[(kk*8 + q4)*72 + wc + ni*8 + g];
                bb[ni][0] = __float_as_uint(bp[0]);
                bb[ni][1] = __float_as_uint(bp[4*72]);
            }
            #pragma unroll
            for (int mi = 0; mi < 2; mi++)
                #pragma unroll
                for (int ni = 0; ni < 2; ni++) mma8(OF[mi][ni], a[mi], bb[ni]);
        }
    }
    // rowsum reduce (lanes sharing a row: q4 quad), accumulate across wc warps
    #pragma unroll
    for (int mi = 0; mi < 2; mi++)
        #pragma unroll
        for (int gh = 0; gh < 2; gh++) {
            float v = rs[mi][gh];
            v += __shfl_xor_sync(0xFFFFFFFFu, v, 1);
            v += __shfl_xor_sync(0xFFFFFFFFu, v, 2);
            if (q4 == 0) atomicAdd(&srs[wn + mi*16 + gh*8 + g], v);
        }
    __syncthreads();
    // normalize + stage O [n][d] into mqs
    #pragma unroll
    for (int mi = 0; mi < 2; mi++) {
        float inv0 = 1.f / srs[wn + mi*16 + g];
        float inv1 = 1.f / srs[wn + mi*16 + 8 + g];
        #pragma unroll
        for (int ni = 0; ni < 2; ni++) {
            int col = wc + ni*8 + 2*q4;
            mqs[(wn + mi*16 + g)*68 + col]       = OF[mi][ni][0] * inv0;
            mqs[(wn + mi*16 + g)*68 + col + 1]   = OF[mi][ni][1] * inv0;
            mqs[(wn + mi*16 + 8 + g)*68 + col]   = OF[mi][ni][2] * inv1;
            mqs[(wn + mi*16 + 8 + g)*68 + col+1] = OF[mi][ni][3] * inv1;
        }
    }
    __syncthreads();
    float* ao = g_attnout + (size_t)b * INNER * NTOT + nb;
    #pragma unroll
    for (int i = 0; i < 16; i++) {
        int idx = t + i * 256; int n = idx & 63, d = idx >> 6;
        ao[(size_t)(4*d + h) * NTOT + n] = mqs[n*68 + d];
    }
}

// ------------------ zero accumulators ------------------
__global__ void k_zero()
{
    int i = blockIdx.x * 256 + threadIdx.x;
    if (i < BSZ * NHEAD * MTOT * DHEAD) g_monum[i] = 0.f;
    if (i < BSZ * NHEAD * MTOT)         g_colsum[i] = 0.f;
}

// ------------------ attention pass 2 (tf32 mma, split-K) ------------------
__global__ __launch_bounds__(256) void k_attn2()
{
    __shared__ float As[128*36];  // [m][k] (E already tf32 bits in g_attn)
    __shared__ float Bs[32*72];   // [k(n)][d]
    __shared__ float scs[128];
    int t = threadIdx.x, w = t >> 5, l = t & 31, g = l >> 2, q4 = l & 3;
    int bh = blockIdx.z; int mtile = blockIdx.y * 128; int nb = blockIdx.x * KLEN;
    int wm = (w >> 1) * 32, wd = (w & 1) * 32;
    const float* Ab = g_attn + (size_t)bh * MTOT * NTOT;
    const float* Vb = g_fv + (size_t)bh * NTOT * 64;
    float C[2][4][4] = {};
    float cs[16];
    #pragma unroll
    for (int i = 0; i < 16; i++) cs[i] = 0.f;
    if (t < 128) scs[t] = 0.f;

    for (int kb = 0; kb < KLEN; kb += 32) {
        __syncthreads();
        #pragma unroll
        for (int i = 0; i < 16; i++) {
            int idx = t + i * 256; int m = idx >> 5, k = idx & 31;
            float v = Ab[(size_t)(mtile + m)*NTOT + nb + kb + k];
            As[m*36 + k] = v;
            cs[i] += v;
        }
        #pragma unroll
        for (int i = 0; i < 8; i++) {
            int idx = t + i * 256; int nr = idx >> 6, d = idx & 63;
            Bs[nr*72 + d] = f2tf(Vb[(size_t)(nb + kb + nr)*64 + d]);
        }
        __syncthreads();
        #pragma unroll
        for (int kk = 0; kk < 4; kk++) {
            uint32_t a[2][4], bb[4][2];
            #pragma unroll
            for (int mi = 0; mi < 2; mi++) {
                const float* ap = &As[(wm + mi*16 + g)*36 + kk*8 + q4];
                a[mi][0] = __float_as_uint(ap[0]);
                a[mi][1] = __float_as_uint(ap[8*36]);
                a[mi][2] = __float_as_uint(ap[4]);
                a[mi][3] = __float_as_uint(ap[8*36+4]);
            }
            #pragma unroll
            for (int ni = 0; ni < 4; ni++) {
                const float* bp = &Bs[(kk*8 + q4)*72 + wd + ni*8 + g];
                bb[ni][0] = __float_as_uint(bp[0]);
                bb[ni][1] = __float_as_uint(bp[4*72]);
            }
            #pragma unroll
            for (int mi = 0; mi < 2; mi++)
                #pragma unroll
                for (int ni = 0; ni < 4; ni++) mma8(C[mi][ni], a[mi], bb[ni]);
        }
    }
    #pragma unroll
    for (int i = 0; i < 16; i++) {
        float v = cs[i];
        v += __shfl_xor_sync(0xFFFFFFFFu, v, 16);
        v += __shfl_xor_sync(0xFFFFFFFFu, v, 8);
        v += __shfl_xor_sync(0xFFFFFFFFu, v, 4);
        v += __shfl_xor_sync(0xFFFFFFFFu, v, 2);
        v += __shfl_xor_sync(0xFFFFFFFFu, v, 1);
        if (l == 0) atomicAdd(&scs[w + i*8], v);
    }
    __syncthreads();
    if (t < 128) atomicAdd(&g_colsum[(size_t)bh*MTOT + mtile + t], scs[t]);
    #pragma unroll
    for (int mi = 0; mi < 2; mi++)
        #pragma unroll
        for (int ni = 0; ni < 4; ni++)
            #pragma unroll
            for (int cc = 0; cc < 4; cc++) {
                int m = mtile + wm + mi*16 + g + (cc >> 1)*8;
                int d = wd + ni*8 + 2*q4 + (cc & 1);
                atomicAdd(&g_monum[((size_t)bh*MTOT + m)*64 + d], C[mi][ni][cc]);
            }
}

// ------------------ finalize map_out ------------------
__global__ void k_mapout(const float* __restrict__ w, float* __restrict__ outp)
{
    int gid = blockIdx.x * 256 + threadIdx.x;
    int m = gid & 511;
    int o = (gid >> 9) & 63;
    int b = gid >> 15;
    float inv[4];
    #pragma unroll
    for (int hh = 0; hh < 4; hh++)
        inv[hh] = 1.f / g_colsum[(size_t)(b * 4 + hh) * 512 + m];
    float s = 0.f;
    #pragma unroll 4
    for (int c = 0; c < 256; c++) {
        int d = c >> 2, hh = c & 3;
        s += w[o * 256 + c] * g_monum[((size_t)(b * 4 + hh) * 512 + m) * 64 + d] * inv[hh];
    }
    outp[(size_t)FEAT_OUT_ELEMS + ((size_t)(b * 64 + o)) * 512 + m] = s;
}

// ------------------ pointwise out GEMM (tf32 mma): [128,256]@[256,N] ------
__global__ __launch_bounds__(256) void k_pw_out(const float* __restrict__ A,
                                                float* __restrict__ outp)
{
    __shared__ float As[64*36];
    __shared__ float Bs[32*136];
    int t = threadIdx.x, w = t >> 5, l = t & 31, g = l >> 2, q4 = l & 3;
    int bn = blockIdx.x * 128, bo = blockIdx.y * 64, b = blockIdx.z;
    int wm = (w >> 2) * 32, wn = (w & 3) * 32;
    float C[2][4][4] = {};
    const float* Xb = g_dw2 + (size_t)b * INNER * NTOT;
    for (int kc = 0; kc < 256; kc += 32) {
        __syncthreads();
        #pragma unroll
        for (int i = 0; i < 8; i++) {
            int idx = t + i * 256; int m = idx >> 5, k = idx & 31;
            As[m*36 + k] = f2tf(A[(bo + m)*256 + kc + k]);
        }
        #pragma unroll
        for (int i = 0; i < 16; i++) {
            int idx = t + i * 256; int k = idx >> 7, n = idx & 127;
            Bs[k*136 + n] = f2tf(Xb[(size_t)(kc + k)*NTOT + bn + n]);
        }
        __syncthreads();
        #pragma unroll
        for (int kk = 0; kk < 4; kk++) {
            uint32_t a[2][4], bb[4][2];
            #pragma unroll
            for (int mi = 0; mi < 2; mi++) {
                const float* ap = &As[(wm + mi*16 + g)*36 + kk*8 + q4];
                a[mi][0] = __float_as_uint(ap[0]);
                a[mi][1] = __float_as_uint(ap[8*36]);
                a[mi][2] = __float_as_uint(ap[4]);
                a[mi][3] = __float_as_uint(ap[8*36+4]);
            }
            #pragma unroll
            for (int ni = 0; ni < 4; ni++) {
                const float* bp = &Bs[(kk*8 + q4)*136 + wn + ni*8 + g];
                bb[ni][0] = __float_as_uint(bp[0]);
                bb[ni][1] = __float_as_uint(bp[4*136]);
            }
            #pragma unroll
            for (int mi = 0; mi < 2; mi++)
                #pragma unroll
                for (int ni = 0; ni < 4; ni++) mma8(C[mi][ni], a[mi], bb[ni]);
        }
    }
    #pragma unroll
    for (int mi = 0; mi < 2; mi++)
        #pragma unroll
        for (int ni = 0; ni < 4; ni++)
            #pragma unroll
            for (int cc = 0; cc < 4; cc++) {
                int o = bo + wm + mi*16 + g + (cc >> 1)*8;
                int n = bn + wn + ni*8 + 2*q4 + (cc & 1);
                outp[((size_t)(b * 128 + o)) * NTOT + n] = C[mi][ni][cc];
            }
}

// ------------------ launch ------------------
extern "C" void kernel_launch(void* const* d_in, const int* in_sizes, int n_in,
                              void* d_out, int out_size)
{
    const float* feat    = (const float*)d_in[0];
    const float* smap    = (const float*)d_in[1];
    const float* fqv_dw  = (const float*)d_in[2];
    const float* fqv_pw  = (const float*)d_in[3];
    const float* fout_dw = (const float*)d_in[4];
    const float* fout_pw = (const float*)d_in[5];
    const float* mqv_w   = (const float*)d_in[6];
    const float* mout_w  = (const float*)d_in[7];
    float* outp = (float*)d_out;

    k_dwconv1<<<dim3(54, 128, 2), 256>>>(feat, fqv_dw);
    k_pw_qv  <<<dim3(108, 8, 2), 256>>>(fqv_pw);
    k_map_qv <<<dim3(2, 512, 2), 256>>>(mqv_w, smap);
    k_zero   <<<1024, 256>>>();
    k_attn1  <<<dim3(216, 8), 256>>>();
    k_attn2  <<<dim3(KSPLIT, 4, 8), 256>>>();
    k_mapout <<<256, 256>>>(mout_w, outp);
    k_dwconv2<<<dim3(54, 256, 2), 256>>>(fout_dw);
    k_pw_out <<<dim3(108, 2, 2), 256>>>(fout_pw, outp);
}

// round 6
// speedup vs baseline: 2.4794x; 1.3320x over previous
#include <cuda_runtime.h>
#include <math.h>
#include <stdint.h>

#define BSZ   2
#define CF    128
#define NTOT  13824      // 24^3
#define MTOT  512        // 8^3
#define NHEAD 4
#define DHEAD 64
#define INNER 256
#define SCALE 0.125f     // 64^-0.5
#define FEAT_OUT_ELEMS 3538944   // 2*128*13824
#define KSPLIT 9
#define KLEN   1536      // 13824/9

// ------------------ scratch (device globals; no allocs) ------------------
__device__ __align__(16) float g_t1   [BSZ*CF*NTOT];            // dwconv1 out
__device__ __align__(16) float g_q    [BSZ*NHEAD*NTOT*DHEAD];   // feat_q  [bh][n][d]
__device__ __align__(16) float g_fv   [BSZ*NHEAD*NTOT*DHEAD];   // feat_v  [bh][n][d]
__device__ __align__(16) float g_mq   [BSZ*NHEAD*MTOT*DHEAD];   // map_q   [bh][m][d]
__device__ __align__(16) float g_mv   [BSZ*NHEAD*MTOT*DHEAD];   // map_v   [bh][m][d]
__device__ __align__(16) float g_attn [(size_t)BSZ*NHEAD*MTOT*NTOT]; // E [bh][m][n] (tf32 bits)
__device__ __align__(16) float g_attnout[BSZ*INNER*NTOT];       // feat attn out [b][c][n]
__device__ __align__(16) float g_dw2  [BSZ*INNER*NTOT];         // dwconv2 out
__device__ __align__(16) float g_monum[BSZ*NHEAD*MTOT*DHEAD];   // map_out numerator
__device__ __align__(16) float g_colsum[BSZ*NHEAD*MTOT];

// ------------------ tf32 mma helpers ------------------
__device__ __forceinline__ uint32_t f2t(float x){
    uint32_t r; asm("cvt.rna.tf32.f32 %0,%1;":"=r"(r):"f"(x)); return r;
}
__device__ __forceinline__ float f2tf(float x){ return __uint_as_float(f2t(x)); }
__device__ __forceinline__ float4 f2tf4(float4 v){
    v.x = f2tf(v.x); v.y = f2tf(v.y); v.z = f2tf(v.z); v.w = f2tf(v.w); return v;
}

__device__ __forceinline__ void mma8(float* c, const uint32_t* a, const uint32_t* b){
    asm volatile("mma.sync.aligned.m16n8k8.row.col.f32.tf32.tf32.f32 "
        "{%0,%1,%2,%3},{%4,%5,%6,%7},{%8,%9},{%0,%1,%2,%3};"
        : "+f"(c[0]),"+f"(c[1]),"+f"(c[2]),"+f"(c[3])
        : "r"(a[0]),"r"(a[1]),"r"(a[2]),"r"(a[3]),"r"(b[0]),"r"(b[1]));
}

// ------------------ depthwise 3x3x3, SAME, x-vectorized (4 outputs/thread) --
__device__ __forceinline__ void dw_body_v4(const float* __restrict__ in,
                                           const float* __restrict__ w,
                                           float* __restrict__ out, int C)
{
    __shared__ float ws[27];
    int t = threadIdx.x;
    int c = blockIdx.y, b = blockIdx.z;
    if (t < 27) ws[t] = w[c * 27 + t];
    __syncthreads();
    int idx = blockIdx.x * 256 + t;          // over 24*24*6 = 3456
    if (idx >= 3456) return;
    int x4 = (idx % 6) * 4;
    int y  = (idx / 6) % 24;
    int z  = idx / 144;
    const float* ip = in + ((size_t)(b * C + c)) * NTOT;
    float acc0 = 0.f, acc1 = 0.f, acc2 = 0.f, acc3 = 0.f;
    #pragma unroll
    for (int dz = -1; dz <= 1; dz++) {
        int zz = z + dz; if (zz < 0 || zz >= 24) continue;
        #pragma unroll
        for (int dy = -1; dy <= 1; dy++) {
            int yy = y + dy; if (yy < 0 || yy >= 24) continue;
            const float* row = ip + (zz * 24 + yy) * 24;
            float4 mid = *(const float4*)(row + x4);
            float left  = (x4 > 0)      ? row[x4 - 1] : 0.f;
            float right = (x4 + 4 < 24) ? row[x4 + 4] : 0.f;
            const float* wr = ws + (dz + 1) * 9 + (dy + 1) * 3;
            float w0 = wr[0], w1 = wr[1], w2 = wr[2];
            acc0 += w0 * left  + w1 * mid.x + w2 * mid.y;
            acc1 += w0 * mid.x + w1 * mid.y + w2 * mid.z;
            acc2 += w0 * mid.y + w1 * mid.z + w2 * mid.w;
            acc3 += w0 * mid.z + w1 * mid.w + w2 * right;
        }
    }
    float4 o = make_float4(acc0, acc1, acc2, acc3);
    *(float4*)(out + ((size_t)(b * C + c)) * NTOT + (z * 24 + y) * 24 + x4) = o;
}

__global__ void k_dwconv1(const float* __restrict__ feat, const float* __restrict__ w)
{   dw_body_v4(feat, w, g_t1, CF); }

__global__ void k_dwconv2(const float* __restrict__ w)
{   dw_body_v4(g_attnout, w, g_dw2, INNER); }

// ------------------ pointwise qv GEMM (tf32 mma): [512,128]@[128,N] + head scatter
__global__ __launch_bounds__(256) void k_pw_qv(const float* __restrict__ A)
{
    __shared__ float As[64*36];   // [m][k] pitch 36
    __shared__ float Bs[32*136];  // [k][n] pitch 136
    int t = threadIdx.x, w = t >> 5, l = t & 31, g = l >> 2, q4 = l & 3;
    int bn = blockIdx.x * 128, bo = blockIdx.y * 64, b = blockIdx.z;
    int wm = (w >> 2) * 32, wn = (w & 3) * 32;
    float C[2][4][4] = {};
    const float* Xb = g_t1 + (size_t)b * CF * NTOT;
    for (int kc = 0; kc < 128; kc += 32) {
        __syncthreads();
        #pragma unroll
        for (int i = 0; i < 2; i++) {
            int idx = t + i * 256; int m = idx >> 3, k4 = idx & 7;
            float4 v = f2tf4(*(const float4*)&A[(bo + m)*128 + kc + k4*4]);
            *(float4*)&As[m*36 + k4*4] = v;
        }
        #pragma unroll
        for (int i = 0; i < 4; i++) {
            int idx = t + i * 256; int k = idx >> 5, n4 = idx & 31;
            float4 v = f2tf4(*(const float4*)&Xb[(size_t)(kc + k)*NTOT + bn + n4*4]);
            *(float4*)&Bs[k*136 + n4*4] = v;
        }
        __syncthreads();
        #pragma unroll
        for (int kk = 0; kk < 4; kk++) {
            uint32_t a[2][4], bb[4][2];
            #pragma unroll
            for (int mi = 0; mi < 2; mi++) {
                const float* ap = &As[(wm + mi*16 + g)*36 + kk*8 + q4];
                a[mi][0] = __float_as_uint(ap[0]);
                a[mi][1] = __float_as_uint(ap[8*36]);
                a[mi][2] = __float_as_uint(ap[4]);
                a[mi][3] = __float_as_uint(ap[8*36+4]);
            }
            #pragma unroll
            for (int ni = 0; ni < 4; ni++) {
                const float* bp = &Bs[(kk*8 + q4)*136 + wn + ni*8 + g];
                bb[ni][0] = __float_as_uint(bp[0]);
                bb[ni][1] = __float_as_uint(bp[4*136]);
            }
            #pragma unroll
            for (int mi = 0; mi < 2; mi++)
                #pragma unroll
                for (int ni = 0; ni < 4; ni++) mma8(C[mi][ni], a[mi], bb[ni]);
        }
    }
    #pragma unroll
    for (int mi = 0; mi < 2; mi++)
        #pragma unroll
        for (int ni = 0; ni < 4; ni++)
            #pragma unroll
            for (int cc = 0; cc < 4; cc++) {
                int o = bo + wm + mi*16 + g + (cc >> 1)*8;
                int n = bn + wn + ni*8 + 2*q4 + (cc & 1);
                float v = C[mi][ni][cc];
                if (o < 256)
                    g_q[((size_t)(b*4 + (o & 3))*NTOT + n)*64 + (o >> 2)] = v;
                else {
                    int c2 = o - 256;
                    g_fv[((size_t)(b*4 + (c2 & 3))*NTOT + n)*64 + (c2 >> 2)] = v;
                }
            }
}

// ------------------ map qv: [512,64] @ smap[b][64][512] ------------------
__global__ void k_map_qv(const float* __restrict__ w, const float* __restrict__ smap)
{
    int m = blockIdx.x * 256 + threadIdx.x;
    int o = blockIdx.y, b = blockIdx.z;
    float s = 0.f;
    #pragma unroll 8
    for (int c = 0; c < 64; c++)
        s += w[o * 64 + c] * smap[((size_t)(b * 64 + c)) * 512 + m];
    if (o < 256)
        g_mq[((size_t)(b * 4 + (o & 3)) * 512 + m) * 64 + (o >> 2)] = s;
    else {
        int c = o - 256;
        g_mv[((size_t)(b * 4 + (c & 3)) * 512 + m) * 64 + (c >> 2)] = s;
    }
}

// ------------------ attention pass 1 (tf32 mma flash block) ---------------
// n-tile 64; loop 8 chunks of 64 map tokens. 8 warps: wn=(w>>2)*32, wc=(w&3)*16
__global__ __launch_bounds__(256, 2) void k_attn1()
{
    __shared__ float mqs[64*68];  // Q-stage -> MQ chunk -> E tile -> O tile
    __shared__ float mvs[64*72];
    __shared__ float srs[64];
    int t = threadIdx.x, w = t >> 5, l = t & 31, g = l >> 2, q4 = l & 3;
    int bh = blockIdx.y, b = bh >> 2, h = bh & 3;
    int nb = blockIdx.x * 64;
    int wn = (w >> 2) * 32, wc = (w & 3) * 16;

    if (t < 64) srs[t] = 0.f;
    // stage Q tile [64][64] into mqs (float4)
    #pragma unroll
    for (int i = 0; i < 4; i++) {
        int idx = t + i * 256; int n = idx >> 4, d4 = idx & 15;
        float4 v = *(const float4*)&g_q[((size_t)bh*NTOT + nb + n)*64 + d4*4];
        *(float4*)&mqs[n*68 + d4*4] = v;
    }
    __syncthreads();
    uint32_t QF[8][2][4];
    #pragma unroll
    for (int kk = 0; kk < 8; kk++)
        #pragma unroll
        for (int mi = 0; mi < 2; mi++) {
            const float* ap = &mqs[(wn + mi*16 + g)*68 + kk*8 + q4];
            QF[kk][mi][0] = f2t(ap[0]);
            QF[kk][mi][1] = f2t(ap[8*68]);
            QF[kk][mi][2] = f2t(ap[4]);
            QF[kk][mi][3] = f2t(ap[8*68+4]);
        }
    float OF[2][2][4] = {};
    float rs[2][2] = {};
    float* arow_base = g_attn + (size_t)bh * MTOT * NTOT + nb;

    for (int mc = 0; mc < 8; mc++) {
        __syncthreads();
        #pragma unroll
        for (int i = 0; i < 4; i++) {
            int idx = t + i * 256; int m = idx >> 4, d4 = idx & 15;
            float4 vq = f2tf4(*(const float4*)&g_mq[((size_t)bh*MTOT + mc*64 + m)*64 + d4*4]);
            float4 vv = f2tf4(*(const float4*)&g_mv[((size_t)bh*MTOT + mc*64 + m)*64 + d4*4]);
            *(float4*)&mqs[m*68 + d4*4] = vq;
            *(float4*)&mvs[m*72 + d4*4] = vv;
        }
        __syncthreads();
        // S = Q @ MQ^T
        float C[2][2][4] = {};
        #pragma unroll
        for (int kk = 0; kk < 8; kk++) {
            uint32_t bb[2][2];
            #pragma unroll
            for (int ni = 0; ni < 2; ni++) {
                const float* bp = &mqs[(wc + ni*8 + g)*68 + kk*8 + q4];
                bb[ni][0] = __float_as_uint(bp[0]);
                bb[ni][1] = __float_as_uint(bp[4]);
            }
            #pragma unroll
            for (int mi = 0; mi < 2; mi++)
                #pragma unroll
                for (int ni = 0; ni < 2; ni++) mma8(C[mi][ni], QF[kk][mi], bb[ni]);
        }
        __syncthreads();   // all warps done reading mqs(MQ) before E overwrites it
        // exp, rowsum, stage E (tf32 bits) into mqs as [n][m]
        #pragma unroll
        for (int mi = 0; mi < 2; mi++)
            #pragma unroll
            for (int ni = 0; ni < 2; ni++)
                #pragma unroll
                for (int cc = 0; cc < 4; cc++) {
                    float e = __expf(C[mi][ni][cc] * SCALE);
                    rs[mi][cc >> 1] += e;
                    mqs[(wn + mi*16 + (cc>>1)*8 + g)*68 + wc + ni*8 + 2*q4 + (cc&1)] = f2tf(e);
                }
        __syncthreads();
        // write E chunk to g_attn [m][n] (STG.128 over n)
        float* ar = arow_base + (size_t)(mc * 64) * NTOT;
        #pragma unroll
        for (int i = 0; i < 4; i++) {
            int idx = t + i * 256; int m = idx >> 4, n4 = idx & 15;
            float4 v;
            v.x = mqs[(n4*4+0)*68 + m];
            v.y = mqs[(n4*4+1)*68 + m];
            v.z = mqs[(n4*4+2)*68 + m];
            v.w = mqs[(n4*4+3)*68 + m];
            *(float4*)&ar[(size_t)m * NTOT + n4*4] = v;
        }
        // O += E @ MV
        #pragma unroll
        for (int kk = 0; kk < 8; kk++) {
            uint32_t a[2][4], bb[2][2];
            #pragma unroll
            for (int mi = 0; mi < 2; mi++) {
                const float* ap = &mqs[(wn + mi*16 + g)*68 + kk*8 + q4];
                a[mi][0] = __float_as_uint(ap[0]);
                a[mi][1] = __float_as_uint(ap[8*68]);
                a[mi][2] = __float_as_uint(ap[4]);
                a[mi][3] = __float_as_uint(ap[8*68+4]);
            }
            #pragma unroll
            for (int ni = 0; ni < 2; ni++) {
                const float* bp = &mvs[(kk*8 + q4)*72 + wc + ni*8 + g];
                bb[ni][0] = __float_as_uint(bp[0]);
                bb[ni][1] = __float_as_uint(bp[4*72]);
            }
            #pragma unroll
            for (int mi = 0; mi < 2; mi++)
                #pragma unroll
                for (int ni = 0; ni < 2; ni++) mma8(OF[mi][ni], a[mi], bb[ni]);
        }
    }
    // rowsum reduce
    #pragma unroll
    for (int mi = 0; mi < 2; mi++)
        #pragma unroll
        for (int gh = 0; gh < 2; gh++) {
            float v = rs[mi][gh];
            v += __shfl_xor_sync(0xFFFFFFFFu, v, 1);
            v += __shfl_xor_sync(0xFFFFFFFFu, v, 2);
            if (q4 == 0) atomicAdd(&srs[wn + mi*16 + gh*8 + g], v);
        }
    __syncthreads();
    // normalize + stage O [n][d] into mqs
    #pragma unroll
    for (int mi = 0; mi < 2; mi++) {
        float inv0 = 1.f / srs[wn + mi*16 + g];
        float inv1 = 1.f / srs[wn + mi*16 + 8 + g];
        #pragma unroll
        for (int ni = 0; ni < 2; ni++) {
            int col = wc + ni*8 + 2*q4;
            mqs[(wn + mi*16 + g)*68 + col]       = OF[mi][ni][0] * inv0;
            mqs[(wn + mi*16 + g)*68 + col + 1]   = OF[mi][ni][1] * inv0;
            mqs[(wn + mi*16 + 8 + g)*68 + col]   = OF[mi][ni][2] * inv1;
            mqs[(wn + mi*16 + 8 + g)*68 + col+1] = OF[mi][ni][3] * inv1;
        }
    }
    __syncthreads();
    float* ao = g_attnout + (size_t)b * INNER * NTOT + nb;
    #pragma unroll
    for (int i = 0; i < 4; i++) {
        int idx = t + i * 256; int d = idx >> 4, n4 = idx & 15;
        float4 v;
        v.x = mqs[(n4*4+0)*68 + d];
        v.y = mqs[(n4*4+1)*68 + d];
        v.z = mqs[(n4*4+2)*68 + d];
        v.w = mqs[(n4*4+3)*68 + d];
        *(float4*)&ao[(size_t)(4*d + h) * NTOT + n4*4] = v;
    }
}

// ------------------ zero accumulators (split for ncu launch indexing) ------
__global__ void k_zero_a()
{
    int i = blockIdx.x * 256 + threadIdx.x;
    if (i < BSZ * NHEAD * MTOT * DHEAD) g_monum[i] = 0.f;
}
__global__ void k_zero_b()
{
    int i = blockIdx.x * 256 + threadIdx.x;
    if (i < BSZ * NHEAD * MTOT) g_colsum[i] = 0.f;
}

// ------------------ attention pass 2 (tf32 mma, split-K) ------------------
__global__ __launch_bounds__(256) void k_attn2()
{
    __shared__ float As[128*36];  // [m][k] (E already tf32 bits in g_attn)
    __shared__ float Bs[32*72];   // [k(n)][d]
    __shared__ float scs[128];
    int t = threadIdx.x, w = t >> 5, l = t & 31, g = l >> 2, q4 = l & 3;
    int bh = blockIdx.z; int mtile = blockIdx.y * 128; int nb = blockIdx.x * KLEN;
    int wm = (w >> 1) * 32, wd = (w & 1) * 32;
    const float* Ab = g_attn + (size_t)bh * MTOT * NTOT;
    const float* Vb = g_fv + (size_t)bh * NTOT * 64;
    float C[2][4][4] = {};
    float cs[4] = {};
    if (t < 128) scs[t] = 0.f;

    for (int kb = 0; kb < KLEN; kb += 32) {
        __syncthreads();
        #pragma unroll
        for (int i = 0; i < 4; i++) {
            int idx = t + i * 256; int m = idx >> 3, k4 = idx & 7;
            float4 v = *(const float4*)&Ab[(size_t)(mtile + m)*NTOT + nb + kb + k4*4];
            *(float4*)&As[m*36 + k4*4] = v;
            cs[i] += (v.x + v.y) + (v.z + v.w);
        }
        #pragma unroll
        for (int i = 0; i < 2; i++) {
            int idx = t + i * 256; int nr = idx >> 4, d4 = idx & 15;
            float4 v = f2tf4(*(const float4*)&Vb[(size_t)(nb + kb + nr)*64 + d4*4]);
            *(float4*)&Bs[nr*72 + d4*4] = v;
        }
        __syncthreads();
        #pragma unroll
        for (int kk = 0; kk < 4; kk++) {
            uint32_t a[2][4], bb[4][2];
            #pragma unroll
            for (int mi = 0; mi < 2; mi++) {
                const float* ap = &As[(wm + mi*16 + g)*36 + kk*8 + q4];
                a[mi][0] = __float_as_uint(ap[0]);
                a[mi][1] = __float_as_uint(ap[8*36]);
                a[mi][2] = __float_as_uint(ap[4]);
                a[mi][3] = __float_as_uint(ap[8*36+4]);
            }
            #pragma unroll
            for (int ni = 0; ni < 4; ni++) {
                const float* bp = &Bs[(kk*8 + q4)*72 + wd + ni*8 + g];
                bb[ni][0] = __float_as_uint(bp[0]);
                bb[ni][1] = __float_as_uint(bp[4*72]);
            }
            #pragma unroll
            for (int mi = 0; mi < 2; mi++)
                #pragma unroll
                for (int ni = 0; ni < 4; ni++) mma8(C[mi][ni], a[mi], bb[ni]);
        }
    }
    // colsum: cs[i] belongs to m = (t>>3) + i*32; 8 lanes (l&7) share each m
    #pragma unroll
    for (int i = 0; i < 4; i++) {
        float v = cs[i];
        v += __shfl_xor_sync(0xFFFFFFFFu, v, 1);
        v += __shfl_xor_sync(0xFFFFFFFFu, v, 2);
        v += __shfl_xor_sync(0xFFFFFFFFu, v, 4);
        if ((l & 7) == 0) atomicAdd(&scs[(t >> 3) + i * 32], v);
    }
    __syncthreads();
    if (t < 128) atomicAdd(&g_colsum[(size_t)bh*MTOT + mtile + t], scs[t]);
    #pragma unroll
    for (int mi = 0; mi < 2; mi++)
        #pragma unroll
        for (int ni = 0; ni < 4; ni++)
            #pragma unroll
            for (int cc = 0; cc < 4; cc++) {
                int m = mtile + wm + mi*16 + g + (cc >> 1)*8;
                int d = wd + ni*8 + 2*q4 + (cc & 1);
                atomicAdd(&g_monum[((size_t)bh*MTOT + m)*64 + d], C[mi][ni][cc]);
            }
}

// ------------------ finalize map_out ------------------
__global__ void k_mapout(const float* __restrict__ w, float* __restrict__ outp)
{
    int gid = blockIdx.x * 256 + threadIdx.x;
    int m = gid & 511;
    int o = (gid >> 9) & 63;
    int b = gid >> 15;
    float inv[4];
    #pragma unroll
    for (int hh = 0; hh < 4; hh++)
        inv[hh] = 1.f / g_colsum[(size_t)(b * 4 + hh) * 512 + m];
    float s = 0.f;
    #pragma unroll 4
    for (int c = 0; c < 256; c++) {
        int d = c >> 2, hh = c & 3;
        s += w[o * 256 + c] * g_monum[((size_t)(b * 4 + hh) * 512 + m) * 64 + d] * inv[hh];
    }
    outp[(size_t)FEAT_OUT_ELEMS + ((size_t)(b * 64 + o)) * 512 + m] = s;
}

// ------------------ pointwise out GEMM (tf32 mma): [128,256]@[256,N] ------
__global__ __launch_bounds__(256) void k_pw_out(const float* __restrict__ A,
                                                float* __restrict__ outp)
{
    __shared__ float As[64*36];
    __shared__ float Bs[32*136];
    int t = threadIdx.x, w = t >> 5, l = t & 31, g = l >> 2, q4 = l & 3;
    int bn = blockIdx.x * 128, bo = blockIdx.y * 64, b = blockIdx.z;
    int wm = (w >> 2) * 32, wn = (w & 3) * 32;
    float C[2][4][4] = {};
    const float* Xb = g_dw2 + (size_t)b * INNER * NTOT;
    for (int kc = 0; kc < 256; kc += 32) {
        __syncthreads();
        #pragma unroll
        for (int i = 0; i < 2; i++) {
            int idx = t + i * 256; int m = idx >> 3, k4 = idx & 7;
            float4 v = f2tf4(*(const float4*)&A[(bo + m)*256 + kc + k4*4]);
            *(float4*)&As[m*36 + k4*4] = v;
        }
        #pragma unroll
        for (int i = 0; i < 4; i++) {
            int idx = t + i * 256; int k = idx >> 5, n4 = idx & 31;
            float4 v = f2tf4(*(const float4*)&Xb[(size_t)(kc + k)*NTOT + bn + n4*4]);
            *(float4*)&Bs[k*136 + n4*4] = v;
        }
        __syncthreads();
        #pragma unroll
        for (int kk = 0; kk < 4; kk++) {
            uint32_t a[2][4], bb[4][2];
            #pragma unroll
            for (int mi = 0; mi < 2; mi++) {
                const float* ap = &As[(wm + mi*16 + g)*36 + kk*8 + q4];
                a[mi][0] = __float_as_uint(ap[0]);
                a[mi][1] = __float_as_uint(ap[8*36]);
                a[mi][2] = __float_as_uint(ap[4]);
                a[mi][3] = __float_as_uint(ap[8*36+4]);
            }
            #pragma unroll
            for (int ni = 0; ni < 4; ni++) {
                const float* bp = &Bs[(kk*8 + q4)*136 + wn + ni*8 + g];
                bb[ni][0] = __float_as_uint(bp[0]);
                bb[ni][1] = __float_as_uint(bp[4*136]);
            }
            #pragma unroll
            for (int mi = 0; mi < 2; mi++)
                #pragma unroll
                for (int ni = 0; ni < 4; ni++) mma8(C[mi][ni], a[mi], bb[ni]);
        }
    }
    #pragma unroll
    for (int mi = 0; mi < 2; mi++)
        #pragma unroll
        for (int ni = 0; ni < 4; ni++)
            #pragma unroll
            for (int cc = 0; cc < 4; cc++) {
                int o = bo + wm + mi*16 + g + (cc >> 1)*8;
                int n = bn + wn + ni*8 + 2*q4 + (cc & 1);
                outp[((size_t)(b * 128 + o)) * NTOT + n] = C[mi][ni][cc];
            }
}

// ------------------ launch ------------------
extern "C" void kernel_launch(void* const* d_in, const int* in_sizes, int n_in,
                              void* d_out, int out_size)
{
    const float* feat    = (const float*)d_in[0];
    const float* smap    = (const float*)d_in[1];
    const float* fqv_dw  = (const float*)d_in[2];
    const float* fqv_pw  = (const float*)d_in[3];
    const float* fout_dw = (const float*)d_in[4];
    const float* fout_pw = (const float*)d_in[5];
    const float* mqv_w   = (const float*)d_in[6];
    const float* mout_w  = (const float*)d_in[7];
    float* outp = (float*)d_out;

    k_zero_a <<<1024, 256>>>();
    k_zero_b <<<16, 256>>>();
    k_dwconv1<<<dim3(14, 128, 2), 256>>>(feat, fqv_dw);
    k_map_qv <<<dim3(2, 512, 2), 256>>>(mqv_w, smap);
    k_pw_qv  <<<dim3(108, 8, 2), 256>>>(fqv_pw);
    k_attn1  <<<dim3(216, 8), 256>>>();
    k_attn2  <<<dim3(KSPLIT, 4, 8), 256>>>();
    k_mapout <<<256, 256>>>(mout_w, outp);
    k_dwconv2<<<dim3(14, 256, 2), 256>>>(fout_dw);
    k_pw_out <<<dim3(108, 2, 2), 256>>>(fout_pw, outp);
}

// round 7
// speedup vs baseline: 2.7247x; 1.0989x over previous
#include <cuda_runtime.h>
#include <math.h>
#include <stdint.h>

#define BSZ   2
#define CF    128
#define NTOT  13824      // 24^3
#define MTOT  512        // 8^3
#define NHEAD 4
#define DHEAD 64
#define INNER 256
#define SCALE 0.125f     // 64^-0.5
#define FEAT_OUT_ELEMS 3538944   // 2*128*13824
#define KSPLIT 9
#define KLEN   1536      // 13824/9

// ------------------ scratch (device globals; no allocs) ------------------
__device__ __align__(16) float g_t1   [BSZ*CF*NTOT];            // dwconv1 out
__device__ __align__(16) float g_q    [BSZ*NHEAD*NTOT*DHEAD];   // feat_q  [bh][n][d]
__device__ __align__(16) float g_fv   [BSZ*NHEAD*NTOT*DHEAD];   // feat_v  [bh][n][d]
__device__ __align__(16) float g_mq   [BSZ*NHEAD*MTOT*DHEAD];   // map_q   [bh][m][d]
__device__ __align__(16) float g_mv   [BSZ*NHEAD*MTOT*DHEAD];   // map_v   [bh][m][d]
__device__ __align__(16) float g_attnout[BSZ*INNER*NTOT];       // feat attn out [b][c][n]
__device__ __align__(16) float g_dw2  [BSZ*INNER*NTOT];         // dwconv2 out
__device__ __align__(16) float g_monum[BSZ*NHEAD*MTOT*DHEAD];   // map_out numerator
__device__ __align__(16) float g_colsum[BSZ*NHEAD*MTOT];

// ------------------ tf32 mma helpers ------------------
__device__ __forceinline__ uint32_t f2t(float x){
    uint32_t r; asm("cvt.rna.tf32.f32 %0,%1;":"=r"(r):"f"(x)); return r;
}
__device__ __forceinline__ float f2tf(float x){ return __uint_as_float(f2t(x)); }
__device__ __forceinline__ float4 f2tf4(float4 v){
    v.x = f2tf(v.x); v.y = f2tf(v.y); v.z = f2tf(v.z); v.w = f2tf(v.w); return v;
}

__device__ __forceinline__ void mma8(float* c, const uint32_t* a, const uint32_t* b){
    asm volatile("mma.sync.aligned.m16n8k8.row.col.f32.tf32.tf32.f32 "
        "{%0,%1,%2,%3},{%4,%5,%6,%7},{%8,%9},{%0,%1,%2,%3};"
        : "+f"(c[0]),"+f"(c[1]),"+f"(c[2]),"+f"(c[3])
        : "r"(a[0]),"r"(a[1]),"r"(a[2]),"r"(a[3]),"r"(b[0]),"r"(b[1]));
}

// ------------------ depthwise 3x3x3, SAME, x-vectorized (4 outputs/thread) --
__device__ __forceinline__ void dw_body_v4(const float* __restrict__ in,
                                           const float* __restrict__ w,
                                           float* __restrict__ out, int C)
{
    __shared__ float ws[27];
    int t = threadIdx.x;
    int c = blockIdx.y, b = blockIdx.z;
    if (t < 27) ws[t] = w[c * 27 + t];
    __syncthreads();
    int idx = blockIdx.x * 256 + t;          // over 24*24*6 = 3456
    if (idx >= 3456) return;
    int x4 = (idx % 6) * 4;
    int y  = (idx / 6) % 24;
    int z  = idx / 144;
    const float* ip = in + ((size_t)(b * C + c)) * NTOT;
    float acc0 = 0.f, acc1 = 0.f, acc2 = 0.f, acc3 = 0.f;
    #pragma unroll
    for (int dz = -1; dz <= 1; dz++) {
        int zz = z + dz; if (zz < 0 || zz >= 24) continue;
        #pragma unroll
        for (int dy = -1; dy <= 1; dy++) {
            int yy = y + dy; if (yy < 0 || yy >= 24) continue;
            const float* row = ip + (zz * 24 + yy) * 24;
            float4 mid = *(const float4*)(row + x4);
            float left  = (x4 > 0)      ? row[x4 - 1] : 0.f;
            float right = (x4 + 4 < 24) ? row[x4 + 4] : 0.f;
            const float* wr = ws + (dz + 1) * 9 + (dy + 1) * 3;
            float w0 = wr[0], w1 = wr[1], w2 = wr[2];
            acc0 += w0 * left  + w1 * mid.x + w2 * mid.y;
            acc1 += w0 * mid.x + w1 * mid.y + w2 * mid.z;
            acc2 += w0 * mid.y + w1 * mid.z + w2 * mid.w;
            acc3 += w0 * mid.z + w1 * mid.w + w2 * right;
        }
    }
    float4 o = make_float4(acc0, acc1, acc2, acc3);
    *(float4*)(out + ((size_t)(b * C + c)) * NTOT + (z * 24 + y) * 24 + x4) = o;
}

__global__ void k_dwconv1(const float* __restrict__ feat, const float* __restrict__ w)
{   dw_body_v4(feat, w, g_t1, CF); }

__global__ void k_dwconv2(const float* __restrict__ w)
{   dw_body_v4(g_attnout, w, g_dw2, INNER); }

// ------------------ pointwise qv GEMM (tf32 mma): [512,128]@[128,N] + head scatter
__global__ __launch_bounds__(256) void k_pw_qv(const float* __restrict__ A)
{
    __shared__ float As[64*36];   // [m][k] pitch 36
    __shared__ float Bs[32*136];  // [k][n] pitch 136
    int t = threadIdx.x, w = t >> 5, l = t & 31, g = l >> 2, q4 = l & 3;
    int bn = blockIdx.x * 128, bo = blockIdx.y * 64, b = blockIdx.z;
    int wm = (w >> 2) * 32, wn = (w & 3) * 32;
    float C[2][4][4] = {};
    const float* Xb = g_t1 + (size_t)b * CF * NTOT;
    for (int kc = 0; kc < 128; kc += 32) {
        __syncthreads();
        #pragma unroll
        for (int i = 0; i < 2; i++) {
            int idx = t + i * 256; int m = idx >> 3, k4 = idx & 7;
            float4 v = f2tf4(*(const float4*)&A[(bo + m)*128 + kc + k4*4]);
            *(float4*)&As[m*36 + k4*4] = v;
        }
        #pragma unroll
        for (int i = 0; i < 4; i++) {
            int idx = t + i * 256; int k = idx >> 5, n4 = idx & 31;
            float4 v = f2tf4(*(const float4*)&Xb[(size_t)(kc + k)*NTOT + bn + n4*4]);
            *(float4*)&Bs[k*136 + n4*4] = v;
        }
        __syncthreads();
        #pragma unroll
        for (int kk = 0; kk < 4; kk++) {
            uint32_t a[2][4], bb[4][2];
            #pragma unroll
            for (int mi = 0; mi < 2; mi++) {
                const float* ap = &As[(wm + mi*16 + g)*36 + kk*8 + q4];
                a[mi][0] = __float_as_uint(ap[0]);
                a[mi][1] = __float_as_uint(ap[8*36]);
                a[mi][2] = __float_as_uint(ap[4]);
                a[mi][3] = __float_as_uint(ap[8*36+4]);
            }
            #pragma unroll
            for (int ni = 0; ni < 4; ni++) {
                const float* bp = &Bs[(kk*8 + q4)*136 + wn + ni*8 + g];
                bb[ni][0] = __float_as_uint(bp[0]);
                bb[ni][1] = __float_as_uint(bp[4*136]);
            }
            #pragma unroll
            for (int mi = 0; mi < 2; mi++)
                #pragma unroll
                for (int ni = 0; ni < 4; ni++) mma8(C[mi][ni], a[mi], bb[ni]);
        }
    }
    #pragma unroll
    for (int mi = 0; mi < 2; mi++)
        #pragma unroll
        for (int ni = 0; ni < 4; ni++)
            #pragma unroll
            for (int cc = 0; cc < 4; cc++) {
                int o = bo + wm + mi*16 + g + (cc >> 1)*8;
                int n = bn + wn + ni*8 + 2*q4 + (cc & 1);
                float v = C[mi][ni][cc];
                if (o < 256)
                    g_q[((size_t)(b*4 + (o & 3))*NTOT + n)*64 + (o >> 2)] = v;
                else {
                    int c2 = o - 256;
                    g_fv[((size_t)(b*4 + (c2 & 3))*NTOT + n)*64 + (c2 >> 2)] = v;
                }
            }
}

// ------------------ map qv: [512,64] @ smap[b][64][512], 4 m per thread -----
__global__ void k_map_qv(const float* __restrict__ w, const float* __restrict__ smap)
{
    int gid = blockIdx.x * 256 + threadIdx.x;   // < 131072
    int m4 = gid & 127;          // m = m4*4 .. m4*4+3
    int o  = (gid >> 7) & 511;
    int b  = gid >> 16;
    const float* wp = w + o * 64;
    const float* sp = smap + (size_t)b * 64 * 512 + m4 * 4;
    float s0 = 0.f, s1 = 0.f, s2 = 0.f, s3 = 0.f;
    #pragma unroll 8
    for (int c = 0; c < 64; c++) {
        float wc = wp[c];
        float4 v = *(const float4*)(sp + (size_t)c * 512);
        s0 += wc * v.x; s1 += wc * v.y; s2 += wc * v.z; s3 += wc * v.w;
    }
    int m = m4 * 4;
    float* dst;
    int oc = o;
    if (o < 256) dst = g_mq; else { dst = g_mv; oc = o - 256; }
    size_t base = ((size_t)(b * 4 + (oc & 3)) * 512 + m) * 64 + (oc >> 2);
    dst[base]        = s0;
    dst[base + 64]   = s1;
    dst[base + 128]  = s2;
    dst[base + 192]  = s3;
}

// ------------------ attention pass 1 (tf32 mma flash block, no E store) ----
// n-tile 64; loop 8 chunks of 64 map tokens. 8 warps: wn=(w>>2)*32, wc=(w&3)*16
__global__ __launch_bounds__(256, 2) void k_attn1()
{
    __shared__ float mqs[64*68];  // Q-stage -> MQ chunk -> E tile -> O tile
    __shared__ float mvs[64*72];
    __shared__ float srs[64];
    int t = threadIdx.x, w = t >> 5, l = t & 31, g = l >> 2, q4 = l & 3;
    int bh = blockIdx.y, b = bh >> 2, h = bh & 3;
    int nb = blockIdx.x * 64;
    int wn = (w >> 2) * 32, wc = (w & 3) * 16;

    if (t < 64) srs[t] = 0.f;
    #pragma unroll
    for (int i = 0; i < 4; i++) {
        int idx = t + i * 256; int n = idx >> 4, d4 = idx & 15;
        float4 v = *(const float4*)&g_q[((size_t)bh*NTOT + nb + n)*64 + d4*4];
        *(float4*)&mqs[n*68 + d4*4] = v;
    }
    __syncthreads();
    uint32_t QF[8][2][4];
    #pragma unroll
    for (int kk = 0; kk < 8; kk++)
        #pragma unroll
        for (int mi = 0; mi < 2; mi++) {
            const float* ap = &mqs[(wn + mi*16 + g)*68 + kk*8 + q4];
            QF[kk][mi][0] = f2t(ap[0]);
            QF[kk][mi][1] = f2t(ap[8*68]);
            QF[kk][mi][2] = f2t(ap[4]);
            QF[kk][mi][3] = f2t(ap[8*68+4]);
        }
    float OF[2][2][4] = {};
    float rs[2][2] = {};

    for (int mc = 0; mc < 8; mc++) {
        __syncthreads();
        #pragma unroll
        for (int i = 0; i < 4; i++) {
            int idx = t + i * 256; int m = idx >> 4, d4 = idx & 15;
            float4 vq = f2tf4(*(const float4*)&g_mq[((size_t)bh*MTOT + mc*64 + m)*64 + d4*4]);
            float4 vv = f2tf4(*(const float4*)&g_mv[((size_t)bh*MTOT + mc*64 + m)*64 + d4*4]);
            *(float4*)&mqs[m*68 + d4*4] = vq;
            *(float4*)&mvs[m*72 + d4*4] = vv;
        }
        __syncthreads();
        // S = Q @ MQ^T
        float C[2][2][4] = {};
        #pragma unroll
        for (int kk = 0; kk < 8; kk++) {
            uint32_t bb[2][2];
            #pragma unroll
            for (int ni = 0; ni < 2; ni++) {
                const float* bp = &mqs[(wc + ni*8 + g)*68 + kk*8 + q4];
                bb[ni][0] = __float_as_uint(bp[0]);
                bb[ni][1] = __float_as_uint(bp[4]);
            }
            #pragma unroll
            for (int mi = 0; mi < 2; mi++)
                #pragma unroll
                for (int ni = 0; ni < 2; ni++) mma8(C[mi][ni], QF[kk][mi], bb[ni]);
        }
        __syncthreads();   // all warps done reading mqs(MQ) before E overwrites it
        // exp, rowsum, stage E (tf32 bits) into mqs as [n][m]
        #pragma unroll
        for (int mi = 0; mi < 2; mi++)
            #pragma unroll
            for (int ni = 0; ni < 2; ni++)
                #pragma unroll
                for (int cc = 0; cc < 4; cc++) {
                    float e = __expf(C[mi][ni][cc] * SCALE);
                    rs[mi][cc >> 1] += e;
                    mqs[(wn + mi*16 + (cc>>1)*8 + g)*68 + wc + ni*8 + 2*q4 + (cc&1)] = f2tf(e);
                }
        __syncthreads();
        // O += E @ MV
        #pragma unroll
        for (int kk = 0; kk < 8; kk++) {
            uint32_t a[2][4], bb[2][2];
            #pragma unroll
            for (int mi = 0; mi < 2; mi++) {
                const float* ap = &mqs[(wn + mi*16 + g)*68 + kk*8 + q4];
                a[mi][0] = __float_as_uint(ap[0]);
                a[mi][1] = __float_as_uint(ap[8*68]);
                a[mi][2] = __float_as_uint(ap[4]);
                a[mi][3] = __float_as_uint(ap[8*68+4]);
            }
            #pragma unroll
            for (int ni = 0; ni < 2; ni++) {
                const float* bp = &mvs[(kk*8 + q4)*72 + wc + ni*8 + g];
                bb[ni][0] = __float_as_uint(bp[0]);
                bb[ni][1] = __float_as_uint(bp[4*72]);
            }
            #pragma unroll
            for (int mi = 0; mi < 2; mi++)
                #pragma unroll
                for (int ni = 0; ni < 2; ni++) mma8(OF[mi][ni], a[mi], bb[ni]);
        }
    }
    // rowsum reduce
    #pragma unroll
    for (int mi = 0; mi < 2; mi++)
        #pragma unroll
        for (int gh = 0; gh < 2; gh++) {
            float v = rs[mi][gh];
            v += __shfl_xor_sync(0xFFFFFFFFu, v, 1);
            v += __shfl_xor_sync(0xFFFFFFFFu, v, 2);
            if (q4 == 0) atomicAdd(&srs[wn + mi*16 + gh*8 + g], v);
        }
    __syncthreads();
    // normalize + stage O [n][d] into mqs
    #pragma unroll
    for (int mi = 0; mi < 2; mi++) {
        float inv0 = 1.f / srs[wn + mi*16 + g];
        float inv1 = 1.f / srs[wn + mi*16 + 8 + g];
        #pragma unroll
        for (int ni = 0; ni < 2; ni++) {
            int col = wc + ni*8 + 2*q4;
            mqs[(wn + mi*16 + g)*68 + col]       = OF[mi][ni][0] * inv0;
            mqs[(wn + mi*16 + g)*68 + col + 1]   = OF[mi][ni][1] * inv0;
            mqs[(wn + mi*16 + 8 + g)*68 + col]   = OF[mi][ni][2] * inv1;
            mqs[(wn + mi*16 + 8 + g)*68 + col+1] = OF[mi][ni][3] * inv1;
        }
    }
    __syncthreads();
    float* ao = g_attnout + (size_t)b * INNER * NTOT + nb;
    #pragma unroll
    for (int i = 0; i < 4; i++) {
        int idx = t + i * 256; int d = idx >> 4, n4 = idx & 15;
        float4 v;
        v.x = mqs[(n4*4+0)*68 + d];
        v.y = mqs[(n4*4+1)*68 + d];
        v.z = mqs[(n4*4+2)*68 + d];
        v.w = mqs[(n4*4+3)*68 + d];
        *(float4*)&ao[(size_t)(4*d + h) * NTOT + n4*4] = v;
    }
}

// ------------------ zero accumulators ------------------
__global__ void k_zero_a()
{
    int i = blockIdx.x * 256 + threadIdx.x;
    if (i < BSZ * NHEAD * MTOT * DHEAD) g_monum[i] = 0.f;
}
__global__ void k_zero_b()
{
    int i = blockIdx.x * 256 + threadIdx.x;
    if (i < BSZ * NHEAD * MTOT) g_colsum[i] = 0.f;
}

// ------------------ attention pass 2: recompute E, split-K over n ----------
// monum[m][d] += sum_n exp(S[m][n])*fv[n][d]; colsum[m] += sum_n exp(S[m][n])
// block: m-tile 128 x all 64 d; n in chunks of 32. 8 warps:
//   wm=(w>>1)*32 (m rows, both MMAs), wsn=(w&1)*16 (S-MMA n cols), wd=(w&1)*32 (out d cols)
__global__ __launch_bounds__(256, 2) void k_attn2()
{
    __shared__ float Qs[32*68];   // [n][d]
    __shared__ float Vs[32*72];   // [n][d]
    __shared__ float Es[128*36];  // [m][n-chunk]
    __shared__ float scs[128];
    int t = threadIdx.x, w = t >> 5, l = t & 31, g = l >> 2, q4 = l & 3;
    int bh = blockIdx.z; int mtile = blockIdx.y * 128; int nb = blockIdx.x * KLEN;
    int wm = (w >> 1) * 32, wsn = (w & 1) * 16, wd = (w & 1) * 32;
    const float* Qb = g_q  + (size_t)bh * NTOT * 64;
    const float* Vb = g_fv + (size_t)bh * NTOT * 64;
    if (t < 128) scs[t] = 0.f;

    // MQ A-fragments for whole m-tile, held in registers (one-time gmem load)
    uint32_t AF[8][2][4];
    const float* MQb = g_mq + ((size_t)bh * MTOT + mtile) * 64;
    #pragma unroll
    for (int kk = 0; kk < 8; kk++)
        #pragma unroll
        for (int mi = 0; mi < 2; mi++) {
            const float* p = MQb + (wm + mi*16 + g)*64 + kk*8 + q4;
            AF[kk][mi][0] = f2t(p[0]);
            AF[kk][mi][1] = f2t(p[8*64]);
            AF[kk][mi][2] = f2t(p[4]);
            AF[kk][mi][3] = f2t(p[8*64+4]);
        }
    float C[2][4][4] = {};
    float cs[2][2] = {};

    for (int nc = nb; nc < nb + KLEN; nc += 32) {
        __syncthreads();
        #pragma unroll
        for (int i = 0; i < 2; i++) {
            int idx = t + i * 256; int n = idx >> 4, d4 = idx & 15;
            float4 vq = f2tf4(*(const float4*)&Qb[(size_t)(nc + n)*64 + d4*4]);
            float4 vv = f2tf4(*(const float4*)&Vb[(size_t)(nc + n)*64 + d4*4]);
            *(float4*)&Qs[n*68 + d4*4] = vq;
            *(float4*)&Vs[n*72 + d4*4] = vv;
        }
        __syncthreads();
        // S = MQ @ Q^T  -> [128m][32n]
        float Cs[2][2][4] = {};
        #pragma unroll
        for (int kk = 0; kk < 8; kk++) {
            uint32_t bb[2][2];
            #pragma unroll
            for (int ni = 0; ni < 2; ni++) {
                const float* bp = &Qs[(wsn + ni*8 + g)*68 + kk*8 + q4];
                bb[ni][0] = __float_as_uint(bp[0]);
                bb[ni][1] = __float_as_uint(bp[4]);
            }
            #pragma unroll
            for (int mi = 0; mi < 2; mi++)
                #pragma unroll
                for (int ni = 0; ni < 2; ni++) mma8(Cs[mi][ni], AF[kk][mi], bb[ni]);
        }
        // exp, colsum, stage E (tf32 bits) into Es [m][n]
        #pragma unroll
        for (int mi = 0; mi < 2; mi++)
            #pragma unroll
            for (int ni = 0; ni < 2; ni++)
                #pragma unroll
                for (int cc = 0; cc < 4; cc++) {
                    float e = __expf(Cs[mi][ni][cc] * SCALE);
                    cs[mi][cc >> 1] += e;
                    Es[(wm + mi*16 + (cc>>1)*8 + g)*36 + wsn + ni*8 + 2*q4 + (cc&1)] = f2tf(e);
                }
        __syncthreads();
        // monum += E @ V
        #pragma unroll
        for (int kk = 0; kk < 4; kk++) {
            uint32_t a[2][4], bb[4][2];
            #pragma unroll
            for (int mi = 0; mi < 2; mi++) {
                const float* ap = &Es[(wm + mi*16 + g)*36 + kk*8 + q4];
                a[mi][0] = __float_as_uint(ap[0]);
                a[mi][1] = __float_as_uint(ap[8*36]);
                a[mi][2] = __float_as_uint(ap[4]);
                a[mi][3] = __float_as_uint(ap[8*36+4]);
            }
            #pragma unroll
            for (int ni = 0; ni < 4; ni++) {
                const float* bp = &Vs[(kk*8 + q4)*72 + wd + ni*8 + g];
                bb[ni][0] = __float_as_uint(bp[0]);
                bb[ni][1] = __float_as_uint(bp[4*72]);
            }
            #pragma unroll
            for (int mi = 0; mi < 2; mi++)
                #pragma unroll
                for (int ni = 0; ni < 4; ni++) mma8(C[mi][ni], a[mi], bb[ni]);
        }
    }
    // colsum reduce: for (mi,gh), m = wm + mi*16 + gh*8 + g; sum over q4 lanes
    #pragma unroll
    for (int mi = 0; mi < 2; mi++)
        #pragma unroll
        for (int gh = 0; gh < 2; gh++) {
            float v = cs[mi][gh];
            v += __shfl_xor_sync(0xFFFFFFFFu, v, 1);
            v += __shfl_xor_sync(0xFFFFFFFFu, v, 2);
            if (q4 == 0) atomicAdd(&scs[wm + mi*16 + gh*8 + g], v);
        }
    __syncthreads();
    if (t < 128) atomicAdd(&g_colsum[(size_t)bh*MTOT + mtile + t], scs[t]);
    #pragma unroll
    for (int mi = 0; mi < 2; mi++)
        #pragma unroll
        for (int ni = 0; ni < 4; ni++)
            #pragma unroll
            for (int cc = 0; cc < 4; cc++) {
                int m = mtile + wm + mi*16 + g + (cc >> 1)*8;
                int d = wd + ni*8 + 2*q4 + (cc & 1);
                atomicAdd(&g_monum[((size_t)bh*MTOT + m)*64 + d], C[mi][ni][cc]);
            }
}

// ------------------ finalize map_out ------------------
__global__ void k_mapout(const float* __restrict__ w, float* __restrict__ outp)
{
    int gid = blockIdx.x * 256 + threadIdx.x;
    int m = gid & 511;
    int o = (gid >> 9) & 63;
    int b = gid >> 15;
    float inv[4];
    #pragma unroll
    for (int hh = 0; hh < 4; hh++)
        inv[hh] = 1.f / g_colsum[(size_t)(b * 4 + hh) * 512 + m];
    float s = 0.f;
    #pragma unroll 4
    for (int c = 0; c < 256; c++) {
        int d = c >> 2, hh = c & 3;
        s += w[o * 256 + c] * g_monum[((size_t)(b * 4 + hh) * 512 + m) * 64 + d] * inv[hh];
    }
    outp[(size_t)FEAT_OUT_ELEMS + ((size_t)(b * 64 + o)) * 512 + m] = s;
}

// ------------------ pointwise out GEMM (tf32 mma): [128,256]@[256,N] ------
__global__ __launch_bounds__(256) void k_pw_out(const float* __restrict__ A,
                                                float* __restrict__ outp)
{
    __shared__ float As[64*36];
    __shared__ float Bs[32*136];
    int t = threadIdx.x, w = t >> 5, l = t & 31, g = l >> 2, q4 = l & 3;
    int bn = blockIdx.x * 128, bo = blockIdx.y * 64, b = blockIdx.z;
    int wm = (w >> 2) * 32, wn = (w & 3) * 32;
    float C[2][4][4] = {};
    const float* Xb = g_dw2 + (size_t)b * INNER * NTOT;
    for (int kc = 0; kc < 256; kc += 32) {
        __syncthreads();
        #pragma unroll
        for (int i = 0; i < 2; i++) {
            int idx = t + i * 256; int m = idx >> 3, k4 = idx & 7;
            float4 v = f2tf4(*(const float4*)&A[(bo + m)*256 + kc + k4*4]);
            *(float4*)&As[m*36 + k4*4] = v;
        }
        #pragma unroll
        for (int i = 0; i < 4; i++) {
            int idx = t + i * 256; int k = idx >> 5, n4 = idx & 31;
            float4 v = f2tf4(*(const float4*)&Xb[(size_t)(kc + k)*NTOT + bn + n4*4]);
            *(float4*)&Bs[k*136 + n4*4] = v;
        }
        __syncthreads();
        #pragma unroll
        for (int kk = 0; kk < 4; kk++) {
            uint32_t a[2][4], bb[4][2];
            #pragma unroll
            for (int mi = 0; mi < 2; mi++) {
                const float* ap = &As[(wm + mi*16 + g)*36 + kk*8 + q4];
                a[mi][0] = __float_as_uint(ap[0]);
                a[mi][1] = __float_as_uint(ap[8*36]);
                a[mi][2] = __float_as_uint(ap[4]);
                a[mi][3] = __float_as_uint(ap[8*36+4]);
            }
            #pragma unroll
            for (int ni = 0; ni < 4; ni++) {
                const float* bp = &Bs[(kk*8 + q4)*136 + wn + ni*8 + g];
                bb[ni][0] = __float_as_uint(bp[0]);
                bb[ni][1] = __float_as_uint(bp[4*136]);
            }
            #pragma unroll
            for (int mi = 0; mi < 2; mi++)
                #pragma unroll
                for (int ni = 0; ni < 4; ni++) mma8(C[mi][ni], a[mi], bb[ni]);
        }
    }
    #pragma unroll
    for (int mi = 0; mi < 2; mi++)
        #pragma unroll
        for (int ni = 0; ni < 4; ni++)
            #pragma unroll
            for (int cc = 0; cc < 4; cc++) {
                int o = bo + wm + mi*16 + g + (cc >> 1)*8;
                int n = bn + wn + ni*8 + 2*q4 + (cc & 1);
                outp[((size_t)(b * 128 + o)) * NTOT + n] = C[mi][ni][cc];
            }
}

// ------------------ launch ------------------
extern "C" void kernel_launch(void* const* d_in, const int* in_sizes, int n_in,
                              void* d_out, int out_size)
{
    const float* feat    = (const float*)d_in[0];
    const float* smap    = (const float*)d_in[1];
    const float* fqv_dw  = (const float*)d_in[2];
    const float* fqv_pw  = (const float*)d_in[3];
    const float* fout_dw = (const float*)d_in[4];
    const float* fout_pw = (const float*)d_in[5];
    const float* mqv_w   = (const float*)d_in[6];
    const float* mout_w  = (const float*)d_in[7];
    float* outp = (float*)d_out;

    k_zero_a <<<1024, 256>>>();
    k_zero_b <<<16, 256>>>();
    k_dwconv1<<<dim3(14, 128, 2), 256>>>(feat, fqv_dw);
    k_map_qv <<<512, 256>>>(mqv_w, smap);
    k_pw_qv  <<<dim3(108, 8, 2), 256>>>(fqv_pw);
    k_attn1  <<<dim3(216, 8), 256>>>();
    k_attn2  <<<dim3(KSPLIT, 4, 8), 256>>>();
    k_mapout <<<256, 256>>>(mout_w, outp);
    k_dwconv2<<<dim3(14, 256, 2), 256>>>(fout_dw);
    k_pw_out <<<dim3(108, 2, 2), 256>>>(fout_pw, outp);
}

// round 8
// speedup vs baseline: 3.0452x; 1.1176x over previous
#include <cuda_runtime.h>
#include <math.h>
#include <stdint.h>

#define BSZ   2
#define CF    128
#define NTOT  13824      // 24^3
#define MTOT  512        // 8^3
#define NHEAD 4
#define DHEAD 64
#define INNER 256
#define SCALE 0.125f     // 64^-0.5
#define FEAT_OUT_ELEMS 3538944   // 2*128*13824
#define KSPLIT 9
#define KLEN   1536      // 13824/9

// ------------------ scratch (device globals; no allocs) ------------------
__device__ __align__(16) float g_t1   [BSZ*CF*NTOT];            // dwconv1 out
__device__ __align__(16) float g_q    [BSZ*NHEAD*NTOT*DHEAD];   // feat_q  [bh][n][d] (tf32 bits)
__device__ __align__(16) float g_fv   [BSZ*NHEAD*NTOT*DHEAD];   // feat_v  [bh][n][d] (tf32 bits)
__device__ __align__(16) float g_mq   [BSZ*NHEAD*MTOT*DHEAD];   // map_q   [bh][m][d] (tf32 bits)
__device__ __align__(16) float g_mv   [BSZ*NHEAD*MTOT*DHEAD];   // map_v   [bh][m][d] (tf32 bits)
__device__ __align__(16) float g_attnout[BSZ*INNER*NTOT];       // feat attn out [b][c][n]
__device__ __align__(16) float g_dw2  [BSZ*INNER*NTOT];         // dwconv2 out
__device__ __align__(16) float g_monum[BSZ*NHEAD*MTOT*DHEAD];   // map_out numerator
__device__ __align__(16) float g_colsum[BSZ*NHEAD*MTOT];

// ------------------ tf32 mma helpers ------------------
__device__ __forceinline__ uint32_t f2t(float x){
    uint32_t r; asm("cvt.rna.tf32.f32 %0,%1;":"=r"(r):"f"(x)); return r;
}
__device__ __forceinline__ float f2tf(float x){ return __uint_as_float(f2t(x)); }
__device__ __forceinline__ float4 f2tf4(float4 v){
    v.x = f2tf(v.x); v.y = f2tf(v.y); v.z = f2tf(v.z); v.w = f2tf(v.w); return v;
}

__device__ __forceinline__ void mma8(float* c, const uint32_t* a, const uint32_t* b){
    asm volatile("mma.sync.aligned.m16n8k8.row.col.f32.tf32.tf32.f32 "
        "{%0,%1,%2,%3},{%4,%5,%6,%7},{%8,%9},{%0,%1,%2,%3};"
        : "+f"(c[0]),"+f"(c[1]),"+f"(c[2]),"+f"(c[3])
        : "r"(a[0]),"r"(a[1]),"r"(a[2]),"r"(a[3]),"r"(b[0]),"r"(b[1]));
}

// ------------------ cp.async helpers ------------------
__device__ __forceinline__ void cpa16(void* smem, const void* g){
    uint32_t s = (uint32_t)__cvta_generic_to_shared(smem);
    asm volatile("cp.async.ca.shared.global [%0], [%1], 16;" :: "r"(s), "l"(g));
}
#define CPA_COMMIT() asm volatile("cp.async.commit_group;")
#define CPA_WAIT0()  asm volatile("cp.async.wait_group 0;" ::: "memory")

// ------------------ depthwise 3x3x3, SAME, x-vectorized (4 outputs/thread) --
__device__ __forceinline__ void dw_body_v4(const float* __restrict__ in,
                                           const float* __restrict__ w,
                                           float* __restrict__ out, int C)
{
    __shared__ float ws[27];
    int t = threadIdx.x;
    int c = blockIdx.y, b = blockIdx.z;
    if (t < 27) ws[t] = w[c * 27 + t];
    __syncthreads();
    int idx = blockIdx.x * 256 + t;          // over 24*24*6 = 3456
    if (idx >= 3456) return;
    int x4 = (idx % 6) * 4;
    int y  = (idx / 6) % 24;
    int z  = idx / 144;
    const float* ip = in + ((size_t)(b * C + c)) * NTOT;
    float acc0 = 0.f, acc1 = 0.f, acc2 = 0.f, acc3 = 0.f;
    #pragma unroll
    for (int dz = -1; dz <= 1; dz++) {
        int zz = z + dz; if (zz < 0 || zz >= 24) continue;
        #pragma unroll
        for (int dy = -1; dy <= 1; dy++) {
            int yy = y + dy; if (yy < 0 || yy >= 24) continue;
            const float* row = ip + (zz * 24 + yy) * 24;
            float4 mid = *(const float4*)(row + x4);
            float left  = (x4 > 0)      ? row[x4 - 1] : 0.f;
            float right = (x4 + 4 < 24) ? row[x4 + 4] : 0.f;
            const float* wr = ws + (dz + 1) * 9 + (dy + 1) * 3;
            float w0 = wr[0], w1 = wr[1], w2 = wr[2];
            acc0 += w0 * left  + w1 * mid.x + w2 * mid.y;
            acc1 += w0 * mid.x + w1 * mid.y + w2 * mid.z;
            acc2 += w0 * mid.y + w1 * mid.z + w2 * mid.w;
            acc3 += w0 * mid.z + w1 * mid.w + w2 * right;
        }
    }
    float4 o = make_float4(acc0, acc1, acc2, acc3);
    *(float4*)(out + ((size_t)(b * C + c)) * NTOT + (z * 24 + y) * 24 + x4) = o;
}

__global__ void k_dwconv1(const float* __restrict__ feat, const float* __restrict__ w)
{   dw_body_v4(feat, w, g_t1, CF); }

__global__ void k_dwconv2(const float* __restrict__ w)
{   dw_body_v4(g_attnout, w, g_dw2, INNER); }

// ------------------ pointwise qv GEMM (tf32 mma): [512,128]@[128,N] + head scatter
__global__ __launch_bounds__(256) void k_pw_qv(const float* __restrict__ A)
{
    __shared__ float As[64*36];   // [m][k] pitch 36
    __shared__ float Bs[32*136];  // [k][n] pitch 136
    int t = threadIdx.x, w = t >> 5, l = t & 31, g = l >> 2, q4 = l & 3;
    int bn = blockIdx.x * 128, bo = blockIdx.y * 64, b = blockIdx.z;
    int wm = (w >> 2) * 32, wn = (w & 3) * 32;
    float C[2][4][4] = {};
    const float* Xb = g_t1 + (size_t)b * CF * NTOT;
    for (int kc = 0; kc < 128; kc += 32) {
        __syncthreads();
        #pragma unroll
        for (int i = 0; i < 2; i++) {
            int idx = t + i * 256; int m = idx >> 3, k4 = idx & 7;
            float4 v = f2tf4(*(const float4*)&A[(bo + m)*128 + kc + k4*4]);
            *(float4*)&As[m*36 + k4*4] = v;
        }
        #pragma unroll
        for (int i = 0; i < 4; i++) {
            int idx = t + i * 256; int k = idx >> 5, n4 = idx & 31;
            float4 v = f2tf4(*(const float4*)&Xb[(size_t)(kc + k)*NTOT + bn + n4*4]);
            *(float4*)&Bs[k*136 + n4*4] = v;
        }
        __syncthreads();
        #pragma unroll
        for (int kk = 0; kk < 4; kk++) {
            uint32_t a[2][4], bb[4][2];
            #pragma unroll
            for (int mi = 0; mi < 2; mi++) {
                const float* ap = &As[(wm + mi*16 + g)*36 + kk*8 + q4];
                a[mi][0] = __float_as_uint(ap[0]);
                a[mi][1] = __float_as_uint(ap[8*36]);
                a[mi][2] = __float_as_uint(ap[4]);
                a[mi][3] = __float_as_uint(ap[8*36+4]);
            }
            #pragma unroll
            for (int ni = 0; ni < 4; ni++) {
                const float* bp = &Bs[(kk*8 + q4)*136 + wn + ni*8 + g];
                bb[ni][0] = __float_as_uint(bp[0]);
                bb[ni][1] = __float_as_uint(bp[4*136]);
            }
            #pragma unroll
            for (int mi = 0; mi < 2; mi++)
                #pragma unroll
                for (int ni = 0; ni < 4; ni++) mma8(C[mi][ni], a[mi], bb[ni]);
        }
    }
    #pragma unroll
    for (int mi = 0; mi < 2; mi++)
        #pragma unroll
        for (int ni = 0; ni < 4; ni++)
            #pragma unroll
            for (int cc = 0; cc < 4; cc++) {
                int o = bo + wm + mi*16 + g + (cc >> 1)*8;
                int n = bn + wn + ni*8 + 2*q4 + (cc & 1);
                float v = f2tf(C[mi][ni][cc]);   // pre-round for attention consumers
                if (o < 256)
                    g_q[((size_t)(b*4 + (o & 3))*NTOT + n)*64 + (o >> 2)] = v;
                else {
                    int c2 = o - 256;
                    g_fv[((size_t)(b*4 + (c2 & 3))*NTOT + n)*64 + (c2 >> 2)] = v;
                }
            }
}

// ------------------ map qv: smem-tiled [512,64]@[64,512] -------------------
// block: o-tile 32 x full m=512 (chunks of 128); grid (16, 2)
__global__ __launch_bounds__(256) void k_map_qv(const float* __restrict__ w,
                                                const float* __restrict__ smap)
{
    __shared__ float Ws[32*68];   // [o][c]
    __shared__ float Bs[64*132];  // [c][m-chunk]
    int t = threadIdx.x;
    int bo = blockIdx.x * 32, b = blockIdx.y;
    int ol = (t >> 5) * 4;        // local o base (4 per thread)
    int ml = (t & 31) * 4;        // local m base (4 per thread)
    // stage W tile once
    #pragma unroll
    for (int i = 0; i < 2; i++) {
        int idx = t + i * 256; int o = idx >> 4, c4 = idx & 15;
        *(float4*)&Ws[o*68 + c4*4] = *(const float4*)&w[(bo + o)*64 + c4*4];
    }
    for (int mc = 0; mc < 512; mc += 128) {
        __syncthreads();
        #pragma unroll
        for (int i = 0; i < 8; i++) {
            int idx = t + i * 256; int c = idx >> 5, m4 = idx & 31;
            *(float4*)&Bs[c*132 + m4*4] =
                *(const float4*)&smap[((size_t)(b*64 + c))*512 + mc + m4*4];
        }
        __syncthreads();
        float acc[4][4] = {};
        #pragma unroll 8
        for (int c = 0; c < 64; c++) {
            float4 bv = *(const float4*)&Bs[c*132 + ml];
            #pragma unroll
            for (int oi = 0; oi < 4; oi++) {
                float wv = Ws[(ol + oi)*68 + c];
                acc[oi][0] += wv * bv.x; acc[oi][1] += wv * bv.y;
                acc[oi][2] += wv * bv.z; acc[oi][3] += wv * bv.w;
            }
        }
        #pragma unroll
        for (int oi = 0; oi < 4; oi++) {
            int oo = bo + ol + oi;
            float* dst; int oc;
            if (oo < 256) { dst = g_mq; oc = oo; } else { dst = g_mv; oc = oo - 256; }
            size_t base = ((size_t)(b*4 + (oc & 3))*512 + mc + ml)*64 + (oc >> 2);
            dst[base]       = f2tf(acc[oi][0]);
            dst[base + 64]  = f2tf(acc[oi][1]);
            dst[base + 128] = f2tf(acc[oi][2]);
            dst[base + 192] = f2tf(acc[oi][3]);
        }
    }
}

// ------------------ attention pass 1: cp.async pipelined flash block -------
// n-tile 64; 16 chunks of 32 map tokens, double-buffered MQ/MV.
// 8 warps: wn=(w>>2)*32 (n rows), wcs=(w&3)*8 (S m-cols), wd=(w&3)*16 (O d-cols)
__global__ __launch_bounds__(256, 2) void k_attn1()
{
    __shared__ float MQd[2*32*68];   // chunk buffers; also Q-stage / O-stage scratch
    __shared__ float MVd[2*32*68];
    __shared__ float Es[64*36];
    __shared__ float srs[64];
    int t = threadIdx.x, w = t >> 5, l = t & 31, g = l >> 2, q4 = l & 3;
    int bh = blockIdx.y, b = bh >> 2, h = bh & 3;
    int nb = blockIdx.x * 64;
    int wn = (w >> 2) * 32, wcs = (w & 3) * 8, wd = (w & 3) * 16;

    if (t < 64) srs[t] = 0.f;
    // stage Q [64][68] into MQd scratch
    const float* Qb = g_q + ((size_t)bh*NTOT + nb) * 64;
    #pragma unroll
    for (int i = 0; i < 4; i++) {
        int idx = t + i * 256; int n = idx >> 4, d4 = idx & 15;
        *(float4*)&MQd[n*68 + d4*4] = *(const float4*)&Qb[(size_t)n*64 + d4*4];
    }
    __syncthreads();
    uint32_t QF[8][2][4];
    #pragma unroll
    for (int kk = 0; kk < 8; kk++)
        #pragma unroll
        for (int mi = 0; mi < 2; mi++) {
            const float* ap = &MQd[(wn + mi*16 + g)*68 + kk*8 + q4];
            QF[kk][mi][0] = f2t(ap[0]);
            QF[kk][mi][1] = f2t(ap[8*68]);
            QF[kk][mi][2] = f2t(ap[4]);
            QF[kk][mi][3] = f2t(ap[8*68+4]);
        }
    float OF[2][2][4] = {};
    float rs[2][2] = {};
    __syncthreads();   // QF built before chunk0 overwrites MQd

    const float* MQg = g_mq + (size_t)bh * MTOT * 64;
    const float* MVg = g_mv + (size_t)bh * MTOT * 64;
    // prefetch chunk 0 -> buf 0
    #pragma unroll
    for (int i = 0; i < 2; i++) {
        int idx = t + i * 256; int m = idx >> 4, d4 = idx & 15;
        cpa16(&MQd[m*68 + d4*4], MQg + (size_t)m*64 + d4*4);
        cpa16(&MVd[m*68 + d4*4], MVg + (size_t)m*64 + d4*4);
    }
    CPA_COMMIT(); CPA_WAIT0();
    __syncthreads();

    for (int mc = 0; mc < 16; mc++) {
        int buf = (mc & 1) * 2176;
        if (mc < 15) {
            int nxt = ((mc + 1) & 1) * 2176;
            size_t goff = (size_t)(mc + 1) * 32 * 64;
            #pragma unroll
            for (int i = 0; i < 2; i++) {
                int idx = t + i * 256; int m = idx >> 4, d4 = idx & 15;
                cpa16(&MQd[nxt + m*68 + d4*4], MQg + goff + (size_t)m*64 + d4*4);
                cpa16(&MVd[nxt + m*68 + d4*4], MVg + goff + (size_t)m*64 + d4*4);
            }
            CPA_COMMIT();
        }
        // S = Q @ MQ^T  [64n][32m]
        float Cs[2][4] = {};
        #pragma unroll
        for (int kk = 0; kk < 8; kk++) {
            const float* bp = &MQd[buf + (wcs + g)*68 + kk*8 + q4];
            uint32_t bb[2] = { __float_as_uint(bp[0]), __float_as_uint(bp[4]) };
            #pragma unroll
            for (int mi = 0; mi < 2; mi++) mma8(Cs[mi], QF[kk][mi], bb);
        }
        // exp, rowsum, stage E (tf32 bits) into Es [n][m]
        #pragma unroll
        for (int mi = 0; mi < 2; mi++)
            #pragma unroll
            for (int cc = 0; cc < 4; cc++) {
                float e = __expf(Cs[mi][cc] * SCALE);
                rs[mi][cc >> 1] += e;
                Es[(wn + mi*16 + (cc>>1)*8 + g)*36 + wcs + 2*q4 + (cc&1)] = f2tf(e);
            }
        __syncthreads();
        // O += E @ MV  [64n][64d], k=32
        #pragma unroll
        for (int kk = 0; kk < 4; kk++) {
            uint32_t a[2][4], bb[2][2];
            #pragma unroll
            for (int mi = 0; mi < 2; mi++) {
                const float* ap = &Es[(wn + mi*16 + g)*36 + kk*8 + q4];
                a[mi][0] = __float_as_uint(ap[0]);
                a[mi][1] = __float_as_uint(ap[8*36]);
                a[mi][2] = __float_as_uint(ap[4]);
                a[mi][3] = __float_as_uint(ap[8*36+4]);
            }
            #pragma unroll
            for (int ni = 0; ni < 2; ni++) {
                const float* bp = &MVd[buf + (kk*8 + q4)*68 + wd + ni*8 + g];
                bb[ni][0] = __float_as_uint(bp[0]);
                bb[ni][1] = __float_as_uint(bp[4*68]);
            }
            #pragma unroll
            for (int mi = 0; mi < 2; mi++)
                #pragma unroll
                for (int ni = 0; ni < 2; ni++) mma8(OF[mi][ni], a[mi], bb[ni]);
        }
        CPA_WAIT0();
        __syncthreads();
    }
    // rowsum reduce
    #pragma unroll
    for (int mi = 0; mi < 2; mi++)
        #pragma unroll
        for (int gh = 0; gh < 2; gh++) {
            float v = rs[mi][gh];
            v += __shfl_xor_sync(0xFFFFFFFFu, v, 1);
            v += __shfl_xor_sync(0xFFFFFFFFu, v, 2);
            if (q4 == 0) atomicAdd(&srs[wn + mi*16 + gh*8 + g], v);
        }
    __syncthreads();
    // normalize + stage O [n][d] into MQd scratch
    #pragma unroll
    for (int mi = 0; mi < 2; mi++) {
        float inv0 = 1.f / srs[wn + mi*16 + g];
        float inv1 = 1.f / srs[wn + mi*16 + 8 + g];
        #pragma unroll
        for (int ni = 0; ni < 2; ni++) {
            int col = wd + ni*8 + 2*q4;
            MQd[(wn + mi*16 + g)*68 + col]       = OF[mi][ni][0] * inv0;
            MQd[(wn + mi*16 + g)*68 + col + 1]   = OF[mi][ni][1] * inv0;
            MQd[(wn + mi*16 + 8 + g)*68 + col]   = OF[mi][ni][2] * inv1;
            MQd[(wn + mi*16 + 8 + g)*68 + col+1] = OF[mi][ni][3] * inv1;
        }
    }
    __syncthreads();
    float* ao = g_attnout + (size_t)b * INNER * NTOT + nb;
    #pragma unroll
    for (int i = 0; i < 4; i++) {
        int idx = t + i * 256; int d = idx >> 4, n4 = idx & 15;
        float4 v;
        v.x = MQd[(n4*4+0)*68 + d];
        v.y = MQd[(n4*4+1)*68 + d];
        v.z = MQd[(n4*4+2)*68 + d];
        v.w = MQd[(n4*4+3)*68 + d];
        *(float4*)&ao[(size_t)(4*d + h) * NTOT + n4*4] = v;
    }
}

// ------------------ zero accumulators ------------------
__global__ void k_zero_a()
{
    int i = blockIdx.x * 256 + threadIdx.x;
    if (i < BSZ * NHEAD * MTOT * DHEAD) g_monum[i] = 0.f;
}
__global__ void k_zero_b()
{
    int i = blockIdx.x * 256 + threadIdx.x;
    if (i < BSZ * NHEAD * MTOT) g_colsum[i] = 0.f;
}

// ------------------ attention pass 2: recompute E, split-K over n ----------
__global__ __launch_bounds__(256, 2) void k_attn2()
{
    __shared__ float Qs[32*68];   // [n][d]
    __shared__ float Vs[32*72];   // [n][d]
    __shared__ float Es[128*36];  // [m][n-chunk]
    __shared__ float scs[128];
    int t = threadIdx.x, w = t >> 5, l = t & 31, g = l >> 2, q4 = l & 3;
    int bh = blockIdx.z; int mtile = blockIdx.y * 128; int nb = blockIdx.x * KLEN;
    int wm = (w >> 1) * 32, wsn = (w & 1) * 16, wd = (w & 1) * 32;
    const float* Qb = g_q  + (size_t)bh * NTOT * 64;
    const float* Vb = g_fv + (size_t)bh * NTOT * 64;
    if (t < 128) scs[t] = 0.f;

    uint32_t AF[8][2][4];
    const float* MQb = g_mq + ((size_t)bh * MTOT + mtile) * 64;
    #pragma unroll
    for (int kk = 0; kk < 8; kk++)
        #pragma unroll
        for (int mi = 0; mi < 2; mi++) {
            const float* p = MQb + (wm + mi*16 + g)*64 + kk*8 + q4;
            AF[kk][mi][0] = f2t(p[0]);
            AF[kk][mi][1] = f2t(p[8*64]);
            AF[kk][mi][2] = f2t(p[4]);
            AF[kk][mi][3] = f2t(p[8*64+4]);
        }
    float C[2][4][4] = {};
    float cs[2][2] = {};

    for (int nc = nb; nc < nb + KLEN; nc += 32) {
        __syncthreads();
        #pragma unroll
        for (int i = 0; i < 2; i++) {
            int idx = t + i * 256; int n = idx >> 4, d4 = idx & 15;
            float4 vq = f2tf4(*(const float4*)&Qb[(size_t)(nc + n)*64 + d4*4]);
            float4 vv = f2tf4(*(const float4*)&Vb[(size_t)(nc + n)*64 + d4*4]);
            *(float4*)&Qs[n*68 + d4*4] = vq;
            *(float4*)&Vs[n*72 + d4*4] = vv;
        }
        __syncthreads();
        float Cs[2][2][4] = {};
        #pragma unroll
        for (int kk = 0; kk < 8; kk++) {
            uint32_t bb[2][2];
            #pragma unroll
            for (int ni = 0; ni < 2; ni++) {
                const float* bp = &Qs[(wsn + ni*8 + g)*68 + kk*8 + q4];
                bb[ni][0] = __float_as_uint(bp[0]);
                bb[ni][1] = __float_as_uint(bp[4]);
            }
            #pragma unroll
            for (int mi = 0; mi < 2; mi++)
                #pragma unroll
                for (int ni = 0; ni < 2; ni++) mma8(Cs[mi][ni], AF[kk][mi], bb[ni]);
        }
        #pragma unroll
        for (int mi = 0; mi < 2; mi++)
            #pragma unroll
            for (int ni = 0; ni < 2; ni++)
                #pragma unroll
                for (int cc = 0; cc < 4; cc++) {
                    float e = __expf(Cs[mi][ni][cc] * SCALE);
                    cs[mi][cc >> 1] += e;
                    Es[(wm + mi*16 + (cc>>1)*8 + g)*36 + wsn + ni*8 + 2*q4 + (cc&1)] = f2tf(e);
                }
        __syncthreads();
        #pragma unroll
        for (int kk = 0; kk < 4; kk++) {
            uint32_t a[2][4], bb[4][2];
            #pragma unroll
            for (int mi = 0; mi < 2; mi++) {
                const float* ap = &Es[(wm + mi*16 + g)*36 + kk*8 + q4];
                a[mi][0] = __float_as_uint(ap[0]);
                a[mi][1] = __float_as_uint(ap[8*36]);
                a[mi][2] = __float_as_uint(ap[4]);
                a[mi][3] = __float_as_uint(ap[8*36+4]);
            }
            #pragma unroll
            for (int ni = 0; ni < 4; ni++) {
                const float* bp = &Vs[(kk*8 + q4)*72 + wd + ni*8 + g];
                bb[ni][0] = __float_as_uint(bp[0]);
                bb[ni][1] = __float_as_uint(bp[4*72]);
            }
            #pragma unroll
            for (int mi = 0; mi < 2; mi++)
                #pragma unroll
                for (int ni = 0; ni < 4; ni++) mma8(C[mi][ni], a[mi], bb[ni]);
        }
    }
    #pragma unroll
    for (int mi = 0; mi < 2; mi++)
        #pragma unroll
        for (int gh = 0; gh < 2; gh++) {
            float v = cs[mi][gh];
            v += __shfl_xor_sync(0xFFFFFFFFu, v, 1);
            v += __shfl_xor_sync(0xFFFFFFFFu, v, 2);
            if (q4 == 0) atomicAdd(&scs[wm + mi*16 + gh*8 + g], v);
        }
    __syncthreads();
    if (t < 128) atomicAdd(&g_colsum[(size_t)bh*MTOT + mtile + t], scs[t]);
    #pragma unroll
    for (int mi = 0; mi < 2; mi++)
        #pragma unroll
        for (int ni = 0; ni < 4; ni++)
            #pragma unroll
            for (int cc = 0; cc < 4; cc++) {
                int m = mtile + wm + mi*16 + g + (cc >> 1)*8;
                int d = wd + ni*8 + 2*q4 + (cc & 1);
                atomicAdd(&g_monum[((size_t)bh*MTOT + m)*64 + d], C[mi][ni][cc]);
            }
}

// ------------------ finalize map_out (float4 over d) ------------------
__global__ void k_mapout(const float* __restrict__ w, float* __restrict__ outp)
{
    int gid = blockIdx.x * 256 + threadIdx.x;
    int m = gid & 511;
    int o = (gid >> 9) & 63;
    int b = gid >> 15;
    float inv[4];
    #pragma unroll
    for (int hh = 0; hh < 4; hh++)
        inv[hh] = 1.f / g_colsum[(size_t)(b * 4 + hh) * 512 + m];
    const float* wo = w + o * 256;
    float s = 0.f;
    #pragma unroll 4
    for (int d4 = 0; d4 < 16; d4++) {
        #pragma unroll
        for (int hh = 0; hh < 4; hh++) {
            float4 mv = *(const float4*)&g_monum[((size_t)(b*4 + hh)*512 + m)*64 + d4*4];
            s += (wo[16*d4 + hh]      * mv.x +
                  wo[16*d4 + 4 + hh]  * mv.y +
                  wo[16*d4 + 8 + hh]  * mv.z +
                  wo[16*d4 + 12 + hh] * mv.w) * inv[hh];
        }
    }
    outp[(size_t)FEAT_OUT_ELEMS + ((size_t)(b * 64 + o)) * 512 + m] = s;
}

// ------------------ pointwise out GEMM (tf32 mma): [128,256]@[256,N] ------
__global__ __launch_bounds__(256) void k_pw_out(const float* __restrict__ A,
                                                float* __restrict__ outp)
{
    __shared__ float As[64*36];
    __shared__ float Bs[32*136];
    int t = threadIdx.x, w = t >> 5, l = t & 31, g = l >> 2, q4 = l & 3;
    int bn = blockIdx.x * 128, bo = blockIdx.y * 64, b = blockIdx.z;
    int wm = (w >> 2) * 32, wn = (w & 3) * 32;
    float C[2][4][4] = {};
    const float* Xb = g_dw2 + (size_t)b * INNER * NTOT;
    for (int kc = 0; kc < 256; kc += 32) {
        __syncthreads();
        #pragma unroll
        for (int i = 0; i < 2; i++) {
            int idx = t + i * 256; int m = idx >> 3, k4 = idx & 7;
            float4 v = f2tf4(*(const float4*)&A[(bo + m)*256 + kc + k4*4]);
            *(float4*)&As[m*36 + k4*4] = v;
        }
        #pragma unroll
        for (int i = 0; i < 4; i++) {
            int idx = t + i * 256; int k = idx >> 5, n4 = idx & 31;
            float4 v = f2tf4(*(const float4*)&Xb[(size_t)(kc + k)*NTOT + bn + n4*4]);
            *(float4*)&Bs[k*136 + n4*4] = v;
        }
        __syncthreads();
        #pragma unroll
        for (int kk = 0; kk < 4; kk++) {
            uint32_t a[2][4], bb[4][2];
            #pragma unroll
            for (int mi = 0; mi < 2; mi++) {
                const float* ap = &As[(wm + mi*16 + g)*36 + kk*8 + q4];
                a[mi][0] = __float_as_uint(ap[0]);
                a[mi][1] = __float_as_uint(ap[8*36]);
                a[mi][2] = __float_as_uint(ap[4]);
                a[mi][3] = __float_as_uint(ap[8*36+4]);
            }
            #pragma unroll
            for (int ni = 0; ni < 4; ni++) {
                const float* bp = &Bs[(kk*8 + q4)*136 + wn + ni*8 + g];
                bb[ni][0] = __float_as_uint(bp[0]);
                bb[ni][1] = __float_as_uint(bp[4*136]);
            }
            #pragma unroll
            for (int mi = 0; mi < 2; mi++)
                #pragma unroll
                for (int ni = 0; ni < 4; ni++) mma8(C[mi][ni], a[mi], bb[ni]);
        }
    }
    #pragma unroll
    for (int mi = 0; mi < 2; mi++)
        #pragma unroll
        for (int ni = 0; ni < 4; ni++)
            #pragma unroll
            for (int cc = 0; cc < 4; cc++) {
                int o = bo + wm + mi*16 + g + (cc >> 1)*8;
                int n = bn + wn + ni*8 + 2*q4 + (cc & 1);
                outp[((size_t)(b * 128 + o)) * NTOT + n] = C[mi][ni][cc];
            }
}

// ------------------ launch ------------------
extern "C" void kernel_launch(void* const* d_in, const int* in_sizes, int n_in,
                              void* d_out, int out_size)
{
    const float* feat    = (const float*)d_in[0];
    const float* smap    = (const float*)d_in[1];
    const float* fqv_dw  = (const float*)d_in[2];
    const float* fqv_pw  = (const float*)d_in[3];
    const float* fout_dw = (const float*)d_in[4];
    const float* fout_pw = (const float*)d_in[5];
    const float* mqv_w   = (const float*)d_in[6];
    const float* mout_w  = (const float*)d_in[7];
    float* outp = (float*)d_out;

    k_dwconv1<<<dim3(14, 128, 2), 256>>>(feat, fqv_dw);
    k_map_qv <<<dim3(16, 2), 256>>>(mqv_w, smap);
    k_pw_qv  <<<dim3(108, 8, 2), 256>>>(fqv_pw);
    k_attn1  <<<dim3(216, 8), 256>>>();          // launch #4 -> ncu window
    k_zero_a <<<1024, 256>>>();
    k_zero_b <<<16, 256>>>();
    k_attn2  <<<dim3(KSPLIT, 4, 8), 256>>>();
    k_dwconv2<<<dim3(14, 256, 2), 256>>>(fout_dw);
    k_mapout <<<256, 256>>>(mout_w, outp);
    k_pw_out <<<dim3(108, 2, 2), 256>>>(fout_pw, outp);
}

// round 9
// speedup vs baseline: 3.2667x; 1.0727x over previous
#include <cuda_runtime.h>
#include <math.h>
#include <stdint.h>

#define BSZ   2
#define CF    128
#define NTOT  13824      // 24^3
#define MTOT  512        // 8^3
#define NHEAD 4
#define DHEAD 64
#define INNER 256
#define SCALE 0.125f     // 64^-0.5
#define FEAT_OUT_ELEMS 3538944   // 2*128*13824
#define KSPLIT 9
#define KLEN   1536      // 13824/9

// ------------------ scratch (device globals; no allocs) ------------------
__device__ __align__(16) float g_t1   [BSZ*CF*NTOT];            // dwconv1 out
__device__ __align__(16) float g_q    [BSZ*NHEAD*NTOT*DHEAD];   // feat_q  [bh][n][d] (tf32 bits)
__device__ __align__(16) float g_fv   [BSZ*NHEAD*NTOT*DHEAD];   // feat_v  [bh][n][d] (tf32 bits)
__device__ __align__(16) float g_mq   [BSZ*NHEAD*MTOT*DHEAD];   // map_q   [bh][m][d] (tf32 bits)
__device__ __align__(16) float g_mv   [BSZ*NHEAD*MTOT*DHEAD];   // map_v   [bh][m][d] (tf32 bits)
__device__ __align__(16) float g_attnout[BSZ*INNER*NTOT];       // feat attn out [b][c][n]
__device__ __align__(16) float g_dw2  [BSZ*INNER*NTOT];         // dwconv2 out
__device__ __align__(16) float g_monum[BSZ*NHEAD*MTOT*DHEAD];   // map_out numerator
__device__ __align__(16) float g_colsum[BSZ*NHEAD*MTOT];

// ------------------ tf32 mma helpers ------------------
__device__ __forceinline__ uint32_t f2t(float x){
    uint32_t r; asm("cvt.rna.tf32.f32 %0,%1;":"=r"(r):"f"(x)); return r;
}
__device__ __forceinline__ float f2tf(float x){ return __uint_as_float(f2t(x)); }
__device__ __forceinline__ float4 f2tf4(float4 v){
    v.x = f2tf(v.x); v.y = f2tf(v.y); v.z = f2tf(v.z); v.w = f2tf(v.w); return v;
}

__device__ __forceinline__ void mma8(float* c, const uint32_t* a, const uint32_t* b){
    asm volatile("mma.sync.aligned.m16n8k8.row.col.f32.tf32.tf32.f32 "
        "{%0,%1,%2,%3},{%4,%5,%6,%7},{%8,%9},{%0,%1,%2,%3};"
        : "+f"(c[0]),"+f"(c[1]),"+f"(c[2]),"+f"(c[3])
        : "r"(a[0]),"r"(a[1]),"r"(a[2]),"r"(a[3]),"r"(b[0]),"r"(b[1]));
}

// ------------------ cp.async helpers ------------------
__device__ __forceinline__ void cpa16(void* smem, const void* g){
    uint32_t s = (uint32_t)__cvta_generic_to_shared(smem);
    asm volatile("cp.async.ca.shared.global [%0], [%1], 16;" :: "r"(s), "l"(g));
}
#define CPA_COMMIT() asm volatile("cp.async.commit_group;")
#define CPA_WAIT0()  asm volatile("cp.async.wait_group 0;" ::: "memory")

// ------------------ depthwise 3x3x3, SAME, x-vectorized (4 outputs/thread) --
__device__ __forceinline__ void dw_body_v4(const float* __restrict__ in,
                                           const float* __restrict__ w,
                                           float* __restrict__ out, int C)
{
    __shared__ float ws[27];
    int t = threadIdx.x;
    int c = blockIdx.y, b = blockIdx.z;
    if (t < 27) ws[t] = w[c * 27 + t];
    __syncthreads();
    int idx = blockIdx.x * 256 + t;          // over 24*24*6 = 3456
    if (idx >= 3456) return;
    int x4 = (idx % 6) * 4;
    int y  = (idx / 6) % 24;
    int z  = idx / 144;
    const float* ip = in + ((size_t)(b * C + c)) * NTOT;
    float acc0 = 0.f, acc1 = 0.f, acc2 = 0.f, acc3 = 0.f;
    #pragma unroll
    for (int dz = -1; dz <= 1; dz++) {
        int zz = z + dz; if (zz < 0 || zz >= 24) continue;
        #pragma unroll
        for (int dy = -1; dy <= 1; dy++) {
            int yy = y + dy; if (yy < 0 || yy >= 24) continue;
            const float* row = ip + (zz * 24 + yy) * 24;
            float4 mid = *(const float4*)(row + x4);
            float left  = (x4 > 0)      ? row[x4 - 1] : 0.f;
            float right = (x4 + 4 < 24) ? row[x4 + 4] : 0.f;
            const float* wr = ws + (dz + 1) * 9 + (dy + 1) * 3;
            float w0 = wr[0], w1 = wr[1], w2 = wr[2];
            acc0 += w0 * left  + w1 * mid.x + w2 * mid.y;
            acc1 += w0 * mid.x + w1 * mid.y + w2 * mid.z;
            acc2 += w0 * mid.y + w1 * mid.z + w2 * mid.w;
            acc3 += w0 * mid.z + w1 * mid.w + w2 * right;
        }
    }
    float4 o = make_float4(acc0, acc1, acc2, acc3);
    *(float4*)(out + ((size_t)(b * C + c)) * NTOT + (z * 24 + y) * 24 + x4) = o;
}

__global__ void k_dwconv1(const float* __restrict__ feat, const float* __restrict__ w)
{   dw_body_v4(feat, w, g_t1, CF); }

__global__ void k_dwconv2(const float* __restrict__ w)
{   dw_body_v4(g_attnout, w, g_dw2, INNER); }

// ------------------ pointwise qv GEMM (tf32 mma): [512,128]@[128,N] + head scatter
__global__ __launch_bounds__(256) void k_pw_qv(const float* __restrict__ A)
{
    __shared__ float As[64*36];   // [m][k] pitch 36
    __shared__ float Bs[32*136];  // [k][n] pitch 136
    int t = threadIdx.x, w = t >> 5, l = t & 31, g = l >> 2, q4 = l & 3;
    int bn = blockIdx.x * 128, bo = blockIdx.y * 64, b = blockIdx.z;
    int wm = (w >> 2) * 32, wn = (w & 3) * 32;
    float C[2][4][4] = {};
    const float* Xb = g_t1 + (size_t)b * CF * NTOT;
    for (int kc = 0; kc < 128; kc += 32) {
        __syncthreads();
        #pragma unroll
        for (int i = 0; i < 2; i++) {
            int idx = t + i * 256; int m = idx >> 3, k4 = idx & 7;
            float4 v = f2tf4(*(const float4*)&A[(bo + m)*128 + kc + k4*4]);
            *(float4*)&As[m*36 + k4*4] = v;
        }
        #pragma unroll
        for (int i = 0; i < 4; i++) {
            int idx = t + i * 256; int k = idx >> 5, n4 = idx & 31;
            float4 v = f2tf4(*(const float4*)&Xb[(size_t)(kc + k)*NTOT + bn + n4*4]);
            *(float4*)&Bs[k*136 + n4*4] = v;
        }
        __syncthreads();
        #pragma unroll
        for (int kk = 0; kk < 4; kk++) {
            uint32_t a[2][4], bb[4][2];
            #pragma unroll
            for (int mi = 0; mi < 2; mi++) {
                const float* ap = &As[(wm + mi*16 + g)*36 + kk*8 + q4];
                a[mi][0] = __float_as_uint(ap[0]);
                a[mi][1] = __float_as_uint(ap[8*36]);
                a[mi][2] = __float_as_uint(ap[4]);
                a[mi][3] = __float_as_uint(ap[8*36+4]);
            }
            #pragma unroll
            for (int ni = 0; ni < 4; ni++) {
                const float* bp = &Bs[(kk*8 + q4)*136 + wn + ni*8 + g];
                bb[ni][0] = __float_as_uint(bp[0]);
                bb[ni][1] = __float_as_uint(bp[4*136]);
            }
            #pragma unroll
            for (int mi = 0; mi < 2; mi++)
                #pragma unroll
                for (int ni = 0; ni < 4; ni++) mma8(C[mi][ni], a[mi], bb[ni]);
        }
    }
    #pragma unroll
    for (int mi = 0; mi < 2; mi++)
        #pragma unroll
        for (int ni = 0; ni < 4; ni++)
            #pragma unroll
            for (int cc = 0; cc < 4; cc++) {
                int o = bo + wm + mi*16 + g + (cc >> 1)*8;
                int n = bn + wn + ni*8 + 2*q4 + (cc & 1);
                float v = f2tf(C[mi][ni][cc]);   // pre-round for attention consumers
                if (o < 256)
                    g_q[((size_t)(b*4 + (o & 3))*NTOT + n)*64 + (o >> 2)] = v;
                else {
                    int c2 = o - 256;
                    g_fv[((size_t)(b*4 + (c2 & 3))*NTOT + n)*64 + (c2 >> 2)] = v;
                }
            }
}

// ------------------ map qv (also zero-fills monum/colsum) ------------------
__global__ __launch_bounds__(256) void k_map_qv(const float* __restrict__ w,
                                                const float* __restrict__ smap)
{
    __shared__ float Ws[32*68];   // [o][c]
    __shared__ float Bs[64*132];  // [c][m-chunk]
    int t = threadIdx.x;
    int bo = blockIdx.x * 32, b = blockIdx.y;
    int ol = (t >> 5) * 4;
    int ml = (t & 31) * 4;
    // zero accumulators (32 blocks x 256 threads = 8192 threads)
    {
        int flat = (blockIdx.y * gridDim.x + blockIdx.x) * 256 + t;
        float4 z4 = make_float4(0.f, 0.f, 0.f, 0.f);
        #pragma unroll
        for (int i = 0; i < 8; i++)
            *(float4*)&g_monum[((size_t)flat * 8 + i) * 4] = z4;
        if (flat < BSZ * NHEAD * MTOT) g_colsum[flat] = 0.f;
    }
    // stage W tile once
    #pragma unroll
    for (int i = 0; i < 2; i++) {
        int idx = t + i * 256; int o = idx >> 4, c4 = idx & 15;
        *(float4*)&Ws[o*68 + c4*4] = *(const float4*)&w[(bo + o)*64 + c4*4];
    }
    for (int mc = 0; mc < 512; mc += 128) {
        __syncthreads();
        #pragma unroll
        for (int i = 0; i < 8; i++) {
            int idx = t + i * 256; int c = idx >> 5, m4 = idx & 31;
            *(float4*)&Bs[c*132 + m4*4] =
                *(const float4*)&smap[((size_t)(b*64 + c))*512 + mc + m4*4];
        }
        __syncthreads();
        float acc[4][4] = {};
        #pragma unroll 8
        for (int c = 0; c < 64; c++) {
            float4 bv = *(const float4*)&Bs[c*132 + ml];
            #pragma unroll
            for (int oi = 0; oi < 4; oi++) {
                float wv = Ws[(ol + oi)*68 + c];
                acc[oi][0] += wv * bv.x; acc[oi][1] += wv * bv.y;
                acc[oi][2] += wv * bv.z; acc[oi][3] += wv * bv.w;
            }
        }
        #pragma unroll
        for (int oi = 0; oi < 4; oi++) {
            int oo = bo + ol + oi;
            float* dst; int oc;
            if (oo < 256) { dst = g_mq; oc = oo; } else { dst = g_mv; oc = oo - 256; }
            size_t base = ((size_t)(b*4 + (oc & 3))*512 + mc + ml)*64 + (oc >> 2);
            dst[base]       = f2tf(acc[oi][0]);
            dst[base + 64]  = f2tf(acc[oi][1]);
            dst[base + 128] = f2tf(acc[oi][2]);
            dst[base + 192] = f2tf(acc[oi][3]);
        }
    }
}

// ------------------ attention pass 1: n-tile 128, 32x32 warp tiles ---------
// 8 warps = 4 n-groups(32) x 2 col-groups; chunks of 32 map tokens.
// MQ double-buffered (cp.async), MV single-buffered, E via smem, O direct STG.
__global__ __launch_bounds__(256, 2) void k_attn1()
{
    __shared__ float MQd[2*32*68];
    __shared__ float MVd[32*68];     // also QF staging scratch
    __shared__ float Es[128*36];
    __shared__ float srs[128];
    int t = threadIdx.x, w = t >> 5, l = t & 31, g = l >> 2, q4 = l & 3;
    int bh = blockIdx.y, b = bh >> 2, h = bh & 3;
    int nb = blockIdx.x * 128;
    int wn  = (w >> 1) * 32;   // n rows
    int wsm = (w & 1) * 16;    // S-phase m cols
    int wd  = (w & 1) * 32;    // O-phase d cols

    if (t < 128) srs[t] = 0.f;
    const float* Qb  = g_q  + ((size_t)bh*NTOT + nb) * 64;
    const float* MQg = g_mq + (size_t)bh * MTOT * 64;
    const float* MVg = g_mv + (size_t)bh * MTOT * 64;

    // prefetch MQ chunk 0 -> buf 0 (overlaps QF staging)
    #pragma unroll
    for (int i = 0; i < 2; i++) {
        int idx = t + i*256; int m = idx >> 4, d4 = idx & 15;
        cpa16(&MQd[m*68 + d4*4], MQg + (size_t)m*64 + d4*4);
    }
    CPA_COMMIT();

    // QF: 4 passes of 32 Q rows staged through MVd scratch
    uint32_t QF[8][2][4];
    for (int p = 0; p < 4; p++) {
        __syncthreads();
        #pragma unroll
        for (int i = 0; i < 2; i++) {
            int idx = t + i*256; int n = idx >> 4, d4 = idx & 15;
            *(float4*)&MVd[n*68 + d4*4] = *(const float4*)&Qb[(size_t)(p*32 + n)*64 + d4*4];
        }
        __syncthreads();
        if ((w >> 1) == p) {
            #pragma unroll
            for (int kk = 0; kk < 8; kk++)
                #pragma unroll
                for (int mi = 0; mi < 2; mi++) {
                    const float* ap = &MVd[(mi*16 + g)*68 + kk*8 + q4];
                    QF[kk][mi][0] = __float_as_uint(ap[0]);
                    QF[kk][mi][1] = __float_as_uint(ap[8*68]);
                    QF[kk][mi][2] = __float_as_uint(ap[4]);
                    QF[kk][mi][3] = __float_as_uint(ap[8*68+4]);
                }
        }
    }
    CPA_WAIT0();
    __syncthreads();

    float OF[2][4][4] = {};
    float rs[2][2] = {};

    for (int mc = 0; mc < 16; mc++) {
        int buf = (mc & 1) * 2176;
        // issue MV(mc) and MQ(mc+1)
        size_t go = (size_t)mc * 32 * 64;
        #pragma unroll
        for (int i = 0; i < 2; i++) {
            int idx = t + i*256; int m = idx >> 4, d4 = idx & 15;
            cpa16(&MVd[m*68 + d4*4], MVg + go + (size_t)m*64 + d4*4);
        }
        if (mc < 15) {
            int nxt = ((mc + 1) & 1) * 2176;
            #pragma unroll
            for (int i = 0; i < 2; i++) {
                int idx = t + i*256; int m = idx >> 4, d4 = idx & 15;
                cpa16(&MQd[nxt + m*68 + d4*4], MQg + go + 2048 + (size_t)m*64 + d4*4);
            }
        }
        CPA_COMMIT();
        // S = Q @ MQ^T : warp tile 32n x 16m
        float Cs[2][2][4] = {};
        #pragma unroll
        for (int kk = 0; kk < 8; kk++) {
            uint32_t bb[2][2];
            #pragma unroll
            for (int ni = 0; ni < 2; ni++) {
                const float* bp = &MQd[buf + (wsm + ni*8 + g)*68 + kk*8 + q4];
                bb[ni][0] = __float_as_uint(bp[0]);
                bb[ni][1] = __float_as_uint(bp[4]);
            }
            #pragma unroll
            for (int mi = 0; mi < 2; mi++)
                #pragma unroll
                for (int ni = 0; ni < 2; ni++) mma8(Cs[mi][ni], QF[kk][mi], bb[ni]);
        }
        // exp, rowsum, stage E (tf32 bits) into Es [n][m]
        #pragma unroll
        for (int mi = 0; mi < 2; mi++)
            #pragma unroll
            for (int ni = 0; ni < 2; ni++)
                #pragma unroll
                for (int cc = 0; cc < 4; cc++) {
                    float e = __expf(Cs[mi][ni][cc] * SCALE);
                    rs[mi][cc >> 1] += e;
                    Es[(wn + mi*16 + (cc>>1)*8 + g)*36 + wsm + ni*8 + 2*q4 + (cc&1)] = f2tf(e);
                }
        CPA_WAIT0();
        __syncthreads();   // E visible + MV(mc) ready
        // O += E @ MV : warp tile 32n x 32d
        #pragma unroll
        for (int kk = 0; kk < 4; kk++) {
            uint32_t a[2][4], bb[4][2];
            #pragma unroll
            for (int mi = 0; mi < 2; mi++) {
                const float* ap = &Es[(wn + mi*16 + g)*36 + kk*8 + q4];
                a[mi][0] = __float_as_uint(ap[0]);
                a[mi][1] = __float_as_uint(ap[8*36]);
                a[mi][2] = __float_as_uint(ap[4]);
                a[mi][3] = __float_as_uint(ap[8*36+4]);
            }
            #pragma unroll
            for (int ni = 0; ni < 4; ni++) {
                const float* bp = &MVd[(kk*8 + q4)*68 + wd + ni*8 + g];
                bb[ni][0] = __float_as_uint(bp[0]);
                bb[ni][1] = __float_as_uint(bp[4*68]);
            }
            #pragma unroll
            for (int mi = 0; mi < 2; mi++)
                #pragma unroll
                for (int ni = 0; ni < 4; ni++) mma8(OF[mi][ni], a[mi], bb[ni]);
        }
        __syncthreads();   // all done with MVd/Es before next iter overwrites
    }
    // rowsum: quad-reduce then combine the 2 col-group warps via smem atomics
    #pragma unroll
    for (int mi = 0; mi < 2; mi++)
        #pragma unroll
        for (int gh = 0; gh < 2; gh++) {
            float v = rs[mi][gh];
            v += __shfl_xor_sync(0xFFFFFFFFu, v, 1);
            v += __shfl_xor_sync(0xFFFFFFFFu, v, 2);
            if (q4 == 0) atomicAdd(&srs[wn + mi*16 + gh*8 + g], v);
        }
    __syncthreads();
    // normalize + direct store O to g_attnout [4d+h][n]
    float* ao = g_attnout + (size_t)b * INNER * NTOT + nb;
    #pragma unroll
    for (int mi = 0; mi < 2; mi++) {
        int n0 = wn + mi*16 + g;
        float inv0 = 1.f / srs[n0];
        float inv1 = 1.f / srs[n0 + 8];
        #pragma unroll
        for (int ni = 0; ni < 4; ni++) {
            int d0 = wd + ni*8 + 2*q4;
            ao[(size_t)(4*d0 + h)*NTOT + n0]         = OF[mi][ni][0] * inv0;
            ao[(size_t)(4*(d0+1) + h)*NTOT + n0]     = OF[mi][ni][1] * inv0;
            ao[(size_t)(4*d0 + h)*NTOT + n0 + 8]     = OF[mi][ni][2] * inv1;
            ao[(size_t)(4*(d0+1) + h)*NTOT + n0 + 8] = OF[mi][ni][3] * inv1;
        }
    }
}

// ------------------ attention pass 2: recompute E, split-K over n ----------
__global__ __launch_bounds__(256, 2) void k_attn2()
{
    __shared__ float Qs[32*68];   // [n][d]
    __shared__ float Vs[32*72];   // [n][d]
    __shared__ float Es[128*36];  // [m][n-chunk]
    __shared__ float scs[128];
    int t = threadIdx.x, w = t >> 5, l = t & 31, g = l >> 2, q4 = l & 3;
    int bh = blockIdx.z; int mtile = blockIdx.y * 128; int nb = blockIdx.x * KLEN;
    int wm = (w >> 1) * 32, wsn = (w & 1) * 16, wd = (w & 1) * 32;
    const float* Qb = g_q  + (size_t)bh * NTOT * 64;
    const float* Vb = g_fv + (size_t)bh * NTOT * 64;
    if (t < 128) scs[t] = 0.f;

    uint32_t AF[8][2][4];
    const float* MQb = g_mq + ((size_t)bh * MTOT + mtile) * 64;
    #pragma unroll
    for (int kk = 0; kk < 8; kk++)
        #pragma unroll
        for (int mi = 0; mi < 2; mi++) {
            const float* p = MQb + (wm + mi*16 + g)*64 + kk*8 + q4;
            AF[kk][mi][0] = __float_as_uint(p[0]);
            AF[kk][mi][1] = __float_as_uint(p[8*64]);
            AF[kk][mi][2] = __float_as_uint(p[4]);
            AF[kk][mi][3] = __float_as_uint(p[8*64+4]);
        }
    float C[2][4][4] = {};
    float cs[2][2] = {};

    for (int nc = nb; nc < nb + KLEN; nc += 32) {
        __syncthreads();
        #pragma unroll
        for (int i = 0; i < 2; i++) {
            int idx = t + i * 256; int n = idx >> 4, d4 = idx & 15;
            *(float4*)&Qs[n*68 + d4*4] = *(const float4*)&Qb[(size_t)(nc + n)*64 + d4*4];
            *(float4*)&Vs[n*72 + d4*4] = *(const float4*)&Vb[(size_t)(nc + n)*64 + d4*4];
        }
        __syncthreads();
        float Cs[2][2][4] = {};
        #pragma unroll
        for (int kk = 0; kk < 8; kk++) {
            uint32_t bb[2][2];
            #pragma unroll
            for (int ni = 0; ni < 2; ni++) {
                const float* bp = &Qs[(wsn + ni*8 + g)*68 + kk*8 + q4];
                bb[ni][0] = __float_as_uint(bp[0]);
                bb[ni][1] = __float_as_uint(bp[4]);
            }
            #pragma unroll
            for (int mi = 0; mi < 2; mi++)
                #pragma unroll
                for (int ni = 0; ni < 2; ni++) mma8(Cs[mi][ni], AF[kk][mi], bb[ni]);
        }
        #pragma unroll
        for (int mi = 0; mi < 2; mi++)
            #pragma unroll
            for (int ni = 0; ni < 2; ni++)
                #pragma unroll
                for (int cc = 0; cc < 4; cc++) {
                    float e = __expf(Cs[mi][ni][cc] * SCALE);
                    cs[mi][cc >> 1] += e;
                    Es[(wm + mi*16 + (cc>>1)*8 + g)*36 + wsn + ni*8 + 2*q4 + (cc&1)] = f2tf(e);
                }
        __syncthreads();
        #pragma unroll
        for (int kk = 0; kk < 4; kk++) {
            uint32_t a[2][4], bb[4][2];
            #pragma unroll
            for (int mi = 0; mi < 2; mi++) {
                const float* ap = &Es[(wm + mi*16 + g)*36 + kk*8 + q4];
                a[mi][0] = __float_as_uint(ap[0]);
                a[mi][1] = __float_as_uint(ap[8*36]);
                a[mi][2] = __float_as_uint(ap[4]);
                a[mi][3] = __float_as_uint(ap[8*36+4]);
            }
            #pragma unroll
            for (int ni = 0; ni < 4; ni++) {
                const float* bp = &Vs[(kk*8 + q4)*72 + wd + ni*8 + g];
                bb[ni][0] = __float_as_uint(bp[0]);
                bb[ni][1] = __float_as_uint(bp[4*72]);
            }
            #pragma unroll
            for (int mi = 0; mi < 2; mi++)
                #pragma unroll
                for (int ni = 0; ni < 4; ni++) mma8(C[mi][ni], a[mi], bb[ni]);
        }
    }
    #pragma unroll
    for (int mi = 0; mi < 2; mi++)
        #pragma unroll
        for (int gh = 0; gh < 2; gh++) {
            float v = cs[mi][gh];
            v += __shfl_xor_sync(0xFFFFFFFFu, v, 1);
            v += __shfl_xor_sync(0xFFFFFFFFu, v, 2);
            if (q4 == 0) atomicAdd(&scs[wm + mi*16 + gh*8 + g], v);
        }
    __syncthreads();
    if (t < 128) atomicAdd(&g_colsum[(size_t)bh*MTOT + mtile + t], scs[t]);
    #pragma unroll
    for (int mi = 0; mi < 2; mi++)
        #pragma unroll
        for (int ni = 0; ni < 4; ni++)
            #pragma unroll
            for (int cc = 0; cc < 4; cc++) {
                int m = mtile + wm + mi*16 + g + (cc >> 1)*8;
                int d = wd + ni*8 + 2*q4 + (cc & 1);
                atomicAdd(&g_monum[((size_t)bh*MTOT + m)*64 + d], C[mi][ni][cc]);
            }
}

// ------------------ finalize map_out (float4 over d) ------------------
__global__ void k_mapout(const float* __restrict__ w, float* __restrict__ outp)
{
    int gid = blockIdx.x * 256 + threadIdx.x;
    int m = gid & 511;
    int o = (gid >> 9) & 63;
    int b = gid >> 15;
    float inv[4];
    #pragma unroll
    for (int hh = 0; hh < 4; hh++)
        inv[hh] = 1.f / g_colsum[(size_t)(b * 4 + hh) * 512 + m];
    const float* wo = w + o * 256;
    float s = 0.f;
    #pragma unroll 4
    for (int d4 = 0; d4 < 16; d4++) {
        #pragma unroll
        for (int hh = 0; hh < 4; hh++) {
            float4 mv = *(const float4*)&g_monum[((size_t)(b*4 + hh)*512 + m)*64 + d4*4];
            s += (wo[16*d4 + hh]      * mv.x +
                  wo[16*d4 + 4 + hh]  * mv.y +
                  wo[16*d4 + 8 + hh]  * mv.z +
                  wo[16*d4 + 12 + hh] * mv.w) * inv[hh];
        }
    }
    outp[(size_t)FEAT_OUT_ELEMS + ((size_t)(b * 64 + o)) * 512 + m] = s;
}

// ------------------ pointwise out GEMM (tf32 mma): [128,256]@[256,N] ------
__global__ __launch_bounds__(256) void k_pw_out(const float* __restrict__ A,
                                                float* __restrict__ outp)
{
    __shared__ float As[64*36];
    __shared__ float Bs[32*136];
    int t = threadIdx.x, w = t >> 5, l = t & 31, g = l >> 2, q4 = l & 3;
    int bn = blockIdx.x * 128, bo = blockIdx.y * 64, b = blockIdx.z;
    int wm = (w >> 2) * 32, wn = (w & 3) * 32;
    float C[2][4][4] = {};
    const float* Xb = g_dw2 + (size_t)b * INNER * NTOT;
    for (int kc = 0; kc < 256; kc += 32) {
        __syncthreads();
        #pragma unroll
        for (int i = 0; i < 2; i++) {
            int idx = t + i * 256; int m = idx >> 3, k4 = idx & 7;
            float4 v = f2tf4(*(const float4*)&A[(bo + m)*256 + kc + k4*4]);
            *(float4*)&As[m*36 + k4*4] = v;
        }
        #pragma unroll
        for (int i = 0; i < 4; i++) {
            int idx = t + i * 256; int k = idx >> 5, n4 = idx & 31;
            float4 v = f2tf4(*(const float4*)&Xb[(size_t)(kc + k)*NTOT + bn + n4*4]);
            *(float4*)&Bs[k*136 + n4*4] = v;
        }
        __syncthreads();
        #pragma unroll
        for (int kk = 0; kk < 4; kk++) {
            uint32_t a[2][4], bb[4][2];
            #pragma unroll
            for (int mi = 0; mi < 2; mi++) {
                const float* ap = &As[(wm + mi*16 + g)*36 + kk*8 + q4];
                a[mi][0] = __float_as_uint(ap[0]);
                a[mi][1] = __float_as_uint(ap[8*36]);
                a[mi][2] = __float_as_uint(ap[4]);
                a[mi][3] = __float_as_uint(ap[8*36+4]);
            }
            #pragma unroll
            for (int ni = 0; ni < 4; ni++) {
                const float* bp = &Bs[(kk*8 + q4)*136 + wn + ni*8 + g];
                bb[ni][0] = __float_as_uint(bp[0]);
                bb[ni][1] = __float_as_uint(bp[4*136]);
            }
            #pragma unroll
            for (int mi = 0; mi < 2; mi++)
                #pragma unroll
                for (int ni = 0; ni < 4; ni++) mma8(C[mi][ni], a[mi], bb[ni]);
        }
    }
    #pragma unroll
    for (int mi = 0; mi < 2; mi++)
        #pragma unroll
        for (int ni = 0; ni < 4; ni++)
            #pragma unroll
            for (int cc = 0; cc < 4; cc++) {
                int o = bo + wm + mi*16 + g + (cc >> 1)*8;
                int n = bn + wn + ni*8 + 2*q4 + (cc & 1);
                outp[((size_t)(b * 128 + o)) * NTOT + n] = C[mi][ni][cc];
            }
}

// ------------------ launch ------------------
extern "C" void kernel_launch(void* const* d_in, const int* in_sizes, int n_in,
                              void* d_out, int out_size)
{
    const float* feat    = (const float*)d_in[0];
    const float* smap    = (const float*)d_in[1];
    const float* fqv_dw  = (const float*)d_in[2];
    const float* fqv_pw  = (const float*)d_in[3];
    const float* fout_dw = (const float*)d_in[4];
    const float* fout_pw = (const float*)d_in[5];
    const float* mqv_w   = (const float*)d_in[6];
    const float* mout_w  = (const float*)d_in[7];
    float* outp = (float*)d_out;

    k_dwconv1<<<dim3(14, 128, 2), 256>>>(feat, fqv_dw);
    k_map_qv <<<dim3(16, 2), 256>>>(mqv_w, smap);       // also zeros monum/colsum
    k_pw_qv  <<<dim3(108, 8, 2), 256>>>(fqv_pw);
    k_attn2  <<<dim3(KSPLIT, 4, 8), 256>>>();           // launch #4 -> ncu window
    k_attn1  <<<dim3(108, 8), 256>>>();
    k_dwconv2<<<dim3(14, 256, 2), 256>>>(fout_dw);
    k_mapout <<<256, 256>>>(mout_w, outp);
    k_pw_out <<<dim3(108, 2, 2), 256>>>(fout_pw, outp);
}

// round 11
// speedup vs baseline: 3.4309x; 1.0503x over previous
#include <cuda_runtime.h>
#include <math.h>
#include <stdint.h>

#define BSZ   2
#define CF    128
#define NTOT  13824      // 24^3
#define MTOT  512        // 8^3
#define NHEAD 4
#define DHEAD 64
#define INNER 256
#define SCALE 0.125f     // 64^-0.5
#define FEAT_OUT_ELEMS 3538944   // 2*128*13824
#define KSPLIT 9
#define KLEN   1536      // 13824/9

// ------------------ scratch (device globals; no allocs) ------------------
__device__ __align__(16) float g_t1   [BSZ*CF*NTOT];            // dwconv1 out (tf32 bits)
__device__ __align__(16) float g_q    [BSZ*NHEAD*NTOT*DHEAD];   // feat_q (tf32 bits)
__device__ __align__(16) float g_fv   [BSZ*NHEAD*NTOT*DHEAD];   // feat_v (tf32 bits)
__device__ __align__(16) float g_mq   [BSZ*NHEAD*MTOT*DHEAD];   // map_q  (tf32 bits)
__device__ __align__(16) float g_mv   [BSZ*NHEAD*MTOT*DHEAD];   // map_v  (tf32 bits)
__device__ __align__(16) float g_attnout[BSZ*INNER*NTOT];       // feat attn out (fp32)
__device__ __align__(16) float g_dw2  [BSZ*INNER*NTOT];         // dwconv2 out (tf32 bits)
__device__ __align__(16) float g_monum[BSZ*NHEAD*MTOT*DHEAD];
__device__ __align__(16) float g_colsum[BSZ*NHEAD*MTOT];

// ------------------ tf32 mma helpers ------------------
__device__ __forceinline__ uint32_t f2t(float x){
    uint32_t r; asm("cvt.rna.tf32.f32 %0,%1;":"=r"(r):"f"(x)); return r;
}
__device__ __forceinline__ float f2tf(float x){ return __uint_as_float(f2t(x)); }
__device__ __forceinline__ float4 f2tf4(float4 v){
    v.x = f2tf(v.x); v.y = f2tf(v.y); v.z = f2tf(v.z); v.w = f2tf(v.w); return v;
}

__device__ __forceinline__ void mma8(float* c, const uint32_t* a, const uint32_t* b){
    asm volatile("mma.sync.aligned.m16n8k8.row.col.f32.tf32.tf32.f32 "
        "{%0,%1,%2,%3},{%4,%5,%6,%7},{%8,%9},{%0,%1,%2,%3};"
        : "+f"(c[0]),"+f"(c[1]),"+f"(c[2]),"+f"(c[3])
        : "r"(a[0]),"r"(a[1]),"r"(a[2]),"r"(a[3]),"r"(b[0]),"r"(b[1]));
}

// ------------------ cp.async helpers ------------------
__device__ __forceinline__ void cpa16(void* smem, const void* g){
    uint32_t s = (uint32_t)__cvta_generic_to_shared(smem);
    asm volatile("cp.async.ca.shared.global [%0], [%1], 16;" :: "r"(s), "l"(g));
}
#define CPA_COMMIT() asm volatile("cp.async.commit_group;")
#define CPA_WAIT0()  asm volatile("cp.async.wait_group 0;" ::: "memory")
#define CPA_WAIT1()  asm volatile("cp.async.wait_group 1;" ::: "memory")

// ------------------ depthwise 3x3x3, SAME, x-vectorized; output tf32-rounded
__device__ __forceinline__ void dw_body_v4(const float* __restrict__ in,
                                           const float* __restrict__ w,
                                           float* __restrict__ out, int C)
{
    __shared__ float ws[27];
    int t = threadIdx.x;
    int c = blockIdx.y, b = blockIdx.z;
    if (t < 27) ws[t] = w[c * 27 + t];
    __syncthreads();
    int idx = blockIdx.x * 256 + t;          // over 24*24*6 = 3456
    if (idx >= 3456) return;
    int x4 = (idx % 6) * 4;
    int y  = (idx / 6) % 24;
    int z  = idx / 144;
    const float* ip = in + ((size_t)(b * C + c)) * NTOT;
    float acc0 = 0.f, acc1 = 0.f, acc2 = 0.f, acc3 = 0.f;
    #pragma unroll
    for (int dz = -1; dz <= 1; dz++) {
        int zz = z + dz; if (zz < 0 || zz >= 24) continue;
        #pragma unroll
        for (int dy = -1; dy <= 1; dy++) {
            int yy = y + dy; if (yy < 0 || yy >= 24) continue;
            const float* row = ip + (zz * 24 + yy) * 24;
            float4 mid = *(const float4*)(row + x4);
            float left  = (x4 > 0)      ? row[x4 - 1] : 0.f;
            float right = (x4 + 4 < 24) ? row[x4 + 4] : 0.f;
            const float* wr = ws + (dz + 1) * 9 + (dy + 1) * 3;
            float w0 = wr[0], w1 = wr[1], w2 = wr[2];
            acc0 += w0 * left  + w1 * mid.x + w2 * mid.y;
            acc1 += w0 * mid.x + w1 * mid.y + w2 * mid.z;
            acc2 += w0 * mid.y + w1 * mid.z + w2 * mid.w;
            acc3 += w0 * mid.z + w1 * mid.w + w2 * right;
        }
    }
    float4 o = f2tf4(make_float4(acc0, acc1, acc2, acc3));
    *(float4*)(out + ((size_t)(b * C + c)) * NTOT + (z * 24 + y) * 24 + x4) = o;
}

__global__ void k_dwconv1(const float* __restrict__ feat, const float* __restrict__ w)
{   dw_body_v4(feat, w, g_t1, CF); }

__global__ void k_dwconv2(const float* __restrict__ w)
{   dw_body_v4(g_attnout, w, g_dw2, INNER); }

// ------------------ pointwise qv GEMM (pipelined, static smem) -------------
__global__ __launch_bounds__(256) void k_pw_qv(const float* __restrict__ A)
{
    __shared__ float As[64*36];      // single buffer (A staged via registers)
    __shared__ float Bs[2*32*136];   // double buffer
    int t = threadIdx.x, w = t >> 5, l = t & 31, g = l >> 2, q4 = l & 3;
    int bn = blockIdx.x * 128, bo = blockIdx.y * 64, b = blockIdx.z;
    int wm = (w >> 2) * 32, wn = (w & 3) * 32;
    int am = t >> 3, ak4 = t & 7;
    int am2 = (t + 256) >> 3;
    float C[2][4][4] = {};
    const float* Xb = g_t1 + (size_t)b * CF * NTOT;

    // prologue
    float4 Ar0 = *(const float4*)&A[(bo + am)*128 + ak4*4];
    float4 Ar1 = *(const float4*)&A[(bo + am2)*128 + ak4*4];
    #pragma unroll
    for (int i = 0; i < 4; i++) {
        int idx = t + i * 256; int k = idx >> 5, n4 = idx & 31;
        cpa16(&Bs[k*136 + n4*4], &Xb[(size_t)k*NTOT + bn + n4*4]);
    }
    CPA_COMMIT();
    *(float4*)&As[am*36 + ak4*4]  = f2tf4(Ar0);
    *(float4*)&As[am2*36 + ak4*4] = f2tf4(Ar1);
    CPA_WAIT0();
    __syncthreads();

    for (int it = 0; it < 4; it++) {
        int boff = (it & 1) * 4352;
        if (it < 3) {
            int kc = (it + 1) * 32;
            Ar0 = *(const float4*)&A[(bo + am)*128 + kc + ak4*4];
            Ar1 = *(const float4*)&A[(bo + am2)*128 + kc + ak4*4];
            int bn2 = ((it + 1) & 1) * 4352;
            #pragma unroll
            for (int i = 0; i < 4; i++) {
                int idx = t + i * 256; int k = idx >> 5, n4 = idx & 31;
                cpa16(&Bs[bn2 + k*136 + n4*4], &Xb[(size_t)(kc + k)*NTOT + bn + n4*4]);
            }
            CPA_COMMIT();
        }
        #pragma unroll
        for (int kk = 0; kk < 4; kk++) {
            uint32_t a[2][4], bb[4][2];
            #pragma unroll
            for (int mi = 0; mi < 2; mi++) {
                const float* ap = &As[(wm + mi*16 + g)*36 + kk*8 + q4];
                a[mi][0] = __float_as_uint(ap[0]);
                a[mi][1] = __float_as_uint(ap[8*36]);
                a[mi][2] = __float_as_uint(ap[4]);
                a[mi][3] = __float_as_uint(ap[8*36+4]);
            }
            #pragma unroll
            for (int ni = 0; ni < 4; ni++) {
                const float* bp = &Bs[boff + (kk*8 + q4)*136 + wn + ni*8 + g];
                bb[ni][0] = __float_as_uint(bp[0]);
                bb[ni][1] = __float_as_uint(bp[4*136]);
            }
            #pragma unroll
            for (int mi = 0; mi < 2; mi++)
                #pragma unroll
                for (int ni = 0; ni < 4; ni++) mma8(C[mi][ni], a[mi], bb[ni]);
        }
        __syncthreads();                 // all warps done reading As
        if (it < 3) {
            *(float4*)&As[am*36 + ak4*4]  = f2tf4(Ar0);
            *(float4*)&As[am2*36 + ak4*4] = f2tf4(Ar1);
        }
        CPA_WAIT0();
        __syncthreads();
    }
    #pragma unroll
    for (int mi = 0; mi < 2; mi++)
        #pragma unroll
        for (int ni = 0; ni < 4; ni++)
            #pragma unroll
            for (int cc = 0; cc < 4; cc++) {
                int o = bo + wm + mi*16 + g + (cc >> 1)*8;
                int n = bn + wn + ni*8 + 2*q4 + (cc & 1);
                float v = f2tf(C[mi][ni][cc]);
                if (o < 256)
                    g_q[((size_t)(b*4 + (o & 3))*NTOT + n)*64 + (o >> 2)] = v;
                else {
                    int c2 = o - 256;
                    g_fv[((size_t)(b*4 + (c2 & 3))*NTOT + n)*64 + (c2 >> 2)] = v;
                }
            }
}

// ------------------ map qv (also zero-fills monum/colsum) ------------------
__global__ __launch_bounds__(256) void k_map_qv(const float* __restrict__ w,
                                                const float* __restrict__ smap)
{
    __shared__ float Ws[32*68];
    __shared__ float Bs[64*132];
    int t = threadIdx.x;
    int bo = blockIdx.x * 32, b = blockIdx.y;
    int ol = (t >> 5) * 4;
    int ml = (t & 31) * 4;
    {
        int flat = (blockIdx.y * gridDim.x + blockIdx.x) * 256 + t;
        float4 z4 = make_float4(0.f, 0.f, 0.f, 0.f);
        #pragma unroll
        for (int i = 0; i < 8; i++)
            *(float4*)&g_monum[((size_t)flat * 8 + i) * 4] = z4;
        if (flat < BSZ * NHEAD * MTOT) g_colsum[flat] = 0.f;
    }
    #pragma unroll
    for (int i = 0; i < 2; i++) {
        int idx = t + i * 256; int o = idx >> 4, c4 = idx & 15;
        *(float4*)&Ws[o*68 + c4*4] = *(const float4*)&w[(bo + o)*64 + c4*4];
    }
    for (int mc = 0; mc < 512; mc += 128) {
        __syncthreads();
        #pragma unroll
        for (int i = 0; i < 8; i++) {
            int idx = t + i * 256; int c = idx >> 5, m4 = idx & 31;
            *(float4*)&Bs[c*132 + m4*4] =
                *(const float4*)&smap[((size_t)(b*64 + c))*512 + mc + m4*4];
        }
        __syncthreads();
        float acc[4][4] = {};
        #pragma unroll 8
        for (int c = 0; c < 64; c++) {
            float4 bv = *(const float4*)&Bs[c*132 + ml];
            #pragma unroll
            for (int oi = 0; oi < 4; oi++) {
                float wv = Ws[(ol + oi)*68 + c];
                acc[oi][0] += wv * bv.x; acc[oi][1] += wv * bv.y;
                acc[oi][2] += wv * bv.z; acc[oi][3] += wv * bv.w;
            }
        }
        #pragma unroll
        for (int oi = 0; oi < 4; oi++) {
            int oo = bo + ol + oi;
            float* dst; int oc;
            if (oo < 256) { dst = g_mq; oc = oo; } else { dst = g_mv; oc = oo - 256; }
            size_t base = ((size_t)(b*4 + (oc & 3))*512 + mc + ml)*64 + (oc >> 2);
            dst[base]       = f2tf(acc[oi][0]);
            dst[base + 64]  = f2tf(acc[oi][1]);
            dst[base + 128] = f2tf(acc[oi][2]);
            dst[base + 192] = f2tf(acc[oi][3]);
        }
    }
}

// ------------------ attention pass 1: static pipelined flash block ---------
// MQ double-buffered, MV single-buffered; wait_group discipline:
// commits: [MQ0][MV0] then per iter: MQ(mc+1) at top, MV(mc+1) at end.
__global__ __launch_bounds__(256, 2) void k_attn1()
{
    __shared__ float MQd[2*32*68];   // 4352
    __shared__ float MVd[32*72];     // 2304
    __shared__ float Es[128*36];     // 4608 (also Q staging scratch)
    __shared__ float srs[128];
    int t = threadIdx.x, w = t >> 5, l = t & 31, g = l >> 2, q4 = l & 3;
    int bh = blockIdx.y, b = bh >> 2, h = bh & 3;
    int nb = blockIdx.x * 128;
    int wn  = (w >> 1) * 32;
    int wsm = (w & 1) * 16;
    int wd  = (w & 1) * 32;

    if (t < 128) srs[t] = 0.f;
    const float* Qb  = g_q  + ((size_t)bh*NTOT + nb) * 64;
    const float* MQg = g_mq + (size_t)bh * MTOT * 64;
    const float* MVg = g_mv + (size_t)bh * MTOT * 64;

    // prologue commits: group(MQ0), group(MV0)
    #pragma unroll
    for (int i = 0; i < 2; i++) {
        int idx = t + i*256; int m = idx >> 4, d4 = idx & 15;
        cpa16(&MQd[m*68 + d4*4], MQg + (size_t)m*64 + d4*4);
    }
    CPA_COMMIT();
    #pragma unroll
    for (int i = 0; i < 2; i++) {
        int idx = t + i*256; int m = idx >> 4, d4 = idx & 15;
        cpa16(&MVd[m*72 + d4*4], MVg + (size_t)m*64 + d4*4);
    }
    CPA_COMMIT();

    // QF: 4 passes of 32 Q rows staged through Es scratch (overlaps prefetch)
    uint32_t QF[8][2][4];
    for (int p = 0; p < 4; p++) {
        __syncthreads();
        #pragma unroll
        for (int i = 0; i < 2; i++) {
            int idx = t + i*256; int n = idx >> 4, d4 = idx & 15;
            *(float4*)&Es[n*68 + d4*4] = *(const float4*)&Qb[(size_t)(p*32 + n)*64 + d4*4];
        }
        __syncthreads();
        if ((w >> 1) == p) {
            #pragma unroll
            for (int kk = 0; kk < 8; kk++)
                #pragma unroll
                for (int mi = 0; mi < 2; mi++) {
                    const float* ap = &Es[(mi*16 + g)*68 + kk*8 + q4];
                    QF[kk][mi][0] = __float_as_uint(ap[0]);
                    QF[kk][mi][1] = __float_as_uint(ap[8*68]);
                    QF[kk][mi][2] = __float_as_uint(ap[4]);
                    QF[kk][mi][3] = __float_as_uint(ap[8*68+4]);
                }
        }
    }

    float OF[2][4][4] = {};
    float rs[2][2] = {};

    for (int mc = 0; mc < 16; mc++) {
        int mqo = (mc & 1) * 2176;
        CPA_WAIT1();           // MQ(mc) done (MV(mc) may still be in flight)
        __syncthreads();
        if (mc < 15) {
            int mqn = ((mc + 1) & 1) * 2176;
            size_t go = (size_t)(mc + 1) * 32 * 64;
            #pragma unroll
            for (int i = 0; i < 2; i++) {
                int idx = t + i*256; int m = idx >> 4, d4 = idx & 15;
                cpa16(&MQd[mqn + m*68 + d4*4], MQg + go + (size_t)m*64 + d4*4);
            }
            CPA_COMMIT();
        }
        // S = Q @ MQ^T : warp tile 32n x 16m
        float Cs[2][2][4] = {};
        #pragma unroll
        for (int kk = 0; kk < 8; kk++) {
            uint32_t bb[2][2];
            #pragma unroll
            for (int ni = 0; ni < 2; ni++) {
                const float* bp = &MQd[mqo + (wsm + ni*8 + g)*68 + kk*8 + q4];
                bb[ni][0] = __float_as_uint(bp[0]);
                bb[ni][1] = __float_as_uint(bp[4]);
            }
            #pragma unroll
            for (int mi = 0; mi < 2; mi++)
                #pragma unroll
                for (int ni = 0; ni < 2; ni++) mma8(Cs[mi][ni], QF[kk][mi], bb[ni]);
        }
        // exp, rowsum, stage E
        #pragma unroll
        for (int mi = 0; mi < 2; mi++)
            #pragma unroll
            for (int ni = 0; ni < 2; ni++)
                #pragma unroll
                for (int cc = 0; cc < 4; cc++) {
                    float e = __expf(Cs[mi][ni][cc] * SCALE);
                    rs[mi][cc >> 1] += e;
                    Es[(wn + mi*16 + (cc>>1)*8 + g)*36 + wsm + ni*8 + 2*q4 + (cc&1)] = f2tf(e);
                }
        if (mc < 15) CPA_WAIT1(); else CPA_WAIT0();   // MV(mc) done
        __syncthreads();                              // E + MV visible
        // O += E @ MV : warp tile 32n x 32d
        #pragma unroll
        for (int kk = 0; kk < 4; kk++) {
            uint32_t a[2][4], bb[4][2];
            #pragma unroll
            for (int mi = 0; mi < 2; mi++) {
                const float* ap = &Es[(wn + mi*16 + g)*36 + kk*8 + q4];
                a[mi][0] = __float_as_uint(ap[0]);
                a[mi][1] = __float_as_uint(ap[8*36]);
                a[mi][2] = __float_as_uint(ap[4]);
                a[mi][3] = __float_as_uint(ap[8*36+4]);
            }
            #pragma unroll
            for (int ni = 0; ni < 4; ni++) {
                const float* bp = &MVd[(kk*8 + q4)*72 + wd + ni*8 + g];
                bb[ni][0] = __float_as_uint(bp[0]);
                bb[ni][1] = __float_as_uint(bp[4*72]);
            }
            #pragma unroll
            for (int mi = 0; mi < 2; mi++)
                #pragma unroll
                for (int ni = 0; ni < 4; ni++) mma8(OF[mi][ni], a[mi], bb[ni]);
        }
        __syncthreads();       // all warps done reading MVd/Es
        if (mc < 15) {
            size_t go = (size_t)(mc + 1) * 32 * 64;
            #pragma unroll
            for (int i = 0; i < 2; i++) {
                int idx = t + i*256; int m = idx >> 4, d4 = idx & 15;
                cpa16(&MVd[m*72 + d4*4], MVg + go + (size_t)m*64 + d4*4);
            }
            CPA_COMMIT();
        }
    }
    // rowsum reduce
    #pragma unroll
    for (int mi = 0; mi < 2; mi++)
        #pragma unroll
        for (int gh = 0; gh < 2; gh++) {
            float v = rs[mi][gh];
            v += __shfl_xor_sync(0xFFFFFFFFu, v, 1);
            v += __shfl_xor_sync(0xFFFFFFFFu, v, 2);
            if (q4 == 0) atomicAdd(&srs[wn + mi*16 + gh*8 + g], v);
        }
    __syncthreads();
    // normalize + direct store O to g_attnout [4d+h][n]
    float* ao = g_attnout + (size_t)b * INNER * NTOT + nb;
    #pragma unroll
    for (int mi = 0; mi < 2; mi++) {
        int n0 = wn + mi*16 + g;
        float inv0 = 1.f / srs[n0];
        float inv1 = 1.f / srs[n0 + 8];
        #pragma unroll
        for (int ni = 0; ni < 4; ni++) {
            int d0 = wd + ni*8 + 2*q4;
            ao[(size_t)(4*d0 + h)*NTOT + n0]         = OF[mi][ni][0] * inv0;
            ao[(size_t)(4*(d0+1) + h)*NTOT + n0]     = OF[mi][ni][1] * inv0;
            ao[(size_t)(4*d0 + h)*NTOT + n0 + 8]     = OF[mi][ni][2] * inv1;
            ao[(size_t)(4*(d0+1) + h)*NTOT + n0 + 8] = OF[mi][ni][3] * inv1;
        }
    }
}

// ------------------ attention pass 2: static pipelined recompute-E ---------
// Qs double-buffered, Vs single-buffered; same wait_group discipline.
__global__ __launch_bounds__(256, 2) void k_attn2()
{
    __shared__ float Qs[2*32*68];   // 4352
    __shared__ float Vs[32*72];     // 2304
    __shared__ float Es[128*36];    // 4608
    __shared__ float scs[128];
    int t = threadIdx.x, w = t >> 5, l = t & 31, g = l >> 2, q4 = l & 3;
    int bh = blockIdx.z; int mtile = blockIdx.y * 128; int nb = blockIdx.x * KLEN;
    int wm = (w >> 1) * 32, wsn = (w & 1) * 16, wd = (w & 1) * 32;
    const float* Qb = g_q  + (size_t)bh * NTOT * 64;
    const float* Vb = g_fv + (size_t)bh * NTOT * 64;
    if (t < 128) scs[t] = 0.f;

    // prologue commits: group(Q0), group(V0)
    #pragma unroll
    for (int i = 0; i < 2; i++) {
        int idx = t + i*256; int n = idx >> 4, d4 = idx & 15;
        cpa16(&Qs[n*68 + d4*4], Qb + (size_t)(nb + n)*64 + d4*4);
    }
    CPA_COMMIT();
    #pragma unroll
    for (int i = 0; i < 2; i++) {
        int idx = t + i*256; int n = idx >> 4, d4 = idx & 15;
        cpa16(&Vs[n*72 + d4*4], Vb + (size_t)(nb + n)*64 + d4*4);
    }
    CPA_COMMIT();

    // AF loads overlap the prefetch
    uint32_t AF[8][2][4];
    const float* MQb = g_mq + ((size_t)bh * MTOT + mtile) * 64;
    #pragma unroll
    for (int kk = 0; kk < 8; kk++)
        #pragma unroll
        for (int mi = 0; mi < 2; mi++) {
            const float* p = MQb + (wm + mi*16 + g)*64 + kk*8 + q4;
            AF[kk][mi][0] = __float_as_uint(p[0]);
            AF[kk][mi][1] = __float_as_uint(p[8*64]);
            AF[kk][mi][2] = __float_as_uint(p[4]);
            AF[kk][mi][3] = __float_as_uint(p[8*64+4]);
        }
    float C[2][4][4] = {};
    float cs[2][2] = {};

    for (int ci = 0; ci < 48; ci++) {
        int qo = (ci & 1) * 2176;
        CPA_WAIT1();           // Q(ci) done
        __syncthreads();
        if (ci < 47) {
            int qn = ((ci + 1) & 1) * 2176;
            size_t base = (size_t)(nb + (ci + 1) * 32);
            #pragma unroll
            for (int i = 0; i < 2; i++) {
                int idx = t + i*256; int n = idx >> 4, d4 = idx & 15;
                cpa16(&Qs[qn + n*68 + d4*4], Qb + (base + n)*64 + d4*4);
            }
            CPA_COMMIT();
        }
        // S = MQ @ Q^T
        float Cs[2][2][4] = {};
        #pragma unroll
        for (int kk = 0; kk < 8; kk++) {
            uint32_t bb[2][2];
            #pragma unroll
            for (int ni = 0; ni < 2; ni++) {
                const float* bp = &Qs[qo + (wsn + ni*8 + g)*68 + kk*8 + q4];
                bb[ni][0] = __float_as_uint(bp[0]);
                bb[ni][1] = __float_as_uint(bp[4]);
            }
            #pragma unroll
            for (int mi = 0; mi < 2; mi++)
                #pragma unroll
                for (int ni = 0; ni < 2; ni++) mma8(Cs[mi][ni], AF[kk][mi], bb[ni]);
        }
        #pragma unroll
        for (int mi = 0; mi < 2; mi++)
            #pragma unroll
            for (int ni = 0; ni < 2; ni++)
                #pragma unroll
                for (int cc = 0; cc < 4; cc++) {
                    float e = __expf(Cs[mi][ni][cc] * SCALE);
                    cs[mi][cc >> 1] += e;
                    Es[(wm + mi*16 + (cc>>1)*8 + g)*36 + wsn + ni*8 + 2*q4 + (cc&1)] = f2tf(e);
                }
        if (ci < 47) CPA_WAIT1(); else CPA_WAIT0();   // V(ci) done
        __syncthreads();                              // E + V visible
        // monum += E @ V
        #pragma unroll
        for (int kk = 0; kk < 4; kk++) {
            uint32_t a[2][4], bb[4][2];
            #pragma unroll
            for (int mi = 0; mi < 2; mi++) {
                const float* ap = &Es[(wm + mi*16 + g)*36 + kk*8 + q4];
                a[mi][0] = __float_as_uint(ap[0]);
                a[mi][1] = __float_as_uint(ap[8*36]);
                a[mi][2] = __float_as_uint(ap[4]);
                a[mi][3] = __float_as_uint(ap[8*36+4]);
            }
            #pragma unroll
            for (int ni = 0; ni < 4; ni++) {
                const float* bp = &Vs[(kk*8 + q4)*72 + wd + ni*8 + g];
                bb[ni][0] = __float_as_uint(bp[0]);
                bb[ni][1] = __float_as_uint(bp[4*72]);
            }
            #pragma unroll
            for (int mi = 0; mi < 2; mi++)
                #pragma unroll
                for (int ni = 0; ni < 4; ni++) mma8(C[mi][ni], a[mi], bb[ni]);
        }
        __syncthreads();       // all warps done reading Vs/Es
        if (ci < 47) {
            size_t base = (size_t)(nb + (ci + 1) * 32);
            #pragma unroll
            for (int i = 0; i < 2; i++) {
                int idx = t + i*256; int n = idx >> 4, d4 = idx & 15;
                cpa16(&Vs[n*72 + d4*4], Vb + (base + n)*64 + d4*4);
            }
            CPA_COMMIT();
        }
    }
    #pragma unroll
    for (int mi = 0; mi < 2; mi++)
        #pragma unroll
        for (int gh = 0; gh < 2; gh++) {
            float v = cs[mi][gh];
            v += __shfl_xor_sync(0xFFFFFFFFu, v, 1);
            v += __shfl_xor_sync(0xFFFFFFFFu, v, 2);
            if (q4 == 0) atomicAdd(&scs[wm + mi*16 + gh*8 + g], v);
        }
    __syncthreads();
    if (t < 128) atomicAdd(&g_colsum[(size_t)bh*MTOT + mtile + t], scs[t]);
    #pragma unroll
    for (int mi = 0; mi < 2; mi++)
        #pragma unroll
        for (int ni = 0; ni < 4; ni++)
            #pragma unroll
            for (int cc = 0; cc < 4; cc++) {
                int m = mtile + wm + mi*16 + g + (cc >> 1)*8;
                int d = wd + ni*8 + 2*q4 + (cc & 1);
                atomicAdd(&g_monum[((size_t)bh*MTOT + m)*64 + d], C[mi][ni][cc]);
            }
}

// ------------------ finalize map_out (float4 over d) ------------------
__global__ void k_mapout(const float* __restrict__ w, float* __restrict__ outp)
{
    int gid = blockIdx.x * 256 + threadIdx.x;
    int m = gid & 511;
    int o = (gid >> 9) & 63;
    int b = gid >> 15;
    float inv[4];
    #pragma unroll
    for (int hh = 0; hh < 4; hh++)
        inv[hh] = 1.f / g_colsum[(size_t)(b * 4 + hh) * 512 + m];
    const float* wo = w + o * 256;
    float s = 0.f;
    #pragma unroll 4
    for (int d4 = 0; d4 < 16; d4++) {
        #pragma unroll
        for (int hh = 0; hh < 4; hh++) {
            float4 mv = *(const float4*)&g_monum[((size_t)(b*4 + hh)*512 + m)*64 + d4*4];
            s += (wo[16*d4 + hh]      * mv.x +
                  wo[16*d4 + 4 + hh]  * mv.y +
                  wo[16*d4 + 8 + hh]  * mv.z +
                  wo[16*d4 + 12 + hh] * mv.w) * inv[hh];
        }
    }
    outp[(size_t)FEAT_OUT_ELEMS + ((size_t)(b * 64 + o)) * 512 + m] = s;
}

// ------------------ pointwise out GEMM (pipelined, static smem) ------------
__global__ __launch_bounds__(256) void k_pw_out(const float* __restrict__ A,
                                                float* __restrict__ outp)
{
    __shared__ float As[64*36];
    __shared__ float Bs[2*32*136];
    int t = threadIdx.x, w = t >> 5, l = t & 31, g = l >> 2, q4 = l & 3;
    int bn = blockIdx.x * 128, bo = blockIdx.y * 64, b = blockIdx.z;
    int wm = (w >> 2) * 32, wn = (w & 3) * 32;
    int am = t >> 3, ak4 = t & 7;
    int am2 = (t + 256) >> 3;
    float C[2][4][4] = {};
    const float* Xb = g_dw2 + (size_t)b * INNER * NTOT;

    float4 Ar0 = *(const float4*)&A[(bo + am)*256 + ak4*4];
    float4 Ar1 = *(const float4*)&A[(bo + am2)*256 + ak4*4];
    #pragma unroll
    for (int i = 0; i < 4; i++) {
        int idx = t + i * 256; int k = idx >> 5, n4 = idx & 31;
        cpa16(&Bs[k*136 + n4*4], &Xb[(size_t)k*NTOT + bn + n4*4]);
    }
    CPA_COMMIT();
    *(float4*)&As[am*36 + ak4*4]  = f2tf4(Ar0);
    *(float4*)&As[am2*36 + ak4*4] = f2tf4(Ar1);
    CPA_WAIT0();
    __syncthreads();

    for (int it = 0; it < 8; it++) {
        int boff = (it & 1) * 4352;
        if (it < 7) {
            int kc = (it + 1) * 32;
            Ar0 = *(const float4*)&A[(bo + am)*256 + kc + ak4*4];
            Ar1 = *(const float4*)&A[(bo + am2)*256 + kc + ak4*4];
            int bn2 = ((it + 1) & 1) * 4352;
            #pragma unroll
            for (int i = 0; i < 4; i++) {
                int idx = t + i * 256; int k = idx >> 5, n4 = idx & 31;
                cpa16(&Bs[bn2 + k*136 + n4*4], &Xb[(size_t)(kc + k)*NTOT + bn + n4*4]);
            }
            CPA_COMMIT();
        }
        #pragma unroll
        for (int kk = 0; kk < 4; kk++) {
            uint32_t a[2][4], bb[4][2];
            #pragma unroll
            for (int mi = 0; mi < 2; mi++) {
                const float* ap = &As[(wm + mi*16 + g)*36 + kk*8 + q4];
                a[mi][0] = __float_as_uint(ap[0]);
                a[mi][1] = __float_as_uint(ap[8*36]);
                a[mi][2] = __float_as_uint(ap[4]);
                a[mi][3] = __float_as_uint(ap[8*36+4]);
            }
            #pragma unroll
            for (int ni = 0; ni < 4; ni++) {
                const float* bp = &Bs[boff + (kk*8 + q4)*136 + wn + ni*8 + g];
                bb[ni][0] = __float_as_uint(bp[0]);
                bb[ni][1] = __float_as_uint(bp[4*136]);
            }
            #pragma unroll
            for (int mi = 0; mi < 2; mi++)
                #pragma unroll
                for (int ni = 0; ni < 4; ni++) mma8(C[mi][ni], a[mi], bb[ni]);
        }
        __syncthreads();
        if (it < 7) {
            *(float4*)&As[am*36 + ak4*4]  = f2tf4(Ar0);
            *(float4*)&As[am2*36 + ak4*4] = f2tf4(Ar1);
        }
        CPA_WAIT0();
        __syncthreads();
    }
    #pragma unroll
    for (int mi = 0; mi < 2; mi++)
        #pragma unroll
        for (int ni = 0; ni < 4; ni++)
            #pragma unroll
            for (int cc = 0; cc < 4; cc++) {
                int o = bo + wm + mi*16 + g + (cc >> 1)*8;
                int n = bn + wn + ni*8 + 2*q4 + (cc & 1);
                outp[((size_t)(b * 128 + o)) * NTOT + n] = C[mi][ni][cc];
            }
}

// ------------------ launch ------------------
extern "C" void kernel_launch(void* const* d_in, const int* in_sizes, int n_in,
                              void* d_out, int out_size)
{
    const float* feat    = (const float*)d_in[0];
    const float* smap    = (const float*)d_in[1];
    const float* fqv_dw  = (const float*)d_in[2];
    const float* fqv_pw  = (const float*)d_in[3];
    const float* fout_dw = (const float*)d_in[4];
    const float* fout_pw = (const float*)d_in[5];
    const float* mqv_w   = (const float*)d_in[6];
    const float* mout_w  = (const float*)d_in[7];
    float* outp = (float*)d_out;

    k_dwconv1<<<dim3(14, 128, 2), 256>>>(feat, fqv_dw);
    k_map_qv <<<dim3(16, 2), 256>>>(mqv_w, smap);       // also zeros monum/colsum
    k_pw_qv  <<<dim3(108, 8, 2), 256>>>(fqv_pw);
    k_attn1  <<<dim3(108, 8), 256>>>();                 // launch #4 -> ncu window
    k_attn2  <<<dim3(KSPLIT, 4, 8), 256>>>();
    k_dwconv2<<<dim3(14, 256, 2), 256>>>(fout_dw);
    k_mapout <<<256, 256>>>(mout_w, outp);
    k_pw_out <<<dim3(108, 2, 2), 256>>>(fout_pw, outp);
}

// round 12
// speedup vs baseline: 3.4868x; 1.0163x over previous
#include <cuda_runtime.h>
#include <math.h>
#include <stdint.h>

#define BSZ   2
#define CF    128
#define NTOT  13824      // 24^3
#define MTOT  512        // 8^3
#define NHEAD 4
#define DHEAD 64
#define INNER 256
#define SCALE 0.125f     // 64^-0.5
#define FEAT_OUT_ELEMS 3538944   // 2*128*13824
#define KSPLIT 9
#define KLEN   1536      // 13824/9

// ------------------ scratch (device globals; no allocs) ------------------
__device__ __align__(16) float g_t1   [BSZ*CF*NTOT];            // dwconv1 out (tf32 bits)
__device__ __align__(16) float g_q    [BSZ*NHEAD*NTOT*DHEAD];   // feat_q (tf32 bits)
__device__ __align__(16) float g_fv   [BSZ*NHEAD*NTOT*DHEAD];   // feat_v (tf32 bits)
__device__ __align__(16) float g_mq   [BSZ*NHEAD*MTOT*DHEAD];   // map_q  (tf32 bits)
__device__ __align__(16) float g_mv   [BSZ*NHEAD*MTOT*DHEAD];   // map_v  (tf32 bits)
__device__ __align__(16) float g_attnout[BSZ*INNER*NTOT];       // feat attn out (fp32)
__device__ __align__(16) float g_dw2  [BSZ*INNER*NTOT];         // dwconv2 out (tf32 bits)
__device__ __align__(16) float g_monum[BSZ*NHEAD*MTOT*DHEAD];
__device__ __align__(16) float g_colsum[BSZ*NHEAD*MTOT];

// ------------------ tf32 mma helpers ------------------
__device__ __forceinline__ uint32_t f2t(float x){
    uint32_t r; asm("cvt.rna.tf32.f32 %0,%1;":"=r"(r):"f"(x)); return r;
}
__device__ __forceinline__ float f2tf(float x){ return __uint_as_float(f2t(x)); }
__device__ __forceinline__ float4 f2tf4(float4 v){
    v.x = f2tf(v.x); v.y = f2tf(v.y); v.z = f2tf(v.z); v.w = f2tf(v.w); return v;
}

__device__ __forceinline__ void mma8(float* c, const uint32_t* a, const uint32_t* b){
    asm volatile("mma.sync.aligned.m16n8k8.row.col.f32.tf32.tf32.f32 "
        "{%0,%1,%2,%3},{%4,%5,%6,%7},{%8,%9},{%0,%1,%2,%3};"
        : "+f"(c[0]),"+f"(c[1]),"+f"(c[2]),"+f"(c[3])
        : "r"(a[0]),"r"(a[1]),"r"(a[2]),"r"(a[3]),"r"(b[0]),"r"(b[1]));
}

// ------------------ cp.async helpers ------------------
__device__ __forceinline__ void cpa16(void* smem, const void* g){
    uint32_t s = (uint32_t)__cvta_generic_to_shared(smem);
    asm volatile("cp.async.ca.shared.global [%0], [%1], 16;" :: "r"(s), "l"(g));
}
#define CPA_COMMIT() asm volatile("cp.async.commit_group;")
#define CPA_WAIT0()  asm volatile("cp.async.wait_group 0;" ::: "memory")
#define CPA_WAIT1()  asm volatile("cp.async.wait_group 1;" ::: "memory")
#define CPA_WAIT2()  asm volatile("cp.async.wait_group 2;" ::: "memory")

// ------------------ depthwise 3x3x3, SAME, x-vectorized; output tf32-rounded
__device__ __forceinline__ void dw_body_v4(const float* __restrict__ in,
                                           const float* __restrict__ w,
                                           float* __restrict__ out, int C)
{
    __shared__ float ws[27];
    int t = threadIdx.x;
    int c = blockIdx.y, b = blockIdx.z;
    if (t < 27) ws[t] = w[c * 27 + t];
    __syncthreads();
    int idx = blockIdx.x * 256 + t;          // over 24*24*6 = 3456
    if (idx >= 3456) return;
    int x4 = (idx % 6) * 4;
    int y  = (idx / 6) % 24;
    int z  = idx / 144;
    const float* ip = in + ((size_t)(b * C + c)) * NTOT;
    float acc0 = 0.f, acc1 = 0.f, acc2 = 0.f, acc3 = 0.f;
    #pragma unroll
    for (int dz = -1; dz <= 1; dz++) {
        int zz = z + dz; if (zz < 0 || zz >= 24) continue;
        #pragma unroll
        for (int dy = -1; dy <= 1; dy++) {
            int yy = y + dy; if (yy < 0 || yy >= 24) continue;
            const float* row = ip + (zz * 24 + yy) * 24;
            float4 mid = *(const float4*)(row + x4);
            float left  = (x4 > 0)      ? row[x4 - 1] : 0.f;
            float right = (x4 + 4 < 24) ? row[x4 + 4] : 0.f;
            const float* wr = ws + (dz + 1) * 9 + (dy + 1) * 3;
            float w0 = wr[0], w1 = wr[1], w2 = wr[2];
            acc0 += w0 * left  + w1 * mid.x + w2 * mid.y;
            acc1 += w0 * mid.x + w1 * mid.y + w2 * mid.z;
            acc2 += w0 * mid.y + w1 * mid.z + w2 * mid.w;
            acc3 += w0 * mid.z + w1 * mid.w + w2 * right;
        }
    }
    float4 o = f2tf4(make_float4(acc0, acc1, acc2, acc3));
    *(float4*)(out + ((size_t)(b * C + c)) * NTOT + (z * 24 + y) * 24 + x4) = o;
}

__global__ void k_dwconv1(const float* __restrict__ feat, const float* __restrict__ w)
{   dw_body_v4(feat, w, g_t1, CF); }

__global__ void k_dwconv2(const float* __restrict__ w)
{   dw_body_v4(g_attnout, w, g_dw2, INNER); }

// ------------------ pointwise qv GEMM (pipelined, static smem) -------------
__global__ __launch_bounds__(256) void k_pw_qv(const float* __restrict__ A)
{
    __shared__ float As[64*36];
    __shared__ float Bs[2*32*136];
    int t = threadIdx.x, w = t >> 5, l = t & 31, g = l >> 2, q4 = l & 3;
    int bn = blockIdx.x * 128, bo = blockIdx.y * 64, b = blockIdx.z;
    int wm = (w >> 2) * 32, wn = (w & 3) * 32;
    int am = t >> 3, ak4 = t & 7;
    int am2 = (t + 256) >> 3;
    float C[2][4][4] = {};
    const float* Xb = g_t1 + (size_t)b * CF * NTOT;

    float4 Ar0 = *(const float4*)&A[(bo + am)*128 + ak4*4];
    float4 Ar1 = *(const float4*)&A[(bo + am2)*128 + ak4*4];
    #pragma unroll
    for (int i = 0; i < 4; i++) {
        int idx = t + i * 256; int k = idx >> 5, n4 = idx & 31;
        cpa16(&Bs[k*136 + n4*4], &Xb[(size_t)k*NTOT + bn + n4*4]);
    }
    CPA_COMMIT();
    *(float4*)&As[am*36 + ak4*4]  = f2tf4(Ar0);
    *(float4*)&As[am2*36 + ak4*4] = f2tf4(Ar1);
    CPA_WAIT0();
    __syncthreads();

    for (int it = 0; it < 4; it++) {
        int boff = (it & 1) * 4352;
        if (it < 3) {
            int kc = (it + 1) * 32;
            Ar0 = *(const float4*)&A[(bo + am)*128 + kc + ak4*4];
            Ar1 = *(const float4*)&A[(bo + am2)*128 + kc + ak4*4];
            int bn2 = ((it + 1) & 1) * 4352;
            #pragma unroll
            for (int i = 0; i < 4; i++) {
                int idx = t + i * 256; int k = idx >> 5, n4 = idx & 31;
                cpa16(&Bs[bn2 + k*136 + n4*4], &Xb[(size_t)(kc + k)*NTOT + bn + n4*4]);
            }
            CPA_COMMIT();
        }
        #pragma unroll
        for (int kk = 0; kk < 4; kk++) {
            uint32_t a[2][4], bb[4][2];
            #pragma unroll
            for (int mi = 0; mi < 2; mi++) {
                const float* ap = &As[(wm + mi*16 + g)*36 + kk*8 + q4];
                a[mi][0] = __float_as_uint(ap[0]);
                a[mi][1] = __float_as_uint(ap[8*36]);
                a[mi][2] = __float_as_uint(ap[4]);
                a[mi][3] = __float_as_uint(ap[8*36+4]);
            }
            #pragma unroll
            for (int ni = 0; ni < 4; ni++) {
                const float* bp = &Bs[boff + (kk*8 + q4)*136 + wn + ni*8 + g];
                bb[ni][0] = __float_as_uint(bp[0]);
                bb[ni][1] = __float_as_uint(bp[4*136]);
            }
            #pragma unroll
            for (int mi = 0; mi < 2; mi++)
                #pragma unroll
                for (int ni = 0; ni < 4; ni++) mma8(C[mi][ni], a[mi], bb[ni]);
        }
        __syncthreads();
        if (it < 3) {
            *(float4*)&As[am*36 + ak4*4]  = f2tf4(Ar0);
            *(float4*)&As[am2*36 + ak4*4] = f2tf4(Ar1);
        }
        CPA_WAIT0();
        __syncthreads();
    }
    #pragma unroll
    for (int mi = 0; mi < 2; mi++)
        #pragma unroll
        for (int ni = 0; ni < 4; ni++)
            #pragma unroll
            for (int cc = 0; cc < 4; cc++) {
                int o = bo + wm + mi*16 + g + (cc >> 1)*8;
                int n = bn + wn + ni*8 + 2*q4 + (cc & 1);
                float v = f2tf(C[mi][ni][cc]);
                if (o < 256)
                    g_q[((size_t)(b*4 + (o & 3))*NTOT + n)*64 + (o >> 2)] = v;
                else {
                    int c2 = o - 256;
                    g_fv[((size_t)(b*4 + (c2 & 3))*NTOT + n)*64 + (c2 >> 2)] = v;
                }
            }
}

// ------------------ map qv (also zero-fills monum/colsum) ------------------
__global__ __launch_bounds__(256) void k_map_qv(const float* __restrict__ w,
                                                const float* __restrict__ smap)
{
    __shared__ float Ws[32*68];
    __shared__ float Bs[64*132];
    int t = threadIdx.x;
    int bo = blockIdx.x * 32, b = blockIdx.y;
    int ol = (t >> 5) * 4;
    int ml = (t & 31) * 4;
    {
        int flat = (blockIdx.y * gridDim.x + blockIdx.x) * 256 + t;
        float4 z4 = make_float4(0.f, 0.f, 0.f, 0.f);
        #pragma unroll
        for (int i = 0; i < 8; i++)
            *(float4*)&g_monum[((size_t)flat * 8 + i) * 4] = z4;
        if (flat < BSZ * NHEAD * MTOT) g_colsum[flat] = 0.f;
    }
    #pragma unroll
    for (int i = 0; i < 2; i++) {
        int idx = t + i * 256; int o = idx >> 4, c4 = idx & 15;
        *(float4*)&Ws[o*68 + c4*4] = *(const float4*)&w[(bo + o)*64 + c4*4];
    }
    for (int mc = 0; mc < 512; mc += 128) {
        __syncthreads();
        #pragma unroll
        for (int i = 0; i < 8; i++) {
            int idx = t + i * 256; int c = idx >> 5, m4 = idx & 31;
            *(float4*)&Bs[c*132 + m4*4] =
                *(const float4*)&smap[((size_t)(b*64 + c))*512 + mc + m4*4];
        }
        __syncthreads();
        float acc[4][4] = {};
        #pragma unroll 8
        for (int c = 0; c < 64; c++) {
            float4 bv = *(const float4*)&Bs[c*132 + ml];
            #pragma unroll
            for (int oi = 0; oi < 4; oi++) {
                float wv = Ws[(ol + oi)*68 + c];
                acc[oi][0] += wv * bv.x; acc[oi][1] += wv * bv.y;
                acc[oi][2] += wv * bv.z; acc[oi][3] += wv * bv.w;
            }
        }
        #pragma unroll
        for (int oi = 0; oi < 4; oi++) {
            int oo = bo + ol + oi;
            float* dst; int oc;
            if (oo < 256) { dst = g_mq; oc = oo; } else { dst = g_mv; oc = oo - 256; }
            size_t base = ((size_t)(b*4 + (oc & 3))*512 + mc + ml)*64 + (oc >> 2);
            dst[base]       = f2tf(acc[oi][0]);
            dst[base + 64]  = f2tf(acc[oi][1]);
            dst[base + 128] = f2tf(acc[oi][2]);
            dst[base + 192] = f2tf(acc[oi][3]);
        }
    }
}

// ------------------ attention pass 1: 2-sync pipelined flash block ---------
// MQ double-buffered (2-chunk distance), MV single-buffered.
// Invariant entering chunk mc: in-flight groups = [MV(mc), MQ(mc+1)].
__global__ __launch_bounds__(256, 2) void k_attn1()
{
    __shared__ float MQd[2*32*68];   // 4352
    __shared__ float MVd[32*72];     // 2304
    __shared__ float Es[128*36];     // 4608 (also Q staging scratch)
    __shared__ float srs[128];
    int t = threadIdx.x, w = t >> 5, l = t & 31, g = l >> 2, q4 = l & 3;
    int bh = blockIdx.y, b = bh >> 2, h = bh & 3;
    int nb = blockIdx.x * 128;
    int wn  = (w >> 1) * 32;
    int wsm = (w & 1) * 16;
    int wd  = (w & 1) * 32;

    if (t < 128) srs[t] = 0.f;
    const float* Qb  = g_q  + ((size_t)bh*NTOT + nb) * 64;
    const float* MQg = g_mq + (size_t)bh * MTOT * 64;
    const float* MVg = g_mv + (size_t)bh * MTOT * 64;

    // prologue: C_MQ(0), C_MV(0), C_MQ(1)
    #pragma unroll
    for (int i = 0; i < 2; i++) {
        int idx = t + i*256; int m = idx >> 4, d4 = idx & 15;
        cpa16(&MQd[m*68 + d4*4], MQg + (size_t)m*64 + d4*4);
    }
    CPA_COMMIT();
    #pragma unroll
    for (int i = 0; i < 2; i++) {
        int idx = t + i*256; int m = idx >> 4, d4 = idx & 15;
        cpa16(&MVd[m*72 + d4*4], MVg + (size_t)m*64 + d4*4);
    }
    CPA_COMMIT();
    #pragma unroll
    for (int i = 0; i < 2; i++) {
        int idx = t + i*256; int m = idx >> 4, d4 = idx & 15;
        cpa16(&MQd[2176 + m*68 + d4*4], MQg + 2048 + (size_t)m*64 + d4*4);
    }
    CPA_COMMIT();

    // QF: 4 passes of 32 Q rows staged through Es scratch (overlaps prefetch)
    uint32_t QF[8][2][4];
    for (int p = 0; p < 4; p++) {
        __syncthreads();
        #pragma unroll
        for (int i = 0; i < 2; i++) {
            int idx = t + i*256; int n = idx >> 4, d4 = idx & 15;
            *(float4*)&Es[n*68 + d4*4] = *(const float4*)&Qb[(size_t)(p*32 + n)*64 + d4*4];
        }
        __syncthreads();
        if ((w >> 1) == p) {
            #pragma unroll
            for (int kk = 0; kk < 8; kk++)
                #pragma unroll
                for (int mi = 0; mi < 2; mi++) {
                    const float* ap = &Es[(mi*16 + g)*68 + kk*8 + q4];
                    QF[kk][mi][0] = __float_as_uint(ap[0]);
                    QF[kk][mi][1] = __float_as_uint(ap[8*68]);
                    QF[kk][mi][2] = __float_as_uint(ap[4]);
                    QF[kk][mi][3] = __float_as_uint(ap[8*68+4]);
                }
        }
    }
    CPA_WAIT2();       // retire MQ(0); leaves [MV(0), MQ(1)]
    __syncthreads();

    float OF[2][4][4] = {};
    float rs[2][2] = {};

    for (int mc = 0; mc < 16; mc++) {
        int mqo = (mc & 1) * 2176;
        // S = Q @ MQ^T : warp tile 32n x 16m
        float Cs[2][2][4] = {};
        #pragma unroll
        for (int kk = 0; kk < 8; kk++) {
            uint32_t bb[2][2];
            #pragma unroll
            for (int ni = 0; ni < 2; ni++) {
                const float* bp = &MQd[mqo + (wsm + ni*8 + g)*68 + kk*8 + q4];
                bb[ni][0] = __float_as_uint(bp[0]);
                bb[ni][1] = __float_as_uint(bp[4]);
            }
            #pragma unroll
            for (int mi = 0; mi < 2; mi++)
                #pragma unroll
                for (int ni = 0; ni < 2; ni++) mma8(Cs[mi][ni], QF[kk][mi], bb[ni]);
        }
        // exp, rowsum, stage E
        #pragma unroll
        for (int mi = 0; mi < 2; mi++)
            #pragma unroll
            for (int ni = 0; ni < 2; ni++)
                #pragma unroll
                for (int cc = 0; cc < 4; cc++) {
                    float e = __expf(Cs[mi][ni][cc] * SCALE);
                    rs[mi][cc >> 1] += e;
                    Es[(wn + mi*16 + (cc>>1)*8 + g)*36 + wsm + ni*8 + 2*q4 + (cc&1)] = f2tf(e);
                }
        if (mc == 15) CPA_WAIT0(); else CPA_WAIT1();   // retire MV(mc)
        __syncthreads();                               // E + MV visible
        // O += E @ MV : warp tile 32n x 32d
        #pragma unroll
        for (int kk = 0; kk < 4; kk++) {
            uint32_t a[2][4], bb[4][2];
            #pragma unroll
            for (int mi = 0; mi < 2; mi++) {
                const float* ap = &Es[(wn + mi*16 + g)*36 + kk*8 + q4];
                a[mi][0] = __float_as_uint(ap[0]);
                a[mi][1] = __float_as_uint(ap[8*36]);
                a[mi][2] = __float_as_uint(ap[4]);
                a[mi][3] = __float_as_uint(ap[8*36+4]);
            }
            #pragma unroll
            for (int ni = 0; ni < 4; ni++) {
                const float* bp = &MVd[(kk*8 + q4)*72 + wd + ni*8 + g];
                bb[ni][0] = __float_as_uint(bp[0]);
                bb[ni][1] = __float_as_uint(bp[4*72]);
            }
            #pragma unroll
            for (int mi = 0; mi < 2; mi++)
                #pragma unroll
                for (int ni = 0; ni < 4; ni++) mma8(OF[mi][ni], a[mi], bb[ni]);
        }
        __syncthreads();       // readers of MVd/Es/MQd done
        if (mc < 15) {
            size_t go = (size_t)(mc + 1) * 32 * 64;
            #pragma unroll
            for (int i = 0; i < 2; i++) {
                int idx = t + i*256; int m = idx >> 4, d4 = idx & 15;
                cpa16(&MVd[m*72 + d4*4], MVg + go + (size_t)m*64 + d4*4);
            }
            CPA_COMMIT();                     // C_MV(mc+1)
            if (mc < 14) {
                int mqn = (mc & 1) * 2176;    // buf (mc+2)&1 == mc&1
                size_t go2 = (size_t)(mc + 2) * 32 * 64;
                #pragma unroll
                for (int i = 0; i < 2; i++) {
                    int idx = t + i*256; int m = idx >> 4, d4 = idx & 15;
                    cpa16(&MQd[mqn + m*68 + d4*4], MQg + go2 + (size_t)m*64 + d4*4);
                }
                CPA_COMMIT();                 // C_MQ(mc+2)
                CPA_WAIT2();                  // retire MQ(mc+1)
            } else {
                CPA_WAIT1();                  // mc==14: retire MQ(15)
            }
            __syncthreads();                  // MQ(mc+1) visible
        }
    }
    // rowsum reduce
    #pragma unroll
    for (int mi = 0; mi < 2; mi++)
        #pragma unroll
        for (int gh = 0; gh < 2; gh++) {
            float v = rs[mi][gh];
            v += __shfl_xor_sync(0xFFFFFFFFu, v, 1);
            v += __shfl_xor_sync(0xFFFFFFFFu, v, 2);
            if (q4 == 0) atomicAdd(&srs[wn + mi*16 + gh*8 + g], v);
        }
    __syncthreads();
    // normalize + direct store O to g_attnout [4d+h][n]
    float* ao = g_attnout + (size_t)b * INNER * NTOT + nb;
    #pragma unroll
    for (int mi = 0; mi < 2; mi++) {
        int n0 = wn + mi*16 + g;
        float inv0 = 1.f / srs[n0];
        float inv1 = 1.f / srs[n0 + 8];
        #pragma unroll
        for (int ni = 0; ni < 4; ni++) {
            int d0 = wd + ni*8 + 2*q4;
            ao[(size_t)(4*d0 + h)*NTOT + n0]         = OF[mi][ni][0] * inv0;
            ao[(size_t)(4*(d0+1) + h)*NTOT + n0]     = OF[mi][ni][1] * inv0;
            ao[(size_t)(4*d0 + h)*NTOT + n0 + 8]     = OF[mi][ni][2] * inv1;
            ao[(size_t)(4*(d0+1) + h)*NTOT + n0 + 8] = OF[mi][ni][3] * inv1;
        }
    }
}

// ------------------ attention pass 2: 2-sync pipelined recompute-E ---------
// Qs double-buffered (2-chunk distance), Vs single-buffered.
__global__ __launch_bounds__(256, 2) void k_attn2()
{
    __shared__ float Qs[2*32*68];
    __shared__ float Vs[32*72];
    __shared__ float Es[128*36];
    __shared__ float scs[128];
    int t = threadIdx.x, w = t >> 5, l = t & 31, g = l >> 2, q4 = l & 3;
    int bh = blockIdx.z; int mtile = blockIdx.y * 128; int nb = blockIdx.x * KLEN;
    int wm = (w >> 1) * 32, wsn = (w & 1) * 16, wd = (w & 1) * 32;
    const float* Qb = g_q  + (size_t)bh * NTOT * 64;
    const float* Vb = g_fv + (size_t)bh * NTOT * 64;
    if (t < 128) scs[t] = 0.f;

    // prologue: C_Q(0), C_V(0), C_Q(1)
    #pragma unroll
    for (int i = 0; i < 2; i++) {
        int idx = t + i*256; int n = idx >> 4, d4 = idx & 15;
        cpa16(&Qs[n*68 + d4*4], Qb + (size_t)(nb + n)*64 + d4*4);
    }
    CPA_COMMIT();
    #pragma unroll
    for (int i = 0; i < 2; i++) {
        int idx = t + i*256; int n = idx >> 4, d4 = idx & 15;
        cpa16(&Vs[n*72 + d4*4], Vb + (size_t)(nb + n)*64 + d4*4);
    }
    CPA_COMMIT();
    #pragma unroll
    for (int i = 0; i < 2; i++) {
        int idx = t + i*256; int n = idx >> 4, d4 = idx & 15;
        cpa16(&Qs[2176 + n*68 + d4*4], Qb + (size_t)(nb + 32 + n)*64 + d4*4);
    }
    CPA_COMMIT();

    // AF loads overlap the prefetch
    uint32_t AF[8][2][4];
    const float* MQb = g_mq + ((size_t)bh * MTOT + mtile) * 64;
    #pragma unroll
    for (int kk = 0; kk < 8; kk++)
        #pragma unroll
        for (int mi = 0; mi < 2; mi++) {
            const float* p = MQb + (wm + mi*16 + g)*64 + kk*8 + q4;
            AF[kk][mi][0] = __float_as_uint(p[0]);
            AF[kk][mi][1] = __float_as_uint(p[8*64]);
            AF[kk][mi][2] = __float_as_uint(p[4]);
            AF[kk][mi][3] = __float_as_uint(p[8*64+4]);
        }
    float C[2][4][4] = {};
    float cs[2][2] = {};
    CPA_WAIT2();       // retire Q(0); leaves [V(0), Q(1)]
    __syncthreads();

    for (int ci = 0; ci < 48; ci++) {
        int qo = (ci & 1) * 2176;
        // S = MQ @ Q^T
        float Cs[2][2][4] = {};
        #pragma unroll
        for (int kk = 0; kk < 8; kk++) {
            uint32_t bb[2][2];
            #pragma unroll
            for (int ni = 0; ni < 2; ni++) {
                const float* bp = &Qs[qo + (wsn + ni*8 + g)*68 + kk*8 + q4];
                bb[ni][0] = __float_as_uint(bp[0]);
                bb[ni][1] = __float_as_uint(bp[4]);
            }
            #pragma unroll
            for (int mi = 0; mi < 2; mi++)
                #pragma unroll
                for (int ni = 0; ni < 2; ni++) mma8(Cs[mi][ni], AF[kk][mi], bb[ni]);
        }
        #pragma unroll
        for (int mi = 0; mi < 2; mi++)
            #pragma unroll
            for (int ni = 0; ni < 2; ni++)
                #pragma unroll
                for (int cc = 0; cc < 4; cc++) {
                    float e = __expf(Cs[mi][ni][cc] * SCALE);
                    cs[mi][cc >> 1] += e;
                    Es[(wm + mi*16 + (cc>>1)*8 + g)*36 + wsn + ni*8 + 2*q4 + (cc&1)] = f2tf(e);
                }
        if (ci == 47) CPA_WAIT0(); else CPA_WAIT1();   // retire V(ci)
        __syncthreads();                               // E + V visible
        // monum += E @ V
        #pragma unroll
        for (int kk = 0; kk < 4; kk++) {
            uint32_t a[2][4], bb[4][2];
            #pragma unroll
            for (int mi = 0; mi < 2; mi++) {
                const float* ap = &Es[(wm + mi*16 + g)*36 + kk*8 + q4];
                a[mi][0] = __float_as_uint(ap[0]);
                a[mi][1] = __float_as_uint(ap[8*36]);
                a[mi][2] = __float_as_uint(ap[4]);
                a[mi][3] = __float_as_uint(ap[8*36+4]);
            }
            #pragma unroll
            for (int ni = 0; ni < 4; ni++) {
                const float* bp = &Vs[(kk*8 + q4)*72 + wd + ni*8 + g];
                bb[ni][0] = __float_as_uint(bp[0]);
                bb[ni][1] = __float_as_uint(bp[4*72]);
            }
            #pragma unroll
            for (int mi = 0; mi < 2; mi++)
                #pragma unroll
                for (int ni = 0; ni < 4; ni++) mma8(C[mi][ni], a[mi], bb[ni]);
        }
        __syncthreads();       // readers of Vs/Es/Qs done
        if (ci < 47) {
            size_t base = (size_t)(nb + (ci + 1) * 32);
            #pragma unroll
            for (int i = 0; i < 2; i++) {
                int idx = t + i*256; int n = idx >> 4, d4 = idx & 15;
                cpa16(&Vs[n*72 + d4*4], Vb + (base + n)*64 + d4*4);
            }
            CPA_COMMIT();                     // C_V(ci+1)
            if (ci < 46) {
                int qn = (ci & 1) * 2176;     // buf (ci+2)&1 == ci&1
                size_t b2 = (size_t)(nb + (ci + 2) * 32);
                #pragma unroll
                for (int i = 0; i < 2; i++) {
                    int idx = t + i*256; int n = idx >> 4, d4 = idx & 15;
                    cpa16(&Qs[qn + n*68 + d4*4], Qb + (b2 + n)*64 + d4*4);
                }
                CPA_COMMIT();                 // C_Q(ci+2)
                CPA_WAIT2();                  // retire Q(ci+1)
            } else {
                CPA_WAIT1();                  // ci==46: retire Q(47)
            }
            __syncthreads();                  // Q(ci+1) visible
        }
    }
    #pragma unroll
    for (int mi = 0; mi < 2; mi++)
        #pragma unroll
        for (int gh = 0; gh < 2; gh++) {
            float v = cs[mi][gh];
            v += __shfl_xor_sync(0xFFFFFFFFu, v, 1);
            v += __shfl_xor_sync(0xFFFFFFFFu, v, 2);
            if (q4 == 0) atomicAdd(&scs[wm + mi*16 + gh*8 + g], v);
        }
    __syncthreads();
    if (t < 128) atomicAdd(&g_colsum[(size_t)bh*MTOT + mtile + t], scs[t]);
    #pragma unroll
    for (int mi = 0; mi < 2; mi++)
        #pragma unroll
        for (int ni = 0; ni < 4; ni++)
            #pragma unroll
            for (int cc = 0; cc < 4; cc++) {
                int m = mtile + wm + mi*16 + g + (cc >> 1)*8;
                int d = wd + ni*8 + 2*q4 + (cc & 1);
                atomicAdd(&g_monum[((size_t)bh*MTOT + m)*64 + d], C[mi][ni][cc]);
            }
}

// ------------------ finalize map_out (float4 over d) ------------------
__global__ void k_mapout(const float* __restrict__ w, float* __restrict__ outp)
{
    int gid = blockIdx.x * 256 + threadIdx.x;
    int m = gid & 511;
    int o = (gid >> 9) & 63;
    int b = gid >> 15;
    float inv[4];
    #pragma unroll
    for (int hh = 0; hh < 4; hh++)
        inv[hh] = 1.f / g_colsum[(size_t)(b * 4 + hh) * 512 + m];
    const float* wo = w + o * 256;
    float s = 0.f;
    #pragma unroll 4
    for (int d4 = 0; d4 < 16; d4++) {
        #pragma unroll
        for (int hh = 0; hh < 4; hh++) {
            float4 mv = *(const float4*)&g_monum[((size_t)(b*4 + hh)*512 + m)*64 + d4*4];
            s += (wo[16*d4 + hh]      * mv.x +
                  wo[16*d4 + 4 + hh]  * mv.y +
                  wo[16*d4 + 8 + hh]  * mv.z +
                  wo[16*d4 + 12 + hh] * mv.w) * inv[hh];
        }
    }
    outp[(size_t)FEAT_OUT_ELEMS + ((size_t)(b * 64 + o)) * 512 + m] = s;
}

// ------------------ pointwise out GEMM (pipelined, static smem) ------------
__global__ __launch_bounds__(256) void k_pw_out(const float* __restrict__ A,
                                                float* __restrict__ outp)
{
    __shared__ float As[64*36];
    __shared__ float Bs[2*32*136];
    int t = threadIdx.x, w = t >> 5, l = t & 31, g = l >> 2, q4 = l & 3;
    int bn = blockIdx.x * 128, bo = blockIdx.y * 64, b = blockIdx.z;
    int wm = (w >> 2) * 32, wn = (w & 3) * 32;
    int am = t >> 3, ak4 = t & 7;
    int am2 = (t + 256) >> 3;
    float C[2][4][4] = {};
    const float* Xb = g_dw2 + (size_t)b * INNER * NTOT;

    float4 Ar0 = *(const float4*)&A[(bo + am)*256 + ak4*4];
    float4 Ar1 = *(const float4*)&A[(bo + am2)*256 + ak4*4];
    #pragma unroll
    for (int i = 0; i < 4; i++) {
        int idx = t + i * 256; int k = idx >> 5, n4 = idx & 31;
        cpa16(&Bs[k*136 + n4*4], &Xb[(size_t)k*NTOT + bn + n4*4]);
    }
    CPA_COMMIT();
    *(float4*)&As[am*36 + ak4*4]  = f2tf4(Ar0);
    *(float4*)&As[am2*36 + ak4*4] = f2tf4(Ar1);
    CPA_WAIT0();
    __syncthreads();

    for (int it = 0; it < 8; it++) {
        int boff = (it & 1) * 4352;
        if (it < 7) {
            int kc = (it + 1) * 32;
            Ar0 = *(const float4*)&A[(bo + am)*256 + kc + ak4*4];
            Ar1 = *(const float4*)&A[(bo + am2)*256 + kc + ak4*4];
            int bn2 = ((it + 1) & 1) * 4352;
            #pragma unroll
            for (int i = 0; i < 4; i++) {
                int idx = t + i * 256; int k = idx >> 5, n4 = idx & 31;
                cpa16(&Bs[bn2 + k*136 + n4*4], &Xb[(size_t)(kc + k)*NTOT + bn + n4*4]);
            }
            CPA_COMMIT();
        }
        #pragma unroll
        for (int kk = 0; kk < 4; kk++) {
            uint32_t a[2][4], bb[4][2];
            #pragma unroll
            for (int mi = 0; mi < 2; mi++) {
                const float* ap = &As[(wm + mi*16 + g)*36 + kk*8 + q4];
                a[mi][0] = __float_as_uint(ap[0]);
                a[mi][1] = __float_as_uint(ap[8*36]);
                a[mi][2] = __float_as_uint(ap[4]);
                a[mi][3] = __float_as_uint(ap[8*36+4]);
            }
            #pragma unroll
            for (int ni = 0; ni < 4; ni++) {
                const float* bp = &Bs[boff + (kk*8 + q4)*136 + wn + ni*8 + g];
                bb[ni][0] = __float_as_uint(bp[0]);
                bb[ni][1] = __float_as_uint(bp[4*136]);
            }
            #pragma unroll
            for (int mi = 0; mi < 2; mi++)
                #pragma unroll
                for (int ni = 0; ni < 4; ni++) mma8(C[mi][ni], a[mi], bb[ni]);
        }
        __syncthreads();
        if (it < 7) {
            *(float4*)&As[am*36 + ak4*4]  = f2tf4(Ar0);
            *(float4*)&As[am2*36 + ak4*4] = f2tf4(Ar1);
        }
        CPA_WAIT0();
        __syncthreads();
    }
    #pragma unroll
    for (int mi = 0; mi < 2; mi++)
        #pragma unroll
        for (int ni = 0; ni < 4; ni++)
            #pragma unroll
            for (int cc = 0; cc < 4; cc++) {
                int o = bo + wm + mi*16 + g + (cc >> 1)*8;
                int n = bn + wn + ni*8 + 2*q4 + (cc & 1);
                outp[((size_t)(b * 128 + o)) * NTOT + n] = C[mi][ni][cc];
            }
}

// ------------------ launch ------------------
extern "C" void kernel_launch(void* const* d_in, const int* in_sizes, int n_in,
                              void* d_out, int out_size)
{
    const float* feat    = (const float*)d_in[0];
    const float* smap    = (const float*)d_in[1];
    const float* fqv_dw  = (const float*)d_in[2];
    const float* fqv_pw  = (const float*)d_in[3];
    const float* fout_dw = (const float*)d_in[4];
    const float* fout_pw = (const float*)d_in[5];
    const float* mqv_w   = (const float*)d_in[6];
    const float* mout_w  = (const float*)d_in[7];
    float* outp = (float*)d_out;

    k_dwconv1<<<dim3(14, 128, 2), 256>>>(feat, fqv_dw);
    k_map_qv <<<dim3(16, 2), 256>>>(mqv_w, smap);       // also zeros monum/colsum
    k_pw_qv  <<<dim3(108, 8, 2), 256>>>(fqv_pw);
    k_attn2  <<<dim3(KSPLIT, 4, 8), 256>>>();           // launch #4 -> ncu window
    k_attn1  <<<dim3(108, 8), 256>>>();
    k_dwconv2<<<dim3(14, 256, 2), 256>>>(fout_dw);
    k_mapout <<<256, 256>>>(mout_w, outp);
    k_pw_out <<<dim3(108, 2, 2), 256>>>(fout_pw, outp);
}

// round 13
// speedup vs baseline: 3.6162x; 1.0371x over previous
#include <cuda_runtime.h>
#include <math.h>
#include <stdint.h>

#define BSZ   2
#define CF    128
#define NTOT  13824      // 24^3
#define MTOT  512        // 8^3
#define NHEAD 4
#define DHEAD 64
#define INNER 256
#define SCALE 0.125f     // 64^-0.5
#define FEAT_OUT_ELEMS 3538944   // 2*128*13824
#define KSPLIT 9
#define KLEN   1536      // 13824/9

// ------------------ scratch (device globals; no allocs) ------------------
__device__ __align__(16) float g_t1   [BSZ*CF*NTOT];            // dwconv1 out (tf32 bits)
__device__ __align__(16) float g_q    [BSZ*NHEAD*NTOT*DHEAD];   // feat_q (tf32 bits)
__device__ __align__(16) float g_fv   [BSZ*NHEAD*NTOT*DHEAD];   // feat_v (tf32 bits)
__device__ __align__(16) float g_mq   [BSZ*NHEAD*MTOT*DHEAD];   // map_q  (tf32 bits)
__device__ __align__(16) float g_mv   [BSZ*NHEAD*MTOT*DHEAD];   // map_v  (tf32 bits)
__device__ __align__(16) float g_attnout[BSZ*INNER*NTOT];       // feat attn out (fp32)
__device__ __align__(16) float g_dw2  [BSZ*INNER*NTOT];         // dwconv2 out (tf32 bits)
__device__ __align__(16) float g_monum[BSZ*NHEAD*MTOT*DHEAD];
__device__ __align__(16) float g_colsum[BSZ*NHEAD*MTOT];

// ------------------ tf32 mma helpers ------------------
__device__ __forceinline__ uint32_t f2t(float x){
    uint32_t r; asm("cvt.rna.tf32.f32 %0,%1;":"=r"(r):"f"(x)); return r;
}
__device__ __forceinline__ float f2tf(float x){ return __uint_as_float(f2t(x)); }
__device__ __forceinline__ float4 f2tf4(float4 v){
    v.x = f2tf(v.x); v.y = f2tf(v.y); v.z = f2tf(v.z); v.w = f2tf(v.w); return v;
}

__device__ __forceinline__ void mma8(float* c, const uint32_t* a, const uint32_t* b){
    asm volatile("mma.sync.aligned.m16n8k8.row.col.f32.tf32.tf32.f32 "
        "{%0,%1,%2,%3},{%4,%5,%6,%7},{%8,%9},{%0,%1,%2,%3};"
        : "+f"(c[0]),"+f"(c[1]),"+f"(c[2]),"+f"(c[3])
        : "r"(a[0]),"r"(a[1]),"r"(a[2]),"r"(a[3]),"r"(b[0]),"r"(b[1]));
}

// ------------------ cp.async helpers ------------------
__device__ __forceinline__ void cpa16(void* smem, const void* g){
    uint32_t s = (uint32_t)__cvta_generic_to_shared(smem);
    asm volatile("cp.async.ca.shared.global [%0], [%1], 16;" :: "r"(s), "l"(g));
}
#define CPA_COMMIT() asm volatile("cp.async.commit_group;")
#define CPA_WAIT0()  asm volatile("cp.async.wait_group 0;" ::: "memory")
#define CPA_WAIT1()  asm volatile("cp.async.wait_group 1;" ::: "memory")
#define CPA_WAIT2()  asm volatile("cp.async.wait_group 2;" ::: "memory")

// ------------------ depthwise 3x3x3, SAME, x-vectorized; output tf32-rounded
__device__ __forceinline__ void dw_body_v4(const float* __restrict__ in,
                                           const float* __restrict__ w,
                                           float* __restrict__ out, int C)
{
    __shared__ float ws[27];
    int t = threadIdx.x;
    int c = blockIdx.y, b = blockIdx.z;
    if (t < 27) ws[t] = w[c * 27 + t];
    __syncthreads();
    int idx = blockIdx.x * 256 + t;          // over 24*24*6 = 3456
    if (idx >= 3456) return;
    int x4 = (idx % 6) * 4;
    int y  = (idx / 6) % 24;
    int z  = idx / 144;
    const float* ip = in + ((size_t)(b * C + c)) * NTOT;
    float acc0 = 0.f, acc1 = 0.f, acc2 = 0.f, acc3 = 0.f;
    #pragma unroll
    for (int dz = -1; dz <= 1; dz++) {
        int zz = z + dz; if (zz < 0 || zz >= 24) continue;
        #pragma unroll
        for (int dy = -1; dy <= 1; dy++) {
            int yy = y + dy; if (yy < 0 || yy >= 24) continue;
            const float* row = ip + (zz * 24 + yy) * 24;
            float4 mid = *(const float4*)(row + x4);
            float left  = (x4 > 0)      ? row[x4 - 1] : 0.f;
            float right = (x4 + 4 < 24) ? row[x4 + 4] : 0.f;
            const float* wr = ws + (dz + 1) * 9 + (dy + 1) * 3;
            float w0 = wr[0], w1 = wr[1], w2 = wr[2];
            acc0 += w0 * left  + w1 * mid.x + w2 * mid.y;
            acc1 += w0 * mid.x + w1 * mid.y + w2 * mid.z;
            acc2 += w0 * mid.y + w1 * mid.z + w2 * mid.w;
            acc3 += w0 * mid.z + w1 * mid.w + w2 * right;
        }
    }
    float4 o = f2tf4(make_float4(acc0, acc1, acc2, acc3));
    *(float4*)(out + ((size_t)(b * C + c)) * NTOT + (z * 24 + y) * 24 + x4) = o;
}

__global__ void k_dwconv1(const float* __restrict__ feat, const float* __restrict__ w)
{   dw_body_v4(feat, w, g_t1, CF); }

__global__ void k_dwconv2(const float* __restrict__ w)
{   dw_body_v4(g_attnout, w, g_dw2, INNER); }

// ------------------ zero accumulators ------------------
__global__ void k_zero()
{
    int flat = blockIdx.x * 256 + threadIdx.x;     // 65536 threads
    float4 z4 = make_float4(0.f, 0.f, 0.f, 0.f);
    *(float4*)&g_monum[(size_t)flat * 4] = z4;
    if (flat < BSZ * NHEAD * MTOT) g_colsum[flat] = 0.f;
}

// ------------------ pointwise qv GEMM (pipelined, static smem) -------------
// epilogue: smem-transpose then float4 d-run stores (full 32B sectors)
__global__ __launch_bounds__(256) void k_pw_qv(const float* __restrict__ A)
{
    __shared__ float As[64*36];
    __shared__ float Bs[2*32*136];   // also epilogue staging [64o][133]
    int t = threadIdx.x, w = t >> 5, l = t & 31, g = l >> 2, q4 = l & 3;
    int bn = blockIdx.x * 128, bo = blockIdx.y * 64, b = blockIdx.z;
    int wm = (w >> 2) * 32, wn = (w & 3) * 32;
    int am = t >> 3, ak4 = t & 7;
    int am2 = (t + 256) >> 3;
    float C[2][4][4] = {};
    const float* Xb = g_t1 + (size_t)b * CF * NTOT;

    float4 Ar0 = *(const float4*)&A[(bo + am)*128 + ak4*4];
    float4 Ar1 = *(const float4*)&A[(bo + am2)*128 + ak4*4];
    #pragma unroll
    for (int i = 0; i < 4; i++) {
        int idx = t + i * 256; int k = idx >> 5, n4 = idx & 31;
        cpa16(&Bs[k*136 + n4*4], &Xb[(size_t)k*NTOT + bn + n4*4]);
    }
    CPA_COMMIT();
    *(float4*)&As[am*36 + ak4*4]  = f2tf4(Ar0);
    *(float4*)&As[am2*36 + ak4*4] = f2tf4(Ar1);
    CPA_WAIT0();
    __syncthreads();

    for (int it = 0; it < 4; it++) {
        int boff = (it & 1) * 4352;
        if (it < 3) {
            int kc = (it + 1) * 32;
            Ar0 = *(const float4*)&A[(bo + am)*128 + kc + ak4*4];
            Ar1 = *(const float4*)&A[(bo + am2)*128 + kc + ak4*4];
            int bn2 = ((it + 1) & 1) * 4352;
            #pragma unroll
            for (int i = 0; i < 4; i++) {
                int idx = t + i * 256; int k = idx >> 5, n4 = idx & 31;
                cpa16(&Bs[bn2 + k*136 + n4*4], &Xb[(size_t)(kc + k)*NTOT + bn + n4*4]);
            }
            CPA_COMMIT();
        }
        #pragma unroll
        for (int kk = 0; kk < 4; kk++) {
            uint32_t a[2][4], bb[4][2];
            #pragma unroll
            for (int mi = 0; mi < 2; mi++) {
                const float* ap = &As[(wm + mi*16 + g)*36 + kk*8 + q4];
                a[mi][0] = __float_as_uint(ap[0]);
                a[mi][1] = __float_as_uint(ap[8*36]);
                a[mi][2] = __float_as_uint(ap[4]);
                a[mi][3] = __float_as_uint(ap[8*36+4]);
            }
            #pragma unroll
            for (int ni = 0; ni < 4; ni++) {
                const float* bp = &Bs[boff + (kk*8 + q4)*136 + wn + ni*8 + g];
                bb[ni][0] = __float_as_uint(bp[0]);
                bb[ni][1] = __float_as_uint(bp[4*136]);
            }
            #pragma unroll
            for (int mi = 0; mi < 2; mi++)
                #pragma unroll
                for (int ni = 0; ni < 4; ni++) mma8(C[mi][ni], a[mi], bb[ni]);
        }
        __syncthreads();
        if (it < 3) {
            *(float4*)&As[am*36 + ak4*4]  = f2tf4(Ar0);
            *(float4*)&As[am2*36 + ak4*4] = f2tf4(Ar1);
        }
        CPA_WAIT0();
        __syncthreads();
    }
    // ---- epilogue: stage C [o_local][n_local] (pitch 133), then d-run float4 stores
    float* Ct = Bs;   // 64*133 = 8512 <= 8704
    #pragma unroll
    for (int mi = 0; mi < 2; mi++)
        #pragma unroll
        for (int ni = 0; ni < 4; ni++)
            #pragma unroll
            for (int cc = 0; cc < 4; cc++) {
                int ol = wm + mi*16 + g + (cc >> 1)*8;
                int nl = wn + ni*8 + 2*q4 + (cc & 1);
                Ct[ol*133 + nl] = f2tf(C[mi][ni][cc]);
            }
    __syncthreads();
    float* dst = (bo < 256) ? g_q : g_fv;
    int dbase = (bo & 255) >> 2;           // block's 16-d window start
    #pragma unroll
    for (int i = 0; i < 8; i++) {
        int idx = t + i * 256;             // < 2048
        int dq = idx & 3;                  // fastest: 4 lanes -> 64B run
        int h  = (idx >> 2) & 3;
        int n  = idx >> 4;                 // 0..127
        float4 v;
        v.x = Ct[((dq*4+0)*4 + h)*133 + n];
        v.y = Ct[((dq*4+1)*4 + h)*133 + n];
        v.z = Ct[((dq*4+2)*4 + h)*133 + n];
        v.w = Ct[((dq*4+3)*4 + h)*133 + n];
        *(float4*)&dst[((size_t)(b*4 + h)*NTOT + bn + n)*64 + dbase + dq*4] = v;
    }
}

// ------------------ map qv ------------------
__global__ __launch_bounds__(256) void k_map_qv(const float* __restrict__ w,
                                                const float* __restrict__ smap)
{
    __shared__ float Ws[32*68];
    __shared__ float Bs[64*132];
    int t = threadIdx.x;
    int bo = blockIdx.x * 32, b = blockIdx.y;
    int ol = (t >> 5) * 4;
    int ml = (t & 31) * 4;
    #pragma unroll
    for (int i = 0; i < 2; i++) {
        int idx = t + i * 256; int o = idx >> 4, c4 = idx & 15;
        *(float4*)&Ws[o*68 + c4*4] = *(const float4*)&w[(bo + o)*64 + c4*4];
    }
    for (int mc = 0; mc < 512; mc += 128) {
        __syncthreads();
        #pragma unroll
        for (int i = 0; i < 8; i++) {
            int idx = t + i * 256; int c = idx >> 5, m4 = idx & 31;
            *(float4*)&Bs[c*132 + m4*4] =
                *(const float4*)&smap[((size_t)(b*64 + c))*512 + mc + m4*4];
        }
        __syncthreads();
        float acc[4][4] = {};
        #pragma unroll 8
        for (int c = 0; c < 64; c++) {
            float4 bv = *(const float4*)&Bs[c*132 + ml];
            #pragma unroll
            for (int oi = 0; oi < 4; oi++) {
                float wv = Ws[(ol + oi)*68 + c];
                acc[oi][0] += wv * bv.x; acc[oi][1] += wv * bv.y;
                acc[oi][2] += wv * bv.z; acc[oi][3] += wv * bv.w;
            }
        }
        #pragma unroll
        for (int oi = 0; oi < 4; oi++) {
            int oo = bo + ol + oi;
            float* dst; int oc;
            if (oo < 256) { dst = g_mq; oc = oo; } else { dst = g_mv; oc = oo - 256; }
            size_t base = ((size_t)(b*4 + (oc & 3))*512 + mc + ml)*64 + (oc >> 2);
            dst[base]       = f2tf(acc[oi][0]);
            dst[base + 64]  = f2tf(acc[oi][1]);
            dst[base + 128] = f2tf(acc[oi][2]);
            dst[base + 192] = f2tf(acc[oi][3]);
        }
    }
}

// ------------------ attention pass 1: 2-sync pipelined flash block ---------
__global__ __launch_bounds__(256, 2) void k_attn1()
{
    __shared__ float MQd[2*32*68];
    __shared__ float MVd[32*72];
    __shared__ float Es[128*36];
    __shared__ float srs[128];
    int t = threadIdx.x, w = t >> 5, l = t & 31, g = l >> 2, q4 = l & 3;
    int bh = blockIdx.y, b = bh >> 2, h = bh & 3;
    int nb = blockIdx.x * 128;
    int wn  = (w >> 1) * 32;
    int wsm = (w & 1) * 16;
    int wd  = (w & 1) * 32;

    if (t < 128) srs[t] = 0.f;
    const float* Qb  = g_q  + ((size_t)bh*NTOT + nb) * 64;
    const float* MQg = g_mq + (size_t)bh * MTOT * 64;
    const float* MVg = g_mv + (size_t)bh * MTOT * 64;

    #pragma unroll
    for (int i = 0; i < 2; i++) {
        int idx = t + i*256; int m = idx >> 4, d4 = idx & 15;
        cpa16(&MQd[m*68 + d4*4], MQg + (size_t)m*64 + d4*4);
    }
    CPA_COMMIT();
    #pragma unroll
    for (int i = 0; i < 2; i++) {
        int idx = t + i*256; int m = idx >> 4, d4 = idx & 15;
        cpa16(&MVd[m*72 + d4*4], MVg + (size_t)m*64 + d4*4);
    }
    CPA_COMMIT();
    #pragma unroll
    for (int i = 0; i < 2; i++) {
        int idx = t + i*256; int m = idx >> 4, d4 = idx & 15;
        cpa16(&MQd[2176 + m*68 + d4*4], MQg + 2048 + (size_t)m*64 + d4*4);
    }
    CPA_COMMIT();

    uint32_t QF[8][2][4];
    for (int p = 0; p < 4; p++) {
        __syncthreads();
        #pragma unroll
        for (int i = 0; i < 2; i++) {
            int idx = t + i*256; int n = idx >> 4, d4 = idx & 15;
            *(float4*)&Es[n*68 + d4*4] = *(const float4*)&Qb[(size_t)(p*32 + n)*64 + d4*4];
        }
        __syncthreads();
        if ((w >> 1) == p) {
            #pragma unroll
            for (int kk = 0; kk < 8; kk++)
                #pragma unroll
                for (int mi = 0; mi < 2; mi++) {
                    const float* ap = &Es[(mi*16 + g)*68 + kk*8 + q4];
                    QF[kk][mi][0] = __float_as_uint(ap[0]);
                    QF[kk][mi][1] = __float_as_uint(ap[8*68]);
                    QF[kk][mi][2] = __float_as_uint(ap[4]);
                    QF[kk][mi][3] = __float_as_uint(ap[8*68+4]);
                }
        }
    }
    CPA_WAIT2();
    __syncthreads();

    float OF[2][4][4] = {};
    float rs[2][2] = {};

    for (int mc = 0; mc < 16; mc++) {
        int mqo = (mc & 1) * 2176;
        float Cs[2][2][4] = {};
        #pragma unroll
        for (int kk = 0; kk < 8; kk++) {
            uint32_t bb[2][2];
            #pragma unroll
            for (int ni = 0; ni < 2; ni++) {
                const float* bp = &MQd[mqo + (wsm + ni*8 + g)*68 + kk*8 + q4];
                bb[ni][0] = __float_as_uint(bp[0]);
                bb[ni][1] = __float_as_uint(bp[4]);
            }
            #pragma unroll
            for (int mi = 0; mi < 2; mi++)
                #pragma unroll
                for (int ni = 0; ni < 2; ni++) mma8(Cs[mi][ni], QF[kk][mi], bb[ni]);
        }
        #pragma unroll
        for (int mi = 0; mi < 2; mi++)
            #pragma unroll
            for (int ni = 0; ni < 2; ni++)
                #pragma unroll
                for (int cc = 0; cc < 4; cc++) {
                    float e = __expf(Cs[mi][ni][cc] * SCALE);
                    rs[mi][cc >> 1] += e;
                    Es[(wn + mi*16 + (cc>>1)*8 + g)*36 + wsm + ni*8 + 2*q4 + (cc&1)] = f2tf(e);
                }
        if (mc == 15) CPA_WAIT0(); else CPA_WAIT1();
        __syncthreads();
        #pragma unroll
        for (int kk = 0; kk < 4; kk++) {
            uint32_t a[2][4], bb[4][2];
            #pragma unroll
            for (int mi = 0; mi < 2; mi++) {
                const float* ap = &Es[(wn + mi*16 + g)*36 + kk*8 + q4];
                a[mi][0] = __float_as_uint(ap[0]);
                a[mi][1] = __float_as_uint(ap[8*36]);
                a[mi][2] = __float_as_uint(ap[4]);
                a[mi][3] = __float_as_uint(ap[8*36+4]);
            }
            #pragma unroll
            for (int ni = 0; ni < 4; ni++) {
                const float* bp = &MVd[(kk*8 + q4)*72 + wd + ni*8 + g];
                bb[ni][0] = __float_as_uint(bp[0]);
                bb[ni][1] = __float_as_uint(bp[4*72]);
            }
            #pragma unroll
            for (int mi = 0; mi < 2; mi++)
                #pragma unroll
                for (int ni = 0; ni < 4; ni++) mma8(OF[mi][ni], a[mi], bb[ni]);
        }
        __syncthreads();
        if (mc < 15) {
            size_t go = (size_t)(mc + 1) * 32 * 64;
            #pragma unroll
            for (int i = 0; i < 2; i++) {
                int idx = t + i*256; int m = idx >> 4, d4 = idx & 15;
                cpa16(&MVd[m*72 + d4*4], MVg + go + (size_t)m*64 + d4*4);
            }
            CPA_COMMIT();
            if (mc < 14) {
                int mqn = (mc & 1) * 2176;
                size_t go2 = (size_t)(mc + 2) * 32 * 64;
                #pragma unroll
                for (int i = 0; i < 2; i++) {
                    int idx = t + i*256; int m = idx >> 4, d4 = idx & 15;
                    cpa16(&MQd[mqn + m*68 + d4*4], MQg + go2 + (size_t)m*64 + d4*4);
                }
                CPA_COMMIT();
                CPA_WAIT2();
            } else {
                CPA_WAIT1();
            }
            __syncthreads();
        }
    }
    #pragma unroll
    for (int mi = 0; mi < 2; mi++)
        #pragma unroll
        for (int gh = 0; gh < 2; gh++) {
            float v = rs[mi][gh];
            v += __shfl_xor_sync(0xFFFFFFFFu, v, 1);
            v += __shfl_xor_sync(0xFFFFFFFFu, v, 2);
            if (q4 == 0) atomicAdd(&srs[wn + mi*16 + gh*8 + g], v);
        }
    __syncthreads();
    float* ao = g_attnout + (size_t)b * INNER * NTOT + nb;
    #pragma unroll
    for (int mi = 0; mi < 2; mi++) {
        int n0 = wn + mi*16 + g;
        float inv0 = 1.f / srs[n0];
        float inv1 = 1.f / srs[n0 + 8];
        #pragma unroll
        for (int ni = 0; ni < 4; ni++) {
            int d0 = wd + ni*8 + 2*q4;
            ao[(size_t)(4*d0 + h)*NTOT + n0]         = OF[mi][ni][0] * inv0;
            ao[(size_t)(4*(d0+1) + h)*NTOT + n0]     = OF[mi][ni][1] * inv0;
            ao[(size_t)(4*d0 + h)*NTOT + n0 + 8]     = OF[mi][ni][2] * inv1;
            ao[(size_t)(4*(d0+1) + h)*NTOT + n0 + 8] = OF[mi][ni][3] * inv1;
        }
    }
}

// ------------------ attention pass 2: 2-sync pipelined recompute-E ---------
__global__ __launch_bounds__(256, 2) void k_attn2()
{
    __shared__ float Qs[2*32*68];
    __shared__ float Vs[32*72];
    __shared__ float Es[128*36];
    __shared__ float scs[128];
    int t = threadIdx.x, w = t >> 5, l = t & 31, g = l >> 2, q4 = l & 3;
    int bh = blockIdx.z; int mtile = blockIdx.y * 128; int nb = blockIdx.x * KLEN;
    int wm = (w >> 1) * 32, wsn = (w & 1) * 16, wd = (w & 1) * 32;
    const float* Qb = g_q  + (size_t)bh * NTOT * 64;
    const float* Vb = g_fv + (size_t)bh * NTOT * 64;
    if (t < 128) scs[t] = 0.f;

    #pragma unroll
    for (int i = 0; i < 2; i++) {
        int idx = t + i*256; int n = idx >> 4, d4 = idx & 15;
        cpa16(&Qs[n*68 + d4*4], Qb + (size_t)(nb + n)*64 + d4*4);
    }
    CPA_COMMIT();
    #pragma unroll
    for (int i = 0; i < 2; i++) {
        int idx = t + i*256; int n = idx >> 4, d4 = idx & 15;
        cpa16(&Vs[n*72 + d4*4], Vb + (size_t)(nb + n)*64 + d4*4);
    }
    CPA_COMMIT();
    #pragma unroll
    for (int i = 0; i < 2; i++) {
        int idx = t + i*256; int n = idx >> 4, d4 = idx & 15;
        cpa16(&Qs[2176 + n*68 + d4*4], Qb + (size_t)(nb + 32 + n)*64 + d4*4);
    }
    CPA_COMMIT();

    uint32_t AF[8][2][4];
    const float* MQb = g_mq + ((size_t)bh * MTOT + mtile) * 64;
    #pragma unroll
    for (int kk = 0; kk < 8; kk++)
        #pragma unroll
        for (int mi = 0; mi < 2; mi++) {
            const float* p = MQb + (wm + mi*16 + g)*64 + kk*8 + q4;
            AF[kk][mi][0] = __float_as_uint(p[0]);
            AF[kk][mi][1] = __float_as_uint(p[8*64]);
            AF[kk][mi][2] = __float_as_uint(p[4]);
            AF[kk][mi][3] = __float_as_uint(p[8*64+4]);
        }
    float C[2][4][4] = {};
    float cs[2][2] = {};
    CPA_WAIT2();
    __syncthreads();

    for (int ci = 0; ci < 48; ci++) {
        int qo = (ci & 1) * 2176;
        float Cs[2][2][4] = {};
        #pragma unroll
        for (int kk = 0; kk < 8; kk++) {
            uint32_t bb[2][2];
            #pragma unroll
            for (int ni = 0; ni < 2; ni++) {
                const float* bp = &Qs[qo + (wsn + ni*8 + g)*68 + kk*8 + q4];
                bb[ni][0] = __float_as_uint(bp[0]);
                bb[ni][1] = __float_as_uint(bp[4]);
            }
            #pragma unroll
            for (int mi = 0; mi < 2; mi++)
                #pragma unroll
                for (int ni = 0; ni < 2; ni++) mma8(Cs[mi][ni], AF[kk][mi], bb[ni]);
        }
        #pragma unroll
        for (int mi = 0; mi < 2; mi++)
            #pragma unroll
            for (int ni = 0; ni < 2; ni++)
                #pragma unroll
                for (int cc = 0; cc < 4; cc++) {
                    float e = __expf(Cs[mi][ni][cc] * SCALE);
                    cs[mi][cc >> 1] += e;
                    Es[(wm + mi*16 + (cc>>1)*8 + g)*36 + wsn + ni*8 + 2*q4 + (cc&1)] = f2tf(e);
                }
        if (ci == 47) CPA_WAIT0(); else CPA_WAIT1();
        __syncthreads();
        #pragma unroll
        for (int kk = 0; kk < 4; kk++) {
            uint32_t a[2][4], bb[4][2];
            #pragma unroll
            for (int mi = 0; mi < 2; mi++) {
                const float* ap = &Es[(wm + mi*16 + g)*36 + kk*8 + q4];
                a[mi][0] = __float_as_uint(ap[0]);
                a[mi][1] = __float_as_uint(ap[8*36]);
                a[mi][2] = __float_as_uint(ap[4]);
                a[mi][3] = __float_as_uint(ap[8*36+4]);
            }
            #pragma unroll
            for (int ni = 0; ni < 4; ni++) {
                const float* bp = &Vs[(kk*8 + q4)*72 + wd + ni*8 + g];
                bb[ni][0] = __float_as_uint(bp[0]);
                bb[ni][1] = __float_as_uint(bp[4*72]);
            }
            #pragma unroll
            for (int mi = 0; mi < 2; mi++)
                #pragma unroll
                for (int ni = 0; ni < 4; ni++) mma8(C[mi][ni], a[mi], bb[ni]);
        }
        __syncthreads();
        if (ci < 47) {
            size_t base = (size_t)(nb + (ci + 1) * 32);
            #pragma unroll
            for (int i = 0; i < 2; i++) {
                int idx = t + i*256; int n = idx >> 4, d4 = idx & 15;
                cpa16(&Vs[n*72 + d4*4], Vb + (base + n)*64 + d4*4);
            }
            CPA_COMMIT();
            if (ci < 46) {
                int qn = (ci & 1) * 2176;
                size_t b2 = (size_t)(nb + (ci + 2) * 32);
                #pragma unroll
                for (int i = 0; i < 2; i++) {
                    int idx = t + i*256; int n = idx >> 4, d4 = idx & 15;
                    cpa16(&Qs[qn + n*68 + d4*4], Qb + (b2 + n)*64 + d4*4);
                }
                CPA_COMMIT();
                CPA_WAIT2();
            } else {
                CPA_WAIT1();
            }
            __syncthreads();
        }
    }
    #pragma unroll
    for (int mi = 0; mi < 2; mi++)
        #pragma unroll
        for (int gh = 0; gh < 2; gh++) {
            float v = cs[mi][gh];
            v += __shfl_xor_sync(0xFFFFFFFFu, v, 1);
            v += __shfl_xor_sync(0xFFFFFFFFu, v, 2);
            if (q4 == 0) atomicAdd(&scs[wm + mi*16 + gh*8 + g], v);
        }
    __syncthreads();
    if (t < 128) atomicAdd(&g_colsum[(size_t)bh*MTOT + mtile + t], scs[t]);
    #pragma unroll
    for (int mi = 0; mi < 2; mi++)
        #pragma unroll
        for (int ni = 0; ni < 4; ni++)
            #pragma unroll
            for (int cc = 0; cc < 4; cc++) {
                int m = mtile + wm + mi*16 + g + (cc >> 1)*8;
                int d = wd + ni*8 + 2*q4 + (cc & 1);
                atomicAdd(&g_monum[((size_t)bh*MTOT + m)*64 + d], C[mi][ni][cc]);
            }
}

// ------------------ finalize map_out (float4 over d) ------------------
__global__ void k_mapout(const float* __restrict__ w, float* __restrict__ outp)
{
    int gid = blockIdx.x * 256 + threadIdx.x;
    int m = gid & 511;
    int o = (gid >> 9) & 63;
    int b = gid >> 15;
    float inv[4];
    #pragma unroll
    for (int hh = 0; hh < 4; hh++)
        inv[hh] = 1.f / g_colsum[(size_t)(b * 4 + hh) * 512 + m];
    const float* wo = w + o * 256;
    float s = 0.f;
    #pragma unroll 4
    for (int d4 = 0; d4 < 16; d4++) {
        #pragma unroll
        for (int hh = 0; hh < 4; hh++) {
            float4 mv = *(const float4*)&g_monum[((size_t)(b*4 + hh)*512 + m)*64 + d4*4];
            s += (wo[16*d4 + hh]      * mv.x +
                  wo[16*d4 + 4 + hh]  * mv.y +
                  wo[16*d4 + 8 + hh]  * mv.z +
                  wo[16*d4 + 12 + hh] * mv.w) * inv[hh];
        }
    }
    outp[(size_t)FEAT_OUT_ELEMS + ((size_t)(b * 64 + o)) * 512 + m] = s;
}

// ------------------ pointwise out GEMM (pipelined, static smem) ------------
__global__ __launch_bounds__(256) void k_pw_out(const float* __restrict__ A,
                                                float* __restrict__ outp)
{
    __shared__ float As[64*36];
    __shared__ float Bs[2*32*136];
    int t = threadIdx.x, w = t >> 5, l = t & 31, g = l >> 2, q4 = l & 3;
    int bn = blockIdx.x * 128, bo = blockIdx.y * 64, b = blockIdx.z;
    int wm = (w >> 2) * 32, wn = (w & 3) * 32;
    int am = t >> 3, ak4 = t & 7;
    int am2 = (t + 256) >> 3;
    float C[2][4][4] = {};
    const float* Xb = g_dw2 + (size_t)b * INNER * NTOT;

    float4 Ar0 = *(const float4*)&A[(bo + am)*256 + ak4*4];
    float4 Ar1 = *(const float4*)&A[(bo + am2)*256 + ak4*4];
    #pragma unroll
    for (int i = 0; i < 4; i++) {
        int idx = t + i * 256; int k = idx >> 5, n4 = idx & 31;
        cpa16(&Bs[k*136 + n4*4], &Xb[(size_t)k*NTOT + bn + n4*4]);
    }
    CPA_COMMIT();
    *(float4*)&As[am*36 + ak4*4]  = f2tf4(Ar0);
    *(float4*)&As[am2*36 + ak4*4] = f2tf4(Ar1);
    CPA_WAIT0();
    __syncthreads();

    for (int it = 0; it < 8; it++) {
        int boff = (it & 1) * 4352;
        if (it < 7) {
            int kc = (it + 1) * 32;
            Ar0 = *(const float4*)&A[(bo + am)*256 + kc + ak4*4];
            Ar1 = *(const float4*)&A[(bo + am2)*256 + kc + ak4*4];
            int bn2 = ((it + 1) & 1) * 4352;
            #pragma unroll
            for (int i = 0; i < 4; i++) {
                int idx = t + i * 256; int k = idx >> 5, n4 = idx & 31;
                cpa16(&Bs[bn2 + k*136 + n4*4], &Xb[(size_t)(kc + k)*NTOT + bn + n4*4]);
            }
            CPA_COMMIT();
        }
        #pragma unroll
        for (int kk = 0; kk < 4; kk++) {
            uint32_t a[2][4], bb[4][2];
            #pragma unroll
            for (int mi = 0; mi < 2; mi++) {
                const float* ap = &As[(wm + mi*16 + g)*36 + kk*8 + q4];
                a[mi][0] = __float_as_uint(ap[0]);
                a[mi][1] = __float_as_uint(ap[8*36]);
                a[mi][2] = __float_as_uint(ap[4]);
                a[mi][3] = __float_as_uint(ap[8*36+4]);
            }
            #pragma unroll
            for (int ni = 0; ni < 4; ni++) {
                const float* bp = &Bs[boff + (kk*8 + q4)*136 + wn + ni*8 + g];
                bb[ni][0] = __float_as_uint(bp[0]);
                bb[ni][1] = __float_as_uint(bp[4*136]);
            }
            #pragma unroll
            for (int mi = 0; mi < 2; mi++)
                #pragma unroll
                for (int ni = 0; ni < 4; ni++) mma8(C[mi][ni], a[mi], bb[ni]);
        }
        __syncthreads();
        if (it < 7) {
            *(float4*)&As[am*36 + ak4*4]  = f2tf4(Ar0);
            *(float4*)&As[am2*36 + ak4*4] = f2tf4(Ar1);
        }
        CPA_WAIT0();
        __syncthreads();
    }
    #pragma unroll
    for (int mi = 0; mi < 2; mi++)
        #pragma unroll
        for (int ni = 0; ni < 4; ni++)
            #pragma unroll
            for (int cc = 0; cc < 4; cc++) {
                int o = bo + wm + mi*16 + g + (cc >> 1)*8;
                int n = bn + wn + ni*8 + 2*q4 + (cc & 1);
                outp[((size_t)(b * 128 + o)) * NTOT + n] = C[mi][ni][cc];
            }
}

// ------------------ launch ------------------
extern "C" void kernel_launch(void* const* d_in, const int* in_sizes, int n_in,
                              void* d_out, int out_size)
{
    const float* feat    = (const float*)d_in[0];
    const float* smap    = (const float*)d_in[1];
    const float* fqv_dw  = (const float*)d_in[2];
    const float* fqv_pw  = (const float*)d_in[3];
    const float* fout_dw = (const float*)d_in[4];
    const float* fout_pw = (const float*)d_in[5];
    const float* mqv_w   = (const float*)d_in[6];
    const float* mout_w  = (const float*)d_in[7];
    float* outp = (float*)d_out;

    k_map_qv <<<dim3(16, 2), 256>>>(mqv_w, smap);
    k_dwconv1<<<dim3(14, 128, 2), 256>>>(feat, fqv_dw);
    k_zero   <<<256, 256>>>();
    k_pw_qv  <<<dim3(108, 8, 2), 256>>>(fqv_pw);        // launch #4 -> ncu window
    k_attn1  <<<dim3(108, 8), 256>>>();
    k_attn2  <<<dim3(KSPLIT, 4, 8), 256>>>();
    k_dwconv2<<<dim3(14, 256, 2), 256>>>(fout_dw);
    k_mapout <<<256, 256>>>(mout_w, outp);
    k_pw_out <<<dim3(108, 2, 2), 256>>>(fout_pw, outp);
}